// round 1
// baseline (speedup 1.0000x reference)
#include <cuda_runtime.h>
#include <cuda_bf16.h>
#include <math.h>
#include <stdint.h>

// ---------------- problem constants ----------------
#define NN_   8192
#define DIN_  83
#define H_    256
#define C_    34
#define TD_   16
#define NL_   2
#define KNN_  11
#define NSTEPS_ 10

// ---------------- scratch (device globals; no allocation allowed) ----------------
__device__ float g_sim[(size_t)NN_ * NN_];          // 256 MB
__device__ float g_h  [NN_ * H_];
__device__ float g_h2 [NN_ * H_];
__device__ float g_hn [NN_ * H_];
__device__ float g_agg[NN_ * H_];
__device__ float g_d1 [NN_ * H_];
__device__ float g_d2 [NN_ * H_];
__device__ int   g_nidx[NN_ * KNN_];
__device__ float g_nval[NN_ * KNN_];
__device__ float g_bnscale[H_];
__device__ float g_bnshift[H_];
__device__ float g_gatec[NL_ * H_];
__device__ float g_sdebias[NSTEPS_ * H_];

// ---------------- generic fp32 GEMM with fused epilogues ----------------
// C[M,N] = A[M,K] (row-major, lda=K) @ B
//   transB=0: B row-major [K,N] with leading dim ldb (access B[k*ldb+n])
//   transB=1: B row-major [N,K] with leading dim ldb (access B[n*ldb+k])
// Epilogues:
//   0: y = z
//   1: y = relu(z + p1[n])
//   2: y = relu(z + p1[n]) * p2[n] + p3[n]          (encoder2 + folded BN)
//   3: y = z + p1[n]                                 (bias only)
//   4: g = sigmoid(z + p1[n]); y = relu(g*p2[i,n] + (1-g)*p3[i,n])   (gate)
//   5: y = tanh(z + p1[n])
//   6: y = p2[i,n] + tanh(z + p1[n]) * alpha         (SDE Euler update)
#define BM 64
#define BN 64
#define BK 16
#define SPAD 68

__global__ void gemm_kernel(const float* __restrict__ A,
                            const float* __restrict__ B,
                            float* __restrict__ C,
                            int M, int N, int K, int ldb, int transB, int ep,
                            const float* __restrict__ p1,
                            const float* __restrict__ p2,
                            const float* __restrict__ p3,
                            float alpha)
{
    __shared__ float As[BK][SPAD];
    __shared__ float Bs[BK][SPAD];

    const int tid = threadIdx.x;            // 256 threads
    const int tx = tid & 15;                // 16 x 16 thread grid
    const int ty = tid >> 4;
    const int bn0 = blockIdx.x * BN;
    const int bm0 = blockIdx.y * BM;

    float acc[4][4];
#pragma unroll
    for (int i = 0; i < 4; i++)
#pragma unroll
        for (int j = 0; j < 4; j++) acc[i][j] = 0.f;

    const int ktiles = (K + BK - 1) / BK;
    for (int kt = 0; kt < ktiles; kt++) {
        const int k0 = kt * BK;
        // load A tile: 1024 elems, 4 per thread (16 consecutive k per row -> coalesced)
#pragma unroll
        for (int u = 0; u < 4; u++) {
            int li = tid + u * 256;
            int ar = li >> 4, ac = li & 15;
            int gr = bm0 + ar, gk = k0 + ac;
            As[ac][ar] = (gr < M && gk < K) ? A[(size_t)gr * K + gk] : 0.f;
        }
        // load B tile
#pragma unroll
        for (int u = 0; u < 4; u++) {
            int li = tid + u * 256;
            if (!transB) {
                int bk = li >> 6, bnn = li & 63;
                int gk = k0 + bk, gn = bn0 + bnn;
                Bs[bk][bnn] = (gk < K && gn < N) ? B[(size_t)gk * ldb + gn] : 0.f;
            } else {
                int bnn = li >> 4, bk = li & 15;
                int gn = bn0 + bnn, gk = k0 + bk;
                Bs[bk][bnn] = (gn < N && gk < K) ? B[(size_t)gn * ldb + gk] : 0.f;
            }
        }
        __syncthreads();
#pragma unroll
        for (int kk = 0; kk < BK; kk++) {
            float4 a4 = *(const float4*)&As[kk][ty * 4];
            float4 b4 = *(const float4*)&Bs[kk][tx * 4];
            float a[4] = {a4.x, a4.y, a4.z, a4.w};
            float b[4] = {b4.x, b4.y, b4.z, b4.w};
#pragma unroll
            for (int i = 0; i < 4; i++)
#pragma unroll
                for (int j = 0; j < 4; j++)
                    acc[i][j] = fmaf(a[i], b[j], acc[i][j]);
        }
        __syncthreads();
    }

    // epilogue + store
#pragma unroll
    for (int i = 0; i < 4; i++) {
        int gr = bm0 + ty * 4 + i;
        if (gr >= M) continue;
#pragma unroll
        for (int j = 0; j < 4; j++) {
            int gc = bn0 + tx * 4 + j;
            if (gc >= N) continue;
            float z = acc[i][j];
            float y;
            if (ep == 0) {
                y = z;
            } else if (ep == 1) {
                y = fmaxf(z + p1[gc], 0.f);
            } else if (ep == 2) {
                y = fmaxf(z + p1[gc], 0.f) * p2[gc] + p3[gc];
            } else if (ep == 3) {
                y = z + p1[gc];
            } else if (ep == 4) {
                float g = 1.f / (1.f + expf(-(z + p1[gc])));
                float a = p2[(size_t)gr * N + gc];
                float h = p3[(size_t)gr * N + gc];
                y = fmaxf(g * a + (1.f - g) * h, 0.f);
            } else if (ep == 5) {
                y = tanhf(z + p1[gc]);
            } else { // 6
                y = p2[(size_t)gr * N + gc] + tanhf(z + p1[gc]) * alpha;
            }
            C[(size_t)gr * N + gc] = y;
        }
    }
}

// ---------------- row-normalize h -> hn ----------------
__global__ void rownorm_kernel()
{
    int row = blockIdx.x;
    int tid = threadIdx.x;                   // 256 == H_
    float v = g_h[row * H_ + tid];
    float s = v * v;
    // warp reduce
#pragma unroll
    for (int o = 16; o > 0; o >>= 1) s += __shfl_xor_sync(0xffffffff, s, o);
    __shared__ float ws[8];
    if ((tid & 31) == 0) ws[tid >> 5] = s;
    __syncthreads();
    float tot;
    if (tid < 8) {
        float t = ws[tid];
#pragma unroll
        for (int o = 4; o > 0; o >>= 1) t += __shfl_xor_sync(0xff, t, o);
        if (tid == 0) ws[0] = t;
    }
    __syncthreads();
    tot = ws[0];
    float denom = fmaxf(sqrtf(tot), 1e-12f);
    g_hn[row * H_ + tid] = v / denom;
}

// ---------------- per-row top-k over sim + adjacency normalize ----------------
__global__ void topk_kernel()
{
    const int row = blockIdx.x;
    const int tid = threadIdx.x;             // 256 threads
    const float* srow = g_sim + (size_t)row * NN_;

    float lv[KNN_];
    int   li[KNN_];
#pragma unroll
    for (int r = 0; r < KNN_; r++) { lv[r] = -INFINITY; li[r] = 0x7fffffff; }

    for (int j = tid; j < NN_; j += 256) {
        float v = srow[j];
        if (v > lv[KNN_ - 1]) {
            int p = KNN_ - 1;
            while (p > 0 && v > lv[p - 1]) { lv[p] = lv[p - 1]; li[p] = li[p - 1]; p--; }
            lv[p] = v; li[p] = j;
        }
    }

    __shared__ float sv[256 * KNN_];
    __shared__ int   si[256 * KNN_];
#pragma unroll
    for (int r = 0; r < KNN_; r++) { sv[tid * KNN_ + r] = lv[r]; si[tid * KNN_ + r] = li[r]; }
    __syncthreads();

    __shared__ float rv[256];
    __shared__ int   ri[256];
    __shared__ int   rp[256];
    __shared__ float outv[KNN_];
    __shared__ int   outi[KNN_];

    const int TOT = 256 * KNN_;
    for (int r = 0; r < KNN_; r++) {
        float bv = -INFINITY; int bi = 0x7fffffff; int bp = -1;
        for (int t = tid; t < TOT; t += 256) {
            float v = sv[t]; int ii = si[t];
            if (v > bv || (v == bv && ii < bi)) { bv = v; bi = ii; bp = t; }
        }
        rv[tid] = bv; ri[tid] = bi; rp[tid] = bp;
        __syncthreads();
        for (int s = 128; s > 0; s >>= 1) {
            if (tid < s) {
                float v2 = rv[tid + s]; int i2 = ri[tid + s];
                if (v2 > rv[tid] || (v2 == rv[tid] && i2 < ri[tid])) {
                    rv[tid] = v2; ri[tid] = i2; rp[tid] = rp[tid + s];
                }
            }
            __syncthreads();
        }
        if (tid == 0) {
            outv[r] = rv[0]; outi[r] = ri[0];
            sv[rp[0]] = -INFINITY;
        }
        __syncthreads();
    }

    if (tid == 0) {
        float s = 0.f;
#pragma unroll
        for (int r = 0; r < KNN_; r++) s += outv[r];
        float inv = 1.f / fmaxf(s, 1.f);
#pragma unroll
        for (int r = 0; r < KNN_; r++) {
            g_nidx[row * KNN_ + r] = outi[r];
            g_nval[row * KNN_ + r] = outv[r] * inv;
        }
    }
}

// ---------------- sparse aggregation: agg = adj @ ht (ht in g_h2) ----------------
__global__ void agg_kernel()
{
    int row = blockIdx.x;
    int tid = threadIdx.x;                  // 256 == H_
    float acc = 0.f;
#pragma unroll
    for (int r = 0; r < KNN_; r++) {
        float w = g_nval[row * KNN_ + r];
        int   n = g_nidx[row * KNN_ + r];
        acc += w * g_h2[(size_t)n * H_ + tid];
    }
    g_agg[row * H_ + tid] = acc;
}

// ---------------- tiny precompute: BN fold, gate time-embedding bias, SDE biases ----------------
__global__ void precompute_kernel(const float* __restrict__ bn_g, const float* __restrict__ bn_b,
                                  const float* __restrict__ bn_m, const float* __restrict__ bn_v,
                                  const float* __restrict__ t_w1, const float* __restrict__ t_b1,
                                  const float* __restrict__ t_w2, const float* __restrict__ t_b2,
                                  const float* __restrict__ gate_w, const float* __restrict__ gate_b,
                                  const float* __restrict__ sde_w1, const float* __restrict__ sde_b1)
{
    int b = blockIdx.x;
    int j = threadIdx.x;                    // 256 threads
    if (b == 0) {
        float s = bn_g[j] * rsqrtf(bn_v[j] + 1e-5f);
        g_bnscale[j] = s;
        g_bnshift[j] = bn_b[j] - bn_m[j] * s;
    } else if (b <= NL_) {
        int l = b - 1;
        float t = 0.5f * (float)l;
        __shared__ float te[TD_];
        __shared__ float te2[H_];
        if (j < TD_) te[j] = fmaxf(t * t_w1[l * TD_ + j] + t_b1[l * TD_ + j], 0.f);
        __syncthreads();
        float acc = t_b2[l * H_ + j];
#pragma unroll
        for (int k = 0; k < TD_; k++) acc += te[k] * t_w2[l * TD_ * H_ + k * H_ + j];
        te2[j] = acc;
        __syncthreads();
        float c = gate_b[l * H_ + j];
        const float* W = gate_w + (size_t)l * 2 * H_ * H_ + (size_t)H_ * H_; // bottom half
        for (int k = 0; k < H_; k++) c += te2[k] * W[k * H_ + j];
        g_gatec[l * H_ + j] = c;
    } else {
        int s = b - 1 - NL_;                // 0..9
        float ts = (float)s * 0.1f;
        g_sdebias[s * H_ + j] = sde_b1[j] + ts * sde_w1[H_ * H_ + j];
    }
}

// ---------------- host ----------------
static inline void launch_gemm(const float* A, const float* B, float* C,
                               int M, int N, int K, int ldb, int transB, int ep,
                               const float* p1 = nullptr, const float* p2 = nullptr,
                               const float* p3 = nullptr, float alpha = 0.f)
{
    dim3 grid((N + BN - 1) / BN, (M + BM - 1) / BM);
    gemm_kernel<<<grid, 256>>>(A, B, C, M, N, K, ldb, transB, ep, p1, p2, p3, alpha);
}

extern "C" void kernel_launch(void* const* d_in, const int* in_sizes, int n_in,
                              void* d_out, int out_size)
{
    const float* x       = (const float*)d_in[0];
    const float* enc_w1  = (const float*)d_in[1];
    const float* enc_b1  = (const float*)d_in[2];
    const float* enc_w2  = (const float*)d_in[3];
    const float* enc_b2  = (const float*)d_in[4];
    const float* bn_g    = (const float*)d_in[5];
    const float* bn_b    = (const float*)d_in[6];
    const float* bn_m    = (const float*)d_in[7];
    const float* bn_v    = (const float*)d_in[8];
    const float* node_w  = (const float*)d_in[9];
    const float* node_b  = (const float*)d_in[10];
    const float* t_w1    = (const float*)d_in[11];
    const float* t_b1    = (const float*)d_in[12];
    const float* t_w2    = (const float*)d_in[13];
    const float* t_b2    = (const float*)d_in[14];
    const float* gate_w  = (const float*)d_in[15];
    const float* gate_b  = (const float*)d_in[16];
    const float* sde_w1  = (const float*)d_in[17];
    const float* sde_b1  = (const float*)d_in[18];
    const float* sde_w2  = (const float*)d_in[19];
    const float* sde_b2  = (const float*)d_in[20];
    const float* sde_w3  = (const float*)d_in[21];
    const float* sde_b3  = (const float*)d_in[22];
    const float* dec_w1  = (const float*)d_in[23];
    const float* dec_b1  = (const float*)d_in[24];
    const float* dec_w2  = (const float*)d_in[25];
    const float* dec_b2  = (const float*)d_in[26];
    float* out = (float*)d_out;

    float *sim, *h, *h2, *hn, *agg, *d1, *d2, *bns, *bnsh, *gatec, *sdeb;
    cudaGetSymbolAddress((void**)&sim,   g_sim);
    cudaGetSymbolAddress((void**)&h,     g_h);
    cudaGetSymbolAddress((void**)&h2,    g_h2);
    cudaGetSymbolAddress((void**)&hn,    g_hn);
    cudaGetSymbolAddress((void**)&agg,   g_agg);
    cudaGetSymbolAddress((void**)&d1,    g_d1);
    cudaGetSymbolAddress((void**)&d2,    g_d2);
    cudaGetSymbolAddress((void**)&bns,   g_bnscale);
    cudaGetSymbolAddress((void**)&bnsh,  g_bnshift);
    cudaGetSymbolAddress((void**)&gatec, g_gatec);
    cudaGetSymbolAddress((void**)&sdeb,  g_sdebias);

    // precompute folded BN, gate time biases, SDE effective biases
    precompute_kernel<<<1 + NL_ + NSTEPS_, 256>>>(bn_g, bn_b, bn_m, bn_v,
                                                  t_w1, t_b1, t_w2, t_b2,
                                                  gate_w, gate_b, sde_w1, sde_b1);

    // encoder
    launch_gemm(x, enc_w1, h2, NN_, H_, DIN_, H_, 0, /*ep=*/1, enc_b1);
    launch_gemm(h2, enc_w2, h, NN_, H_, H_, H_, 0, /*ep=*/2, enc_b2, bns, bnsh);

    // kNN graph
    rownorm_kernel<<<NN_, 256>>>();
    launch_gemm(hn, hn, sim, NN_, NN_, H_, H_, /*transB=*/1, /*ep=*/0);
    topk_kernel<<<NN_, 256>>>();

    // temporal gated graph conv layers
    for (int l = 0; l < NL_; l++) {
        const float* Wn = node_w + (size_t)l * H_ * H_;
        const float* bn_ = node_b + (size_t)l * H_;
        const float* Wg = gate_w + (size_t)l * 2 * H_ * H_;  // top half (first 256 rows)
        launch_gemm(h, Wn, h2, NN_, H_, H_, H_, 0, /*ep=*/3, bn_);   // ht -> h2
        agg_kernel<<<NN_, 256>>>();                                   // agg from adj, ht
        launch_gemm(agg, Wg, h, NN_, H_, H_, H_, 0, /*ep=*/4,
                    gatec + (size_t)l * H_, agg, h2);                 // h = relu(g*agg+(1-g)*ht)
    }

    // SDE (drift-only Euler, 10 steps)
    const float dt = 0.1f;
    for (int s = 0; s < NSTEPS_; s++) {
        launch_gemm(h, sde_w1, d1, NN_, H_, H_, H_, 0, /*ep=*/5, sdeb + (size_t)s * H_);
        launch_gemm(d1, sde_w2, d2, NN_, H_, H_, H_, 0, /*ep=*/5, sde_b2);
        launch_gemm(d2, sde_w3, h, NN_, H_, H_, H_, 0, /*ep=*/6, sde_b3, h, nullptr, dt);
    }

    // decoder
    launch_gemm(h, dec_w1, d1, NN_, H_ / 2, H_, H_ / 2, 0, /*ep=*/1, dec_b1);
    launch_gemm(d1, dec_w2, out, NN_, C_, H_ / 2, C_, 0, /*ep=*/3, dec_b2);
}

// round 2
// speedup vs baseline: 1.3581x; 1.3581x over previous
#include <cuda_runtime.h>
#include <cuda_bf16.h>
#include <math.h>
#include <stdint.h>

// ---------------- problem constants ----------------
#define NN_   8192
#define DIN_  83
#define H_    256
#define C_    34
#define TD_   16
#define NL_   2
#define KNN_  11
#define NSTEPS_ 10

// ---------------- scratch (device globals; no allocation allowed) ----------------
__device__ float g_sim[(size_t)NN_ * NN_];          // 256 MB
__device__ float g_h  [NN_ * H_];
__device__ float g_h2 [NN_ * H_];
__device__ float g_hn [NN_ * H_];
__device__ float g_agg[NN_ * H_];
__device__ float g_d1 [NN_ * H_];
__device__ float g_d2 [NN_ * H_];
__device__ int   g_nidx[NN_ * KNN_];
__device__ float g_nval[NN_ * KNN_];
__device__ float g_bnscale[H_];
__device__ float g_bnshift[H_];
__device__ float g_gatec[NL_ * H_];
__device__ float g_sdebias[NSTEPS_ * H_];

// ---------------- fp32 GEMM, 128x128x8 tiles, 8x8/thread, double buffered ----------------
// C[M,N] = A[M,K] (row-major) @ B
//   transB=0: B row-major [K,N], leading dim ldb (B[k*ldb+n])
//   transB=1: B row-major [N,K], leading dim ldb (B[n*ldb+k])
// Epilogues:
//   0: y = z
//   1: y = relu(z + p1[n])
//   2: y = relu(z + p1[n]) * p2[n] + p3[n]
//   3: y = z + p1[n]
//   4: g = sigmoid(z + p1[n]); y = relu(g*p2[i,n] + (1-g)*p3[i,n])
//   5: y = tanh(z + p1[n])
//   6: y = p2[i,n] + tanh(z + p1[n]) * alpha
#define BM 128
#define BN 128
#define BK 8

__global__ __launch_bounds__(256) void gemm_kernel(
    const float* __restrict__ A, const float* __restrict__ B, float* __restrict__ C,
    int M, int N, int K, int ldb, int transB, int ep,
    const float* __restrict__ p1, const float* __restrict__ p2,
    const float* __restrict__ p3, float alpha)
{
    __shared__ float As[2][BK][BM + 4];
    __shared__ float Bs[2][BK][BN + 4];

    const int tid = threadIdx.x;                // 256 threads
    const int tx  = tid & 15;                   // 16 x 16 thread grid
    const int ty  = tid >> 4;
    const int bn0 = blockIdx.x * BN;
    const int bm0 = blockIdx.y * BM;

    float acc[8][8];
#pragma unroll
    for (int i = 0; i < 8; i++)
#pragma unroll
        for (int j = 0; j < 8; j++) acc[i][j] = 0.f;

    // loader index maps
    const int aRow = tid >> 1;                  // 0..127
    const int aK   = (tid & 1) * 4;             // 0 or 4
    const int b0Row = tid >> 5;                 // 0..7   (transB=0: k index)
    const int b0N   = (tid & 31) * 4;           // 0..124 (transB=0: n index)
    const int b1Row = tid >> 1;                 // 0..127 (transB=1: n index)
    const int b1K   = (tid & 1) * 4;            // 0 or 4

    const bool avec  = ((K & 3) == 0);
    const bool b0vec = ((ldb & 3) == 0);
    const bool b1vec = ((ldb & 3) == 0) && ((K & 3) == 0);

    float ra[4], rb[4];
    const int ktiles = (K + BK - 1) / BK;

#define LOAD_A(kt) do {                                                        \
        int k0_ = (kt) * BK;                                                   \
        int gr_ = bm0 + aRow, gk_ = k0_ + aK;                                  \
        if (avec && gr_ < M && gk_ + 3 < K) {                                  \
            float4 v_ = *(const float4*)(A + (size_t)gr_ * K + gk_);           \
            ra[0] = v_.x; ra[1] = v_.y; ra[2] = v_.z; ra[3] = v_.w;            \
        } else {                                                               \
            _Pragma("unroll")                                                  \
            for (int j_ = 0; j_ < 4; j_++)                                     \
                ra[j_] = (gr_ < M && gk_ + j_ < K)                             \
                       ? A[(size_t)gr_ * K + gk_ + j_] : 0.f;                  \
        }                                                                      \
    } while (0)

#define LOAD_B(kt) do {                                                        \
        int k0_ = (kt) * BK;                                                   \
        if (!transB) {                                                         \
            int gk_ = k0_ + b0Row, gn_ = bn0 + b0N;                            \
            if (b0vec && gk_ < K && gn_ + 3 < N) {                             \
                float4 v_ = *(const float4*)(B + (size_t)gk_ * ldb + gn_);     \
                rb[0] = v_.x; rb[1] = v_.y; rb[2] = v_.z; rb[3] = v_.w;        \
            } else {                                                           \
                _Pragma("unroll")                                              \
                for (int j_ = 0; j_ < 4; j_++)                                 \
                    rb[j_] = (gk_ < K && gn_ + j_ < N)                         \
                           ? B[(size_t)gk_ * ldb + gn_ + j_] : 0.f;            \
            }                                                                  \
        } else {                                                               \
            int gn_ = bn0 + b1Row, gk_ = k0_ + b1K;                            \
            if (b1vec && gn_ < N && gk_ + 3 < K) {                             \
                float4 v_ = *(const float4*)(B + (size_t)gn_ * ldb + gk_);     \
                rb[0] = v_.x; rb[1] = v_.y; rb[2] = v_.z; rb[3] = v_.w;        \
            } else {                                                           \
                _Pragma("unroll")                                              \
                for (int j_ = 0; j_ < 4; j_++)                                 \
                    rb[j_] = (gn_ < N && gk_ + j_ < K)                         \
                           ? B[(size_t)gn_ * ldb + gk_ + j_] : 0.f;            \
            }                                                                  \
        }                                                                      \
    } while (0)

#define STS_AB(buf) do {                                                       \
        _Pragma("unroll")                                                      \
        for (int j_ = 0; j_ < 4; j_++) As[buf][aK + j_][aRow] = ra[j_];        \
        if (!transB) {                                                         \
            _Pragma("unroll")                                                  \
            for (int j_ = 0; j_ < 4; j_++) Bs[buf][b0Row][b0N + j_] = rb[j_];  \
        } else {                                                               \
            _Pragma("unroll")                                                  \
            for (int j_ = 0; j_ < 4; j_++) Bs[buf][b1K + j_][b1Row] = rb[j_];  \
        }                                                                      \
    } while (0)

    LOAD_A(0); LOAD_B(0);
    STS_AB(0);
    __syncthreads();

    int cur = 0;
    for (int kt = 0; kt < ktiles; kt++) {
        const int hasNext = (kt + 1 < ktiles);
        if (hasNext) { LOAD_A(kt + 1); LOAD_B(kt + 1); }

#pragma unroll
        for (int kk = 0; kk < BK; kk++) {
            const float* as = As[cur][kk];
            const float* bs = Bs[cur][kk];
            float4 A0 = *(const float4*)(as + ty * 4);
            float4 A1 = *(const float4*)(as + 64 + ty * 4);
            float4 B0 = *(const float4*)(bs + tx * 4);
            float4 B1 = *(const float4*)(bs + 64 + tx * 4);
            float av[8] = {A0.x, A0.y, A0.z, A0.w, A1.x, A1.y, A1.z, A1.w};
            float bv[8] = {B0.x, B0.y, B0.z, B0.w, B1.x, B1.y, B1.z, B1.w};
#pragma unroll
            for (int i = 0; i < 8; i++)
#pragma unroll
                for (int j = 0; j < 8; j++)
                    acc[i][j] = fmaf(av[i], bv[j], acc[i][j]);
        }

        if (hasNext) {
            STS_AB(cur ^ 1);
            __syncthreads();
            cur ^= 1;
        }
    }

    // ---- epilogue ----
    auto epi = [&](float z, int gr, int gc) -> float {
        if (ep == 0) return z;
        if (ep == 1) return fmaxf(z + p1[gc], 0.f);
        if (ep == 2) return fmaxf(z + p1[gc], 0.f) * p2[gc] + p3[gc];
        if (ep == 3) return z + p1[gc];
        if (ep == 4) {
            float g = 1.f / (1.f + expf(-(z + p1[gc])));
            float a = p2[(size_t)gr * N + gc];
            float h = p3[(size_t)gr * N + gc];
            return fmaxf(g * a + (1.f - g) * h, 0.f);
        }
        if (ep == 5) return tanhf(z + p1[gc]);
        return p2[(size_t)gr * N + gc] + tanhf(z + p1[gc]) * alpha;  // 6
    };

    if ((N & 3) == 0) {
#pragma unroll
        for (int i = 0; i < 8; i++) {
            int gr = bm0 + ((i < 4) ? (ty * 4 + i) : (64 + ty * 4 + (i - 4)));
            if (gr >= M) continue;
            int gc0 = bn0 + tx * 4;
            int gc1 = bn0 + 64 + tx * 4;
            if (gc0 + 3 < N) {
                float4 o;
                o.x = epi(acc[i][0], gr, gc0 + 0);
                o.y = epi(acc[i][1], gr, gc0 + 1);
                o.z = epi(acc[i][2], gr, gc0 + 2);
                o.w = epi(acc[i][3], gr, gc0 + 3);
                *(float4*)(C + (size_t)gr * N + gc0) = o;
            } else {
#pragma unroll
                for (int j = 0; j < 4; j++)
                    if (gc0 + j < N) C[(size_t)gr * N + gc0 + j] = epi(acc[i][j], gr, gc0 + j);
            }
            if (gc1 + 3 < N) {
                float4 o;
                o.x = epi(acc[i][4], gr, gc1 + 0);
                o.y = epi(acc[i][5], gr, gc1 + 1);
                o.z = epi(acc[i][6], gr, gc1 + 2);
                o.w = epi(acc[i][7], gr, gc1 + 3);
                *(float4*)(C + (size_t)gr * N + gc1) = o;
            } else {
#pragma unroll
                for (int j = 0; j < 4; j++)
                    if (gc1 + j < N) C[(size_t)gr * N + gc1 + j] = epi(acc[i][4 + j], gr, gc1 + j);
            }
        }
    } else {
#pragma unroll
        for (int i = 0; i < 8; i++) {
            int gr = bm0 + ((i < 4) ? (ty * 4 + i) : (64 + ty * 4 + (i - 4)));
            if (gr >= M) continue;
#pragma unroll
            for (int j = 0; j < 8; j++) {
                int gc = bn0 + ((j < 4) ? (tx * 4 + j) : (64 + tx * 4 + (j - 4)));
                if (gc < N) C[(size_t)gr * N + gc] = epi(acc[i][j], gr, gc);
            }
        }
    }
}

// ---------------- row-normalize h -> hn ----------------
__global__ void rownorm_kernel()
{
    int row = blockIdx.x;
    int tid = threadIdx.x;                   // 256 == H_
    float v = g_h[row * H_ + tid];
    float s = v * v;
#pragma unroll
    for (int o = 16; o > 0; o >>= 1) s += __shfl_xor_sync(0xffffffff, s, o);
    __shared__ float ws[8];
    if ((tid & 31) == 0) ws[tid >> 5] = s;
    __syncthreads();
    float tot;
    if (tid < 8) {
        float t = ws[tid];
#pragma unroll
        for (int o = 4; o > 0; o >>= 1) t += __shfl_xor_sync(0xff, t, o);
        if (tid == 0) ws[0] = t;
    }
    __syncthreads();
    tot = ws[0];
    float denom = fmaxf(sqrtf(tot), 1e-12f);
    g_hn[row * H_ + tid] = v / denom;
}

// ---------------- per-row top-k over sim + adjacency normalize ----------------
__global__ void topk_kernel()
{
    const int row = blockIdx.x;
    const int tid = threadIdx.x;             // 256 threads
    const float* srow = g_sim + (size_t)row * NN_;

    float lv[KNN_];
    int   li[KNN_];
#pragma unroll
    for (int r = 0; r < KNN_; r++) { lv[r] = -INFINITY; li[r] = 0x7fffffff; }

    for (int j = tid; j < NN_; j += 256) {
        float v = srow[j];
        if (v > lv[KNN_ - 1]) {
            int p = KNN_ - 1;
            while (p > 0 && v > lv[p - 1]) { lv[p] = lv[p - 1]; li[p] = li[p - 1]; p--; }
            lv[p] = v; li[p] = j;
        }
    }

    __shared__ float sv[256 * KNN_];
    __shared__ int   si[256 * KNN_];
#pragma unroll
    for (int r = 0; r < KNN_; r++) { sv[tid * KNN_ + r] = lv[r]; si[tid * KNN_ + r] = li[r]; }
    __syncthreads();

    __shared__ float rv[256];
    __shared__ int   ri[256];
    __shared__ int   rp[256];
    __shared__ float outv[KNN_];
    __shared__ int   outi[KNN_];

    const int TOT = 256 * KNN_;
    for (int r = 0; r < KNN_; r++) {
        float bv = -INFINITY; int bi = 0x7fffffff; int bp = -1;
        for (int t = tid; t < TOT; t += 256) {
            float v = sv[t]; int ii = si[t];
            if (v > bv || (v == bv && ii < bi)) { bv = v; bi = ii; bp = t; }
        }
        rv[tid] = bv; ri[tid] = bi; rp[tid] = bp;
        __syncthreads();
        for (int s = 128; s > 0; s >>= 1) {
            if (tid < s) {
                float v2 = rv[tid + s]; int i2 = ri[tid + s];
                if (v2 > rv[tid] || (v2 == rv[tid] && i2 < ri[tid])) {
                    rv[tid] = v2; ri[tid] = i2; rp[tid] = rp[tid + s];
                }
            }
            __syncthreads();
        }
        if (tid == 0) {
            outv[r] = rv[0]; outi[r] = ri[0];
            sv[rp[0]] = -INFINITY;
        }
        __syncthreads();
    }

    if (tid == 0) {
        float s = 0.f;
#pragma unroll
        for (int r = 0; r < KNN_; r++) s += outv[r];
        float inv = 1.f / fmaxf(s, 1.f);
#pragma unroll
        for (int r = 0; r < KNN_; r++) {
            g_nidx[row * KNN_ + r] = outi[r];
            g_nval[row * KNN_ + r] = outv[r] * inv;
        }
    }
}

// ---------------- sparse aggregation: agg = adj @ ht (ht in g_h2) ----------------
__global__ void agg_kernel()
{
    int row = blockIdx.x;
    int tid = threadIdx.x;                  // 256 == H_
    float acc = 0.f;
#pragma unroll
    for (int r = 0; r < KNN_; r++) {
        float w = g_nval[row * KNN_ + r];
        int   n = g_nidx[row * KNN_ + r];
        acc += w * g_h2[(size_t)n * H_ + tid];
    }
    g_agg[row * H_ + tid] = acc;
}

// ---------------- tiny precompute: BN fold, gate time-embedding bias, SDE biases ----------------
__global__ void precompute_kernel(const float* __restrict__ bn_g, const float* __restrict__ bn_b,
                                  const float* __restrict__ bn_m, const float* __restrict__ bn_v,
                                  const float* __restrict__ t_w1, const float* __restrict__ t_b1,
                                  const float* __restrict__ t_w2, const float* __restrict__ t_b2,
                                  const float* __restrict__ gate_w, const float* __restrict__ gate_b,
                                  const float* __restrict__ sde_w1, const float* __restrict__ sde_b1)
{
    int b = blockIdx.x;
    int j = threadIdx.x;                    // 256 threads
    if (b == 0) {
        float s = bn_g[j] * rsqrtf(bn_v[j] + 1e-5f);
        g_bnscale[j] = s;
        g_bnshift[j] = bn_b[j] - bn_m[j] * s;
    } else if (b <= NL_) {
        int l = b - 1;
        float t = 0.5f * (float)l;
        __shared__ float te[TD_];
        __shared__ float te2[H_];
        if (j < TD_) te[j] = fmaxf(t * t_w1[l * TD_ + j] + t_b1[l * TD_ + j], 0.f);
        __syncthreads();
        float acc = t_b2[l * H_ + j];
#pragma unroll
        for (int k = 0; k < TD_; k++) acc += te[k] * t_w2[l * TD_ * H_ + k * H_ + j];
        te2[j] = acc;
        __syncthreads();
        float c = gate_b[l * H_ + j];
        const float* W = gate_w + (size_t)l * 2 * H_ * H_ + (size_t)H_ * H_; // bottom half
        for (int k = 0; k < H_; k++) c += te2[k] * W[k * H_ + j];
        g_gatec[l * H_ + j] = c;
    } else {
        int s = b - 1 - NL_;                // 0..9
        float ts = (float)s * 0.1f;
        g_sdebias[s * H_ + j] = sde_b1[j] + ts * sde_w1[H_ * H_ + j];
    }
}

// ---------------- host ----------------
static inline void launch_gemm(const float* A, const float* B, float* C,
                               int M, int N, int K, int ldb, int transB, int ep,
                               const float* p1 = nullptr, const float* p2 = nullptr,
                               const float* p3 = nullptr, float alpha = 0.f)
{
    dim3 grid((N + BN - 1) / BN, (M + BM - 1) / BM);
    gemm_kernel<<<grid, 256>>>(A, B, C, M, N, K, ldb, transB, ep, p1, p2, p3, alpha);
}

extern "C" void kernel_launch(void* const* d_in, const int* in_sizes, int n_in,
                              void* d_out, int out_size)
{
    const float* x       = (const float*)d_in[0];
    const float* enc_w1  = (const float*)d_in[1];
    const float* enc_b1  = (const float*)d_in[2];
    const float* enc_w2  = (const float*)d_in[3];
    const float* enc_b2  = (const float*)d_in[4];
    const float* bn_g    = (const float*)d_in[5];
    const float* bn_b    = (const float*)d_in[6];
    const float* bn_m    = (const float*)d_in[7];
    const float* bn_v    = (const float*)d_in[8];
    const float* node_w  = (const float*)d_in[9];
    const float* node_b  = (const float*)d_in[10];
    const float* t_w1    = (const float*)d_in[11];
    const float* t_b1    = (const float*)d_in[12];
    const float* t_w2    = (const float*)d_in[13];
    const float* t_b2    = (const float*)d_in[14];
    const float* gate_w  = (const float*)d_in[15];
    const float* gate_b  = (const float*)d_in[16];
    const float* sde_w1  = (const float*)d_in[17];
    const float* sde_b1  = (const float*)d_in[18];
    const float* sde_w2  = (const float*)d_in[19];
    const float* sde_b2  = (const float*)d_in[20];
    const float* sde_w3  = (const float*)d_in[21];
    const float* sde_b3  = (const float*)d_in[22];
    const float* dec_w1  = (const float*)d_in[23];
    const float* dec_b1  = (const float*)d_in[24];
    const float* dec_w2  = (const float*)d_in[25];
    const float* dec_b2  = (const float*)d_in[26];
    float* out = (float*)d_out;

    float *sim, *h, *h2, *hn, *agg, *d1, *d2, *bns, *bnsh, *gatec, *sdeb;
    cudaGetSymbolAddress((void**)&sim,   g_sim);
    cudaGetSymbolAddress((void**)&h,     g_h);
    cudaGetSymbolAddress((void**)&h2,    g_h2);
    cudaGetSymbolAddress((void**)&hn,    g_hn);
    cudaGetSymbolAddress((void**)&agg,   g_agg);
    cudaGetSymbolAddress((void**)&d1,    g_d1);
    cudaGetSymbolAddress((void**)&d2,    g_d2);
    cudaGetSymbolAddress((void**)&bns,   g_bnscale);
    cudaGetSymbolAddress((void**)&bnsh,  g_bnshift);
    cudaGetSymbolAddress((void**)&gatec, g_gatec);
    cudaGetSymbolAddress((void**)&sdeb,  g_sdebias);

    // precompute folded BN, gate time biases, SDE effective biases
    precompute_kernel<<<1 + NL_ + NSTEPS_, 256>>>(bn_g, bn_b, bn_m, bn_v,
                                                  t_w1, t_b1, t_w2, t_b2,
                                                  gate_w, gate_b, sde_w1, sde_b1);

    // encoder
    launch_gemm(x, enc_w1, h2, NN_, H_, DIN_, H_, 0, /*ep=*/1, enc_b1);
    launch_gemm(h2, enc_w2, h, NN_, H_, H_, H_, 0, /*ep=*/2, enc_b2, bns, bnsh);

    // kNN graph
    rownorm_kernel<<<NN_, 256>>>();
    launch_gemm(hn, hn, sim, NN_, NN_, H_, H_, /*transB=*/1, /*ep=*/0);
    topk_kernel<<<NN_, 256>>>();

    // temporal gated graph conv layers
    for (int l = 0; l < NL_; l++) {
        const float* Wn = node_w + (size_t)l * H_ * H_;
        const float* bn_ = node_b + (size_t)l * H_;
        const float* Wg = gate_w + (size_t)l * 2 * H_ * H_;  // top half (first 256 rows)
        launch_gemm(h, Wn, h2, NN_, H_, H_, H_, 0, /*ep=*/3, bn_);   // ht -> h2
        agg_kernel<<<NN_, 256>>>();                                   // agg from adj, ht
        launch_gemm(agg, Wg, h, NN_, H_, H_, H_, 0, /*ep=*/4,
                    gatec + (size_t)l * H_, agg, h2);                 // h = relu(g*agg+(1-g)*ht)
    }

    // SDE (drift-only Euler, 10 steps)
    const float dt = 0.1f;
    for (int s = 0; s < NSTEPS_; s++) {
        launch_gemm(h, sde_w1, d1, NN_, H_, H_, H_, 0, /*ep=*/5, sdeb + (size_t)s * H_);
        launch_gemm(d1, sde_w2, d2, NN_, H_, H_, H_, 0, /*ep=*/5, sde_b2);
        launch_gemm(d2, sde_w3, h, NN_, H_, H_, H_, 0, /*ep=*/6, sde_b3, h, nullptr, dt);
    }

    // decoder
    launch_gemm(h, dec_w1, d1, NN_, H_ / 2, H_, H_ / 2, 0, /*ep=*/1, dec_b1);
    launch_gemm(d1, dec_w2, out, NN_, C_, H_ / 2, C_, 0, /*ep=*/3, dec_b2);
}

// round 4
// speedup vs baseline: 1.8313x; 1.3484x over previous
#include <cuda_runtime.h>
#include <cuda_bf16.h>
#include <math.h>
#include <stdint.h>

// ---------------- problem constants ----------------
#define NN_   8192
#define DIN_  83
#define H_    256
#define C_    34
#define TD_   16
#define NL_   2
#define KNN_  11
#define NSTEPS_ 10

typedef __nv_bfloat16 bf16;

// ---------------- scratch (device globals; no allocation allowed) ----------------
__device__ float g_sim[(size_t)NN_ * NN_];          // 256 MB
__device__ float g_h  [NN_ * H_];
__device__ float g_h2 [NN_ * H_];
__device__ float g_hn [NN_ * H_];
__device__ float g_agg[NN_ * H_];
__device__ float g_d1 [NN_ * H_];
__device__ float g_d2 [NN_ * H_];
__device__ int   g_nidx[NN_ * KNN_];
__device__ float g_nval[NN_ * KNN_];
__device__ float g_bnscale[H_];
__device__ float g_bnshift[H_];
__device__ float g_gatec[NL_ * H_];
__device__ float g_sdebias[NSTEPS_ * H_];

// bf16 split copies of activations ([M,256] row-major hi/lo)
__device__ bf16 g_h_hi [NN_ * H_],  g_h_lo [NN_ * H_];
__device__ bf16 g_h2_hi[NN_ * H_],  g_h2_lo[NN_ * H_];
__device__ bf16 g_hn_hi[NN_ * H_],  g_hn_lo[NN_ * H_];
__device__ bf16 g_ag_hi[NN_ * H_],  g_ag_lo[NN_ * H_];
__device__ bf16 g_d1_hi[NN_ * H_],  g_d1_lo[NN_ * H_];
__device__ bf16 g_d2_hi[NN_ * H_],  g_d2_lo[NN_ * H_];

// transposed+split weights, [N,256] K-major; 9 slots of 64K elems
#define WSLOT 65536
__device__ bf16 g_w_hi[9 * WSLOT];
__device__ bf16 g_w_lo[9 * WSLOT];

// ================= helpers =================
__device__ __forceinline__ uint32_t smem_u32(const void* p) {
    uint32_t a;
    asm("{ .reg .u64 t; cvta.to.shared.u64 t, %1; cvt.u32.u64 %0, t; }" : "=r"(a) : "l"(p));
    return a;
}
__device__ __forceinline__ void ldsm4(uint32_t* r, uint32_t addr) {
    asm volatile("ldmatrix.sync.aligned.m8n8.x4.shared.b16 {%0,%1,%2,%3}, [%4];"
                 : "=r"(r[0]), "=r"(r[1]), "=r"(r[2]), "=r"(r[3]) : "r"(addr));
}
__device__ __forceinline__ void mma16816(float* d, const uint32_t* a, uint32_t b0, uint32_t b1) {
    asm volatile("mma.sync.aligned.m16n8k16.row.col.f32.bf16.bf16.f32 "
                 "{%0,%1,%2,%3}, {%4,%5,%6,%7}, {%8,%9}, {%0,%1,%2,%3};"
                 : "+f"(d[0]), "+f"(d[1]), "+f"(d[2]), "+f"(d[3])
                 : "r"(a[0]), "r"(a[1]), "r"(a[2]), "r"(a[3]), "r"(b0), "r"(b1));
}

// ================= tensor-core split-bf16 GEMM (mma.sync HMMA) =================
// C[M=8192, Ntot] = (Ahi+Alo) @ (Bhi+Blo)^T
//   A: [M,256] K-major bf16 hi/lo; B: [Ntot,256] K-major bf16 hi/lo
// 3 split terms: AhBh + AhBl + AlBh, fp32 register accumulation.
// CTA tile 128x128, K chunked 8 x 32; 8 warps, each warp 32(m) x 64(n).
// Epilogues:
//   0: y=z  1: relu(z+p1[n])  2: relu(z+p1[n])*p2[n]+p3[n]  3: z+p1[n]
//   4: g=sigmoid(z+p1[n]); y=relu(g*p2[i,n]+(1-g)*p3[i,n])
//   5: tanh(z+p1[n])  6: p2[i,n] + tanh(z+p1[n])*alpha

__device__ __forceinline__ void load_tile32(const bf16* __restrict__ src, int r0, int k0,
                                            bf16* __restrict__ dst, int tid)
{
#pragma unroll
    for (int u = 0; u < 2; u++) {
        int i = tid + u * 256;                  // 0..511 16B segments
        int row = i >> 2;                       // 0..127
        int seg = i & 3;                        // 0..3 (8 bf16 each)
        uint4 v = *(const uint4*)(src + (size_t)(r0 + row) * 256 + k0 + seg * 8);
        uint32_t off = (uint32_t)row * 64u + (uint32_t)((seg ^ ((row >> 1) & 3)) << 4);
        *(uint4*)((char*)dst + off) = v;
    }
}

__global__ __launch_bounds__(256) void mma_gemm(
    const bf16* __restrict__ Ahi, const bf16* __restrict__ Alo,
    const bf16* __restrict__ Bhi, const bf16* __restrict__ Blo,
    float* __restrict__ C, int Ntot, int ep,
    const float* __restrict__ p1, const float* __restrict__ p2,
    const float* __restrict__ p3, float alpha,
    bf16* __restrict__ Chi, bf16* __restrict__ Clo)
{
    __shared__ bf16 sAh[128 * 32], sAl[128 * 32], sBh[128 * 32], sBl[128 * 32];

    const int tid  = threadIdx.x;
    const int wid  = tid >> 5;
    const int lane = tid & 31;
    const int warp_m = wid & 3;                 // 4 warps over m (32 rows each)
    const int warp_n = wid >> 2;                // 2 warps over n (64 cols each)
    const int bn0 = blockIdx.x * 128;
    const int bm0 = blockIdx.y * 128;

    const uint32_t sAh_b = smem_u32(sAh), sAl_b = smem_u32(sAl);
    const uint32_t sBh_b = smem_u32(sBh), sBl_b = smem_u32(sBl);

    float acc[2][8][4];
#pragma unroll
    for (int i = 0; i < 2; i++)
#pragma unroll
        for (int j = 0; j < 8; j++)
#pragma unroll
            for (int q = 0; q < 4; q++) acc[i][j][q] = 0.f;

    const int lrow = lane & 15;                 // ldmatrix row within 16
    const int lhalf = lane >> 4;                // k half (0/1)

    for (int chunk = 0; chunk < 8; chunk++) {
        const int k0 = chunk * 32;
        load_tile32(Ahi, bm0, k0, sAh, tid);
        load_tile32(Alo, bm0, k0, sAl, tid);
        load_tile32(Bhi, bn0, k0, sBh, tid);
        load_tile32(Blo, bn0, k0, sBl, tid);
        __syncthreads();

#pragma unroll
        for (int kk = 0; kk < 2; kk++) {
            const int segq = kk * 2 + lhalf;    // requested 16B segment (0..3)

            // A fragments for both m-tiles, hi and lo
            uint32_t aH[2][4], aL[2][4];
#pragma unroll
            for (int mt = 0; mt < 2; mt++) {
                int row = warp_m * 32 + mt * 16 + lrow;
                uint32_t off = (uint32_t)row * 64u + (uint32_t)((segq ^ ((row >> 1) & 3)) << 4);
                ldsm4(aH[mt], sAh_b + off);
                ldsm4(aL[mt], sAl_b + off);
            }

#pragma unroll
            for (int g = 0; g < 4; g++) {
                int row = warp_n * 64 + g * 16 + lrow;
                uint32_t off = (uint32_t)row * 64u + (uint32_t)((segq ^ ((row >> 1) & 3)) << 4);
                uint32_t bH[4], bL[4];
                ldsm4(bH, sBh_b + off);
                ldsm4(bL, sBl_b + off);
#pragma unroll
                for (int mt = 0; mt < 2; mt++) {
                    // term hi*hi
                    mma16816(acc[mt][2 * g + 0], aH[mt], bH[0], bH[2]);
                    mma16816(acc[mt][2 * g + 1], aH[mt], bH[1], bH[3]);
                    // term hi*lo
                    mma16816(acc[mt][2 * g + 0], aH[mt], bL[0], bL[2]);
                    mma16816(acc[mt][2 * g + 1], aH[mt], bL[1], bL[3]);
                    // term lo*hi
                    mma16816(acc[mt][2 * g + 0], aL[mt], bH[0], bH[2]);
                    mma16816(acc[mt][2 * g + 1], aL[mt], bH[1], bH[3]);
                }
            }
        }
        __syncthreads();
    }

    // ---- epilogue ----
    auto epi = [&](float z, int gr, int gc) -> float {
        if (ep == 0) return z;
        if (ep == 1) return fmaxf(z + p1[gc], 0.f);
        if (ep == 2) return fmaxf(z + p1[gc], 0.f) * p2[gc] + p3[gc];
        if (ep == 3) return z + p1[gc];
        if (ep == 4) {
            float g = 1.f / (1.f + expf(-(z + p1[gc])));
            float a = p2[(size_t)gr * Ntot + gc];
            float hh = p3[(size_t)gr * Ntot + gc];
            return fmaxf(g * a + (1.f - g) * hh, 0.f);
        }
        if (ep == 5) return tanhf(z + p1[gc]);
        return p2[(size_t)gr * Ntot + gc] + tanhf(z + p1[gc]) * alpha;  // 6
    };

#pragma unroll
    for (int mt = 0; mt < 2; mt++) {
#pragma unroll
        for (int half = 0; half < 2; half++) {
            int gr = bm0 + warp_m * 32 + mt * 16 + (lane >> 2) + half * 8;
#pragma unroll
            for (int nt = 0; nt < 8; nt++) {
                int gc = bn0 + warp_n * 64 + nt * 8 + (lane & 3) * 2;
                float y0 = epi(acc[mt][nt][half * 2 + 0], gr, gc);
                float y1 = epi(acc[mt][nt][half * 2 + 1], gr, gc + 1);
                float2 o; o.x = y0; o.y = y1;
                *(float2*)(C + (size_t)gr * Ntot + gc) = o;
                if (Chi) {
                    bf16 h0 = __float2bfloat16_rn(y0);
                    bf16 h1 = __float2bfloat16_rn(y1);
                    __nv_bfloat162 hp; hp.x = h0; hp.y = h1;
                    __nv_bfloat162 lp;
                    lp.x = __float2bfloat16_rn(y0 - __bfloat162float(h0));
                    lp.y = __float2bfloat16_rn(y1 - __bfloat162float(h1));
                    *(__nv_bfloat162*)(Chi + (size_t)gr * 256 + gc) = hp;
                    *(__nv_bfloat162*)(Clo + (size_t)gr * 256 + gc) = lp;
                }
            }
        }
    }
}

// ================= SIMT fp32 GEMM (odd shapes: enc1 K=83, dec2 N=34) =================
#define BM 128
#define BN 128
#define BK 8

__global__ __launch_bounds__(256) void gemm_kernel(
    const float* __restrict__ A, const float* __restrict__ B, float* __restrict__ C,
    int M, int N, int K, int ldb, int ep,
    const float* __restrict__ p1, bf16* __restrict__ Chi, bf16* __restrict__ Clo)
{
    __shared__ float As[2][BK][BM + 4];
    __shared__ float Bs[2][BK][BN + 4];

    const int tid = threadIdx.x;
    const int tx  = tid & 15;
    const int ty  = tid >> 4;
    const int bn0 = blockIdx.x * BN;
    const int bm0 = blockIdx.y * BM;

    float acc[8][8];
#pragma unroll
    for (int i = 0; i < 8; i++)
#pragma unroll
        for (int j = 0; j < 8; j++) acc[i][j] = 0.f;

    const int aRow = tid >> 1;
    const int aK   = (tid & 1) * 4;
    const int bRow = tid >> 5;
    const int bN   = (tid & 31) * 4;

    float ra[4], rb[4];
    const int ktiles = (K + BK - 1) / BK;

#define LOAD_AB(kt) do {                                                       \
        int k0_ = (kt) * BK;                                                   \
        int gr_ = bm0 + aRow, gk_ = k0_ + aK;                                  \
        _Pragma("unroll")                                                      \
        for (int j_ = 0; j_ < 4; j_++)                                         \
            ra[j_] = (gr_ < M && gk_ + j_ < K) ? A[(size_t)gr_ * K + gk_ + j_] : 0.f; \
        int gk2_ = k0_ + bRow, gn_ = bn0 + bN;                                 \
        _Pragma("unroll")                                                      \
        for (int j_ = 0; j_ < 4; j_++)                                         \
            rb[j_] = (gk2_ < K && gn_ + j_ < N) ? B[(size_t)gk2_ * ldb + gn_ + j_] : 0.f; \
    } while (0)

#define STS_AB2(buf) do {                                                      \
        _Pragma("unroll")                                                      \
        for (int j_ = 0; j_ < 4; j_++) As[buf][aK + j_][aRow] = ra[j_];        \
        _Pragma("unroll")                                                      \
        for (int j_ = 0; j_ < 4; j_++) Bs[buf][bRow][bN + j_] = rb[j_];        \
    } while (0)

    LOAD_AB(0);
    STS_AB2(0);
    __syncthreads();

    int cur = 0;
    for (int kt = 0; kt < ktiles; kt++) {
        const int hasNext = (kt + 1 < ktiles);
        if (hasNext) LOAD_AB(kt + 1);
#pragma unroll
        for (int kk = 0; kk < BK; kk++) {
            const float* as = As[cur][kk];
            const float* bs = Bs[cur][kk];
            float4 A0 = *(const float4*)(as + ty * 4);
            float4 A1 = *(const float4*)(as + 64 + ty * 4);
            float4 B0 = *(const float4*)(bs + tx * 4);
            float4 B1 = *(const float4*)(bs + 64 + tx * 4);
            float av[8] = {A0.x, A0.y, A0.z, A0.w, A1.x, A1.y, A1.z, A1.w};
            float bv[8] = {B0.x, B0.y, B0.z, B0.w, B1.x, B1.y, B1.z, B1.w};
#pragma unroll
            for (int i = 0; i < 8; i++)
#pragma unroll
                for (int j = 0; j < 8; j++)
                    acc[i][j] = fmaf(av[i], bv[j], acc[i][j]);
        }
        if (hasNext) { STS_AB2(cur ^ 1); __syncthreads(); cur ^= 1; }
    }

#pragma unroll
    for (int i = 0; i < 8; i++) {
        int gr = bm0 + ((i < 4) ? (ty * 4 + i) : (64 + ty * 4 + (i - 4)));
        if (gr >= M) continue;
#pragma unroll
        for (int j = 0; j < 8; j++) {
            int gc = bn0 + ((j < 4) ? (tx * 4 + j) : (64 + tx * 4 + (j - 4)));
            if (gc >= N) continue;
            float z = acc[i][j];
            float y;
            if (ep == 1) y = fmaxf(z + p1[gc], 0.f);
            else if (ep == 3) y = z + p1[gc];
            else y = z;
            C[(size_t)gr * N + gc] = y;
            if (Chi) {
                bf16 hb = __float2bfloat16_rn(y);
                Chi[(size_t)gr * 256 + gc] = hb;
                Clo[(size_t)gr * 256 + gc] = __float2bfloat16_rn(y - __bfloat162float(hb));
            }
        }
    }
}

// ---------------- row-normalize h -> hn (+ bf16 split) ----------------
__global__ void rownorm_kernel()
{
    int row = blockIdx.x;
    int tid = threadIdx.x;                   // 256 == H_
    float v = g_h[row * H_ + tid];
    float s = v * v;
#pragma unroll
    for (int o = 16; o > 0; o >>= 1) s += __shfl_xor_sync(0xffffffff, s, o);
    __shared__ float ws[8];
    if ((tid & 31) == 0) ws[tid >> 5] = s;
    __syncthreads();
    if (tid < 8) {
        float t = ws[tid];
#pragma unroll
        for (int o = 4; o > 0; o >>= 1) t += __shfl_xor_sync(0xff, t, o);
        if (tid == 0) ws[0] = t;
    }
    __syncthreads();
    float denom = fmaxf(sqrtf(ws[0]), 1e-12f);
    float y = v / denom;
    g_hn[row * H_ + tid] = y;
    bf16 hb = __float2bfloat16_rn(y);
    g_hn_hi[row * H_ + tid] = hb;
    g_hn_lo[row * H_ + tid] = __float2bfloat16_rn(y - __bfloat162float(hb));
}

// ---------------- per-row top-k over sim + adjacency normalize ----------------
__global__ void topk_kernel()
{
    const int row = blockIdx.x;
    const int tid = threadIdx.x;
    const float* srow = g_sim + (size_t)row * NN_;

    float lv[KNN_];
    int   li[KNN_];
#pragma unroll
    for (int r = 0; r < KNN_; r++) { lv[r] = -INFINITY; li[r] = 0x7fffffff; }

    for (int j = tid; j < NN_; j += 256) {
        float v = srow[j];
        if (v > lv[KNN_ - 1]) {
            int p = KNN_ - 1;
            while (p > 0 && v > lv[p - 1]) { lv[p] = lv[p - 1]; li[p] = li[p - 1]; p--; }
            lv[p] = v; li[p] = j;
        }
    }

    __shared__ float sv[256 * KNN_];
    __shared__ int   si[256 * KNN_];
#pragma unroll
    for (int r = 0; r < KNN_; r++) { sv[tid * KNN_ + r] = lv[r]; si[tid * KNN_ + r] = li[r]; }
    __syncthreads();

    __shared__ float rv[256];
    __shared__ int   ri[256];
    __shared__ int   rp[256];
    __shared__ float outv[KNN_];
    __shared__ int   outi[KNN_];

    const int TOT = 256 * KNN_;
    for (int r = 0; r < KNN_; r++) {
        float bv = -INFINITY; int bi = 0x7fffffff; int bp = -1;
        for (int t = tid; t < TOT; t += 256) {
            float v = sv[t]; int ii = si[t];
            if (v > bv || (v == bv && ii < bi)) { bv = v; bi = ii; bp = t; }
        }
        rv[tid] = bv; ri[tid] = bi; rp[tid] = bp;
        __syncthreads();
        for (int s = 128; s > 0; s >>= 1) {
            if (tid < s) {
                float v2 = rv[tid + s]; int i2 = ri[tid + s];
                if (v2 > rv[tid] || (v2 == rv[tid] && i2 < ri[tid])) {
                    rv[tid] = v2; ri[tid] = i2; rp[tid] = rp[tid + s];
                }
            }
            __syncthreads();
        }
        if (tid == 0) {
            outv[r] = rv[0]; outi[r] = ri[0];
            sv[rp[0]] = -INFINITY;
        }
        __syncthreads();
    }

    if (tid == 0) {
        float s = 0.f;
#pragma unroll
        for (int r = 0; r < KNN_; r++) s += outv[r];
        float inv = 1.f / fmaxf(s, 1.f);
#pragma unroll
        for (int r = 0; r < KNN_; r++) {
            g_nidx[row * KNN_ + r] = outi[r];
            g_nval[row * KNN_ + r] = outv[r] * inv;
        }
    }
}

// ---------------- sparse aggregation (+ bf16 split) ----------------
__global__ void agg_kernel()
{
    int row = blockIdx.x;
    int tid = threadIdx.x;                  // 256 == H_
    float acc = 0.f;
#pragma unroll
    for (int r = 0; r < KNN_; r++) {
        float w = g_nval[row * KNN_ + r];
        int   n = g_nidx[row * KNN_ + r];
        acc += w * g_h2[(size_t)n * H_ + tid];
    }
    g_agg[row * H_ + tid] = acc;
    bf16 hb = __float2bfloat16_rn(acc);
    g_ag_hi[row * H_ + tid] = hb;
    g_ag_lo[row * H_ + tid] = __float2bfloat16_rn(acc - __bfloat162float(hb));
}

// ---------------- weight transpose + split: W[K=256,N] -> [N,256] hi/lo ----------------
__global__ void wsplit_kernel(const float* __restrict__ W, int N, bf16* __restrict__ hi,
                              bf16* __restrict__ lo)
{
    int idx = blockIdx.x * 256 + threadIdx.x;      // over 256*N
    if (idx >= 256 * N) return;
    int k = idx / N, n = idx % N;
    float v = W[k * N + n];
    bf16 hb = __float2bfloat16_rn(v);
    hi[n * 256 + k] = hb;
    lo[n * 256 + k] = __float2bfloat16_rn(v - __bfloat162float(hb));
}

// ---------------- tiny precompute ----------------
__global__ void precompute_kernel(const float* __restrict__ bn_g, const float* __restrict__ bn_b,
                                  const float* __restrict__ bn_m, const float* __restrict__ bn_v,
                                  const float* __restrict__ t_w1, const float* __restrict__ t_b1,
                                  const float* __restrict__ t_w2, const float* __restrict__ t_b2,
                                  const float* __restrict__ gate_w, const float* __restrict__ gate_b,
                                  const float* __restrict__ sde_w1, const float* __restrict__ sde_b1)
{
    int b = blockIdx.x;
    int j = threadIdx.x;
    if (b == 0) {
        float s = bn_g[j] * rsqrtf(bn_v[j] + 1e-5f);
        g_bnscale[j] = s;
        g_bnshift[j] = bn_b[j] - bn_m[j] * s;
    } else if (b <= NL_) {
        int l = b - 1;
        float t = 0.5f * (float)l;
        __shared__ float te[TD_];
        __shared__ float te2[H_];
        if (j < TD_) te[j] = fmaxf(t * t_w1[l * TD_ + j] + t_b1[l * TD_ + j], 0.f);
        __syncthreads();
        float acc = t_b2[l * H_ + j];
#pragma unroll
        for (int k = 0; k < TD_; k++) acc += te[k] * t_w2[l * TD_ * H_ + k * H_ + j];
        te2[j] = acc;
        __syncthreads();
        float c = gate_b[l * H_ + j];
        const float* W = gate_w + (size_t)l * 2 * H_ * H_ + (size_t)H_ * H_;
        for (int k = 0; k < H_; k++) c += te2[k] * W[k * H_ + j];
        g_gatec[l * H_ + j] = c;
    } else {
        int s = b - 1 - NL_;
        float ts = (float)s * 0.1f;
        g_sdebias[s * H_ + j] = sde_b1[j] + ts * sde_w1[H_ * H_ + j];
    }
}

// ---------------- host ----------------
static inline void launch_mma(const bf16* Ahi, const bf16* Alo, const bf16* Bhi, const bf16* Blo,
                              float* C, int Ntot, int ep,
                              const float* p1 = nullptr, const float* p2 = nullptr,
                              const float* p3 = nullptr, float alpha = 0.f,
                              bf16* Chi = nullptr, bf16* Clo = nullptr)
{
    dim3 grid(Ntot / 128, NN_ / 128);
    mma_gemm<<<grid, 256>>>(Ahi, Alo, Bhi, Blo, C, Ntot, ep, p1, p2, p3, alpha, Chi, Clo);
}

extern "C" void kernel_launch(void* const* d_in, const int* in_sizes, int n_in,
                              void* d_out, int out_size)
{
    const float* x       = (const float*)d_in[0];
    const float* enc_w1  = (const float*)d_in[1];
    const float* enc_b1  = (const float*)d_in[2];
    const float* enc_w2  = (const float*)d_in[3];
    const float* enc_b2  = (const float*)d_in[4];
    const float* bn_g    = (const float*)d_in[5];
    const float* bn_b    = (const float*)d_in[6];
    const float* bn_m    = (const float*)d_in[7];
    const float* bn_v    = (const float*)d_in[8];
    const float* node_w  = (const float*)d_in[9];
    const float* node_b  = (const float*)d_in[10];
    const float* t_w1    = (const float*)d_in[11];
    const float* t_b1    = (const float*)d_in[12];
    const float* t_w2    = (const float*)d_in[13];
    const float* t_b2    = (const float*)d_in[14];
    const float* gate_w  = (const float*)d_in[15];
    const float* gate_b  = (const float*)d_in[16];
    const float* sde_w1  = (const float*)d_in[17];
    const float* sde_b1  = (const float*)d_in[18];
    const float* sde_w2  = (const float*)d_in[19];
    const float* sde_b2  = (const float*)d_in[20];
    const float* sde_w3  = (const float*)d_in[21];
    const float* sde_b3  = (const float*)d_in[22];
    const float* dec_w1  = (const float*)d_in[23];
    const float* dec_b1  = (const float*)d_in[24];
    const float* dec_w2  = (const float*)d_in[25];
    const float* dec_b2  = (const float*)d_in[26];
    float* out = (float*)d_out;

    float *sim, *h, *h2, *hn, *agg, *d1, *d2, *bns, *bnsh, *gatec, *sdeb;
    bf16 *hhi, *hlo, *h2hi, *h2lo, *hnhi, *hnlo, *aghi, *aglo, *d1hi, *d1lo, *d2hi, *d2lo, *whi, *wlo;
    cudaGetSymbolAddress((void**)&sim,   g_sim);
    cudaGetSymbolAddress((void**)&h,     g_h);
    cudaGetSymbolAddress((void**)&h2,    g_h2);
    cudaGetSymbolAddress((void**)&hn,    g_hn);
    cudaGetSymbolAddress((void**)&agg,   g_agg);
    cudaGetSymbolAddress((void**)&d1,    g_d1);
    cudaGetSymbolAddress((void**)&d2,    g_d2);
    cudaGetSymbolAddress((void**)&bns,   g_bnscale);
    cudaGetSymbolAddress((void**)&bnsh,  g_bnshift);
    cudaGetSymbolAddress((void**)&gatec, g_gatec);
    cudaGetSymbolAddress((void**)&sdeb,  g_sdebias);
    cudaGetSymbolAddress((void**)&hhi,  g_h_hi);  cudaGetSymbolAddress((void**)&hlo,  g_h_lo);
    cudaGetSymbolAddress((void**)&h2hi, g_h2_hi); cudaGetSymbolAddress((void**)&h2lo, g_h2_lo);
    cudaGetSymbolAddress((void**)&hnhi, g_hn_hi); cudaGetSymbolAddress((void**)&hnlo, g_hn_lo);
    cudaGetSymbolAddress((void**)&aghi, g_ag_hi); cudaGetSymbolAddress((void**)&aglo, g_ag_lo);
    cudaGetSymbolAddress((void**)&d1hi, g_d1_hi); cudaGetSymbolAddress((void**)&d1lo, g_d1_lo);
    cudaGetSymbolAddress((void**)&d2hi, g_d2_hi); cudaGetSymbolAddress((void**)&d2lo, g_d2_lo);
    cudaGetSymbolAddress((void**)&whi, g_w_hi);   cudaGetSymbolAddress((void**)&wlo, g_w_lo);

    precompute_kernel<<<1 + NL_ + NSTEPS_, 256>>>(bn_g, bn_b, bn_m, bn_v,
                                                  t_w1, t_b1, t_w2, t_b2,
                                                  gate_w, gate_b, sde_w1, sde_b1);

    // weight transpose + split (slot: 0 enc2, 1/2 node, 3/4 gate-top, 5/6/7 sde, 8 dec1)
    wsplit_kernel<<<256, 256>>>(enc_w2, 256, whi + 0 * WSLOT, wlo + 0 * WSLOT);
    wsplit_kernel<<<256, 256>>>(node_w,             256, whi + 1 * WSLOT, wlo + 1 * WSLOT);
    wsplit_kernel<<<256, 256>>>(node_w + H_ * H_,   256, whi + 2 * WSLOT, wlo + 2 * WSLOT);
    wsplit_kernel<<<256, 256>>>(gate_w,                     256, whi + 3 * WSLOT, wlo + 3 * WSLOT);
    wsplit_kernel<<<256, 256>>>(gate_w + 2 * H_ * H_,       256, whi + 4 * WSLOT, wlo + 4 * WSLOT);
    wsplit_kernel<<<256, 256>>>(sde_w1, 256, whi + 5 * WSLOT, wlo + 5 * WSLOT);
    wsplit_kernel<<<256, 256>>>(sde_w2, 256, whi + 6 * WSLOT, wlo + 6 * WSLOT);
    wsplit_kernel<<<256, 256>>>(sde_w3, 256, whi + 7 * WSLOT, wlo + 7 * WSLOT);
    wsplit_kernel<<<128, 256>>>(dec_w1, 128, whi + 8 * WSLOT, wlo + 8 * WSLOT);

    // encoder: enc1 SIMT (K=83) with split output; enc2 on tensor cores
    {
        dim3 grid((H_ + BN - 1) / BN, (NN_ + BM - 1) / BM);
        gemm_kernel<<<grid, 256>>>(x, enc_w1, h2, NN_, H_, DIN_, H_, 1, enc_b1, h2hi, h2lo);
    }
    launch_mma(h2hi, h2lo, whi + 0 * WSLOT, wlo + 0 * WSLOT, h, 256, /*ep=*/2,
               enc_b2, bns, bnsh, 0.f, hhi, hlo);

    // kNN graph
    rownorm_kernel<<<NN_, 256>>>();
    launch_mma(hnhi, hnlo, hnhi, hnlo, sim, NN_, /*ep=*/0);
    topk_kernel<<<NN_, 256>>>();

    // temporal gated graph conv layers
    for (int l = 0; l < NL_; l++) {
        launch_mma(hhi, hlo, whi + (1 + l) * WSLOT, wlo + (1 + l) * WSLOT, h2, 256, /*ep=*/3,
                   node_b + (size_t)l * H_);
        agg_kernel<<<NN_, 256>>>();
        launch_mma(aghi, aglo, whi + (3 + l) * WSLOT, wlo + (3 + l) * WSLOT, h, 256, /*ep=*/4,
                   gatec + (size_t)l * H_, agg, h2, 0.f, hhi, hlo);
    }

    // SDE (drift-only Euler, 10 steps)
    const float dt = 0.1f;
    for (int s = 0; s < NSTEPS_; s++) {
        launch_mma(hhi, hlo, whi + 5 * WSLOT, wlo + 5 * WSLOT, d1, 256, /*ep=*/5,
                   sdeb + (size_t)s * H_, nullptr, nullptr, 0.f, d1hi, d1lo);
        launch_mma(d1hi, d1lo, whi + 6 * WSLOT, wlo + 6 * WSLOT, d2, 256, /*ep=*/5,
                   sde_b2, nullptr, nullptr, 0.f, d2hi, d2lo);
        launch_mma(d2hi, d2lo, whi + 7 * WSLOT, wlo + 7 * WSLOT, h, 256, /*ep=*/6,
                   sde_b3, h, nullptr, dt, hhi, hlo);
    }

    // decoder: dec1 tensor (N=128), dec2 SIMT (K=128, N=34)
    launch_mma(hhi, hlo, whi + 8 * WSLOT, wlo + 8 * WSLOT, d1, 128, /*ep=*/1, dec_b1);
    {
        dim3 grid((C_ + BN - 1) / BN, (NN_ + BM - 1) / BM);
        gemm_kernel<<<grid, 256>>>(d1, dec_w2, out, NN_, C_, H_ / 2, C_, 3, dec_b2, nullptr, nullptr);
    }
}

// round 5
// speedup vs baseline: 1.9504x; 1.0651x over previous
#include <cuda_runtime.h>
#include <cuda_bf16.h>
#include <math.h>
#include <stdint.h>

// ---------------- problem constants ----------------
#define NN_   8192
#define DIN_  83
#define H_    256
#define C_    34
#define TD_   16
#define NL_   2
#define KNN_  11
#define NSTEPS_ 10

typedef __nv_bfloat16 bf16;

// ---------------- scratch (device globals; no allocation allowed) ----------------
__device__ float g_sim[(size_t)NN_ * NN_];          // 256 MB
__device__ float g_h  [NN_ * H_];
__device__ float g_h2 [NN_ * H_];
__device__ float g_hn [NN_ * H_];
__device__ float g_agg[NN_ * H_];
__device__ float g_d1 [NN_ * H_];
__device__ float g_d2 [NN_ * H_];
__device__ int   g_nidx[NN_ * KNN_];
__device__ float g_nval[NN_ * KNN_];
__device__ float g_bnscale[H_];
__device__ float g_bnshift[H_];
__device__ float g_gatec[NL_ * H_];
__device__ float g_sdebias[NSTEPS_ * H_];

// bf16 split copies of activations ([M,256] row-major hi/lo)
__device__ bf16 g_h_hi [NN_ * H_],  g_h_lo [NN_ * H_];
__device__ bf16 g_h2_hi[NN_ * H_],  g_h2_lo[NN_ * H_];
__device__ bf16 g_hn_hi[NN_ * H_],  g_hn_lo[NN_ * H_];
__device__ bf16 g_ag_hi[NN_ * H_],  g_ag_lo[NN_ * H_];
__device__ bf16 g_d1_hi[NN_ * H_],  g_d1_lo[NN_ * H_];
__device__ bf16 g_d2_hi[NN_ * H_],  g_d2_lo[NN_ * H_];

// transposed+split weights, [N,256] K-major; 9 slots of 64K elems
#define WSLOT 65536
__device__ bf16 g_w_hi[9 * WSLOT];
__device__ bf16 g_w_lo[9 * WSLOT];

// ================= helpers =================
__device__ __forceinline__ uint32_t smem_u32(const void* p) {
    uint32_t a;
    asm("{ .reg .u64 t; cvta.to.shared.u64 t, %1; cvt.u32.u64 %0, t; }" : "=r"(a) : "l"(p));
    return a;
}
__device__ __forceinline__ void ldsm4(uint32_t* r, uint32_t addr) {
    asm volatile("ldmatrix.sync.aligned.m8n8.x4.shared.b16 {%0,%1,%2,%3}, [%4];"
                 : "=r"(r[0]), "=r"(r[1]), "=r"(r[2]), "=r"(r[3]) : "r"(addr));
}
__device__ __forceinline__ void mma16816(float* d, const uint32_t* a, uint32_t b0, uint32_t b1) {
    asm volatile("mma.sync.aligned.m16n8k16.row.col.f32.bf16.bf16.f32 "
                 "{%0,%1,%2,%3}, {%4,%5,%6,%7}, {%8,%9}, {%0,%1,%2,%3};"
                 : "+f"(d[0]), "+f"(d[1]), "+f"(d[2]), "+f"(d[3])
                 : "r"(a[0]), "r"(a[1]), "r"(a[2]), "r"(a[3]), "r"(b0), "r"(b1));
}

// ================= tensor-core split-bf16 GEMM (mma.sync, cp.async pipelined) =================
// C[M=8192, Ntot] = (Ahi+Alo) @ (Bhi+Blo)^T
//   A: [M,256] K-major bf16 hi/lo; B: [Ntot,256] K-major bf16 hi/lo
// nterms=3: AhBh+AhBl+AlBh; nterms=4 adds AlBl (sim precision).
// CTA tile 128x128, K chunked 8 x 32; 8 warps, each warp 32(m) x 64(n).
// mirror=1: symmetric output (A==B): only blocks bn0<=bm0 run; off-diagonal
// blocks also write the transposed tile via smem staging.
// Epilogues: 0 y=z; 1 relu(z+p1); 2 relu(z+p1)*p2+p3; 3 z+p1;
//            4 gate; 5 tanh(z+p1); 6 p2[i,n]+tanh(z+p1)*alpha.

#define TILE_B   8192                    // 128 rows * 32 bf16 * 2B
#define BUF_B    (4 * TILE_B)            // Ah,Al,Bh,Bl
#define MG_SMEM  (2 * BUF_B)             // 64 KB double buffered

__device__ __forceinline__ void cpa_tile(const bf16* __restrict__ src, int r0, int k0,
                                         char* __restrict__ dst, int tid)
{
#pragma unroll
    for (int u = 0; u < 2; u++) {
        int i = tid + u * 256;                  // 0..511 16B segments
        int row = i >> 2;                       // 0..127
        int seg = i & 3;                        // 0..3
        const void* gp = src + (size_t)(r0 + row) * 256 + k0 + seg * 8;
        uint32_t off = (uint32_t)row * 64u + (uint32_t)((seg ^ ((row >> 1) & 3)) << 4);
        uint32_t sa = smem_u32(dst + off);
        asm volatile("cp.async.cg.shared.global [%0], [%1], 16;" :: "r"(sa), "l"(gp));
    }
}

__global__ __launch_bounds__(256) void mma_gemm(
    const bf16* __restrict__ Ahi, const bf16* __restrict__ Alo,
    const bf16* __restrict__ Bhi, const bf16* __restrict__ Blo,
    float* __restrict__ C, int Ntot, int ep, int nterms, int mirror,
    const float* __restrict__ p1, const float* __restrict__ p2,
    const float* __restrict__ p3, float alpha,
    bf16* __restrict__ Chi, bf16* __restrict__ Clo)
{
    const int bn0 = blockIdx.x * 128;
    const int bm0 = blockIdx.y * 128;
    if (mirror && bn0 > bm0) return;            // symmetric: lower triangle only

    extern __shared__ char smem[];
    char* bufp[2] = {smem, smem + BUF_B};

    const int tid  = threadIdx.x;
    const int wid  = tid >> 5;
    const int lane = tid & 31;
    const int warp_m = wid & 3;
    const int warp_n = wid >> 2;

    float acc[2][8][4];
#pragma unroll
    for (int i = 0; i < 2; i++)
#pragma unroll
        for (int j = 0; j < 8; j++)
#pragma unroll
            for (int q = 0; q < 4; q++) acc[i][j][q] = 0.f;

    const int lrow  = lane & 15;
    const int lhalf = lane >> 4;

    // prologue: chunk 0 into buf 0
    {
        cpa_tile(Ahi, bm0, 0, bufp[0] + 0 * TILE_B, tid);
        cpa_tile(Alo, bm0, 0, bufp[0] + 1 * TILE_B, tid);
        cpa_tile(Bhi, bn0, 0, bufp[0] + 2 * TILE_B, tid);
        cpa_tile(Blo, bn0, 0, bufp[0] + 3 * TILE_B, tid);
        asm volatile("cp.async.commit_group;" ::: "memory");
    }

    int buf = 0;
    for (int chunk = 0; chunk < 8; chunk++) {
        if (chunk + 1 < 8) {
            const int k1 = (chunk + 1) * 32;
            char* nb = bufp[buf ^ 1];
            cpa_tile(Ahi, bm0, k1, nb + 0 * TILE_B, tid);
            cpa_tile(Alo, bm0, k1, nb + 1 * TILE_B, tid);
            cpa_tile(Bhi, bn0, k1, nb + 2 * TILE_B, tid);
            cpa_tile(Blo, bn0, k1, nb + 3 * TILE_B, tid);
            asm volatile("cp.async.commit_group;" ::: "memory");
            asm volatile("cp.async.wait_group 1;" ::: "memory");
        } else {
            asm volatile("cp.async.wait_group 0;" ::: "memory");
        }
        __syncthreads();

        const uint32_t sAh_b = smem_u32(bufp[buf] + 0 * TILE_B);
        const uint32_t sAl_b = smem_u32(bufp[buf] + 1 * TILE_B);
        const uint32_t sBh_b = smem_u32(bufp[buf] + 2 * TILE_B);
        const uint32_t sBl_b = smem_u32(bufp[buf] + 3 * TILE_B);

#pragma unroll
        for (int kk = 0; kk < 2; kk++) {
            const int segq = kk * 2 + lhalf;

            uint32_t aH[2][4], aL[2][4];
#pragma unroll
            for (int mt = 0; mt < 2; mt++) {
                int row = warp_m * 32 + mt * 16 + lrow;
                uint32_t off = (uint32_t)row * 64u + (uint32_t)((segq ^ ((row >> 1) & 3)) << 4);
                ldsm4(aH[mt], sAh_b + off);
                ldsm4(aL[mt], sAl_b + off);
            }

#pragma unroll
            for (int g = 0; g < 4; g++) {
                int row = warp_n * 64 + g * 16 + lrow;
                uint32_t off = (uint32_t)row * 64u + (uint32_t)((segq ^ ((row >> 1) & 3)) << 4);
                uint32_t bH[4], bL[4];
                ldsm4(bH, sBh_b + off);
                ldsm4(bL, sBl_b + off);
#pragma unroll
                for (int mt = 0; mt < 2; mt++) {
                    mma16816(acc[mt][2 * g + 0], aH[mt], bH[0], bH[2]);
                    mma16816(acc[mt][2 * g + 1], aH[mt], bH[1], bH[3]);
                    mma16816(acc[mt][2 * g + 0], aH[mt], bL[0], bL[2]);
                    mma16816(acc[mt][2 * g + 1], aH[mt], bL[1], bL[3]);
                    mma16816(acc[mt][2 * g + 0], aL[mt], bH[0], bH[2]);
                    mma16816(acc[mt][2 * g + 1], aL[mt], bH[1], bH[3]);
                    if (nterms == 4) {
                        mma16816(acc[mt][2 * g + 0], aL[mt], bL[0], bL[2]);
                        mma16816(acc[mt][2 * g + 1], aL[mt], bL[1], bL[3]);
                    }
                }
            }
        }
        __syncthreads();
        buf ^= 1;
    }

    // ---- epilogue ----
    auto epi = [&](float z, int gr, int gc) -> float {
        if (ep == 0) return z;
        if (ep == 1) return fmaxf(z + p1[gc], 0.f);
        if (ep == 2) return fmaxf(z + p1[gc], 0.f) * p2[gc] + p3[gc];
        if (ep == 3) return z + p1[gc];
        if (ep == 4) {
            float g = 1.f / (1.f + expf(-(z + p1[gc])));
            float a = p2[(size_t)gr * Ntot + gc];
            float hh = p3[(size_t)gr * Ntot + gc];
            return fmaxf(g * a + (1.f - g) * hh, 0.f);
        }
        if (ep == 5) return tanhf(z + p1[gc]);
        return p2[(size_t)gr * Ntot + gc] + tanhf(z + p1[gc]) * alpha;  // 6
    };

#pragma unroll
    for (int mt = 0; mt < 2; mt++) {
#pragma unroll
        for (int half = 0; half < 2; half++) {
            int gr = bm0 + warp_m * 32 + mt * 16 + (lane >> 2) + half * 8;
#pragma unroll
            for (int nt = 0; nt < 8; nt++) {
                int gc = bn0 + warp_n * 64 + nt * 8 + (lane & 3) * 2;
                float y0 = epi(acc[mt][nt][half * 2 + 0], gr, gc);
                float y1 = epi(acc[mt][nt][half * 2 + 1], gr, gc + 1);
                float2 o; o.x = y0; o.y = y1;
                *(float2*)(C + (size_t)gr * Ntot + gc) = o;
                if (Chi) {
                    bf16 h0 = __float2bfloat16_rn(y0);
                    bf16 h1 = __float2bfloat16_rn(y1);
                    __nv_bfloat162 hp; hp.x = h0; hp.y = h1;
                    __nv_bfloat162 lp;
                    lp.x = __float2bfloat16_rn(y0 - __bfloat162float(h0));
                    lp.y = __float2bfloat16_rn(y1 - __bfloat162float(h1));
                    *(__nv_bfloat162*)(Chi + (size_t)gr * 256 + gc) = hp;
                    *(__nv_bfloat162*)(Clo + (size_t)gr * 256 + gc) = lp;
                }
            }
        }
    }

    // ---- mirror write (symmetric sim): C[bn0+j, bm0+i] = acc[i][j], smem-staged ----
    if (mirror && bm0 != bn0) {
        float* ts = (float*)smem;     // 64 x (128+4) floats = 33.8 KB, fits 64 KB
#pragma unroll 1
        for (int p = 0; p < 2; p++) {
            __syncthreads();
            if (warp_n == p) {
#pragma unroll
                for (int mt = 0; mt < 2; mt++)
#pragma unroll
                    for (int half = 0; half < 2; half++) {
                        int grl = warp_m * 32 + mt * 16 + (lane >> 2) + half * 8;
#pragma unroll
                        for (int nt = 0; nt < 8; nt++) {
                            int gcl = nt * 8 + (lane & 3) * 2;     // 0..63 within half
                            ts[(gcl + 0) * 132 + grl] = acc[mt][nt][half * 2 + 0];
                            ts[(gcl + 1) * 132 + grl] = acc[mt][nt][half * 2 + 1];
                        }
                    }
            }
            __syncthreads();
            // write 64 rows x 128 cols, coalesced float4
#pragma unroll
            for (int u = 0; u < 8; u++) {
                int i = tid + u * 256;           // 0..2047 float4 segments
                int j = i >> 5;                  // row 0..63
                int q = i & 31;                  // float4 col 0..31
                float4 v;
                v.x = ts[j * 132 + q * 4 + 0];
                v.y = ts[j * 132 + q * 4 + 1];
                v.z = ts[j * 132 + q * 4 + 2];
                v.w = ts[j * 132 + q * 4 + 3];
                *(float4*)(C + (size_t)(bn0 + p * 64 + j) * Ntot + bm0 + q * 4) = v;
            }
        }
    }
}

// ================= SIMT fp32 GEMM (odd shapes: enc1 K=83, dec2 N=34) =================
#define BM 128
#define BN 128
#define BK 8

__global__ __launch_bounds__(256) void gemm_kernel(
    const float* __restrict__ A, const float* __restrict__ B, float* __restrict__ C,
    int M, int N, int K, int ldb, int ep,
    const float* __restrict__ p1, bf16* __restrict__ Chi, bf16* __restrict__ Clo)
{
    __shared__ float As[2][BK][BM + 4];
    __shared__ float Bs[2][BK][BN + 4];

    const int tid = threadIdx.x;
    const int tx  = tid & 15;
    const int ty  = tid >> 4;
    const int bn0 = blockIdx.x * BN;
    const int bm0 = blockIdx.y * BM;

    float acc[8][8];
#pragma unroll
    for (int i = 0; i < 8; i++)
#pragma unroll
        for (int j = 0; j < 8; j++) acc[i][j] = 0.f;

    const int aRow = tid >> 1;
    const int aK   = (tid & 1) * 4;
    const int bRow = tid >> 5;
    const int bN   = (tid & 31) * 4;

    float ra[4], rb[4];
    const int ktiles = (K + BK - 1) / BK;

#define LOAD_AB(kt) do {                                                       \
        int k0_ = (kt) * BK;                                                   \
        int gr_ = bm0 + aRow, gk_ = k0_ + aK;                                  \
        _Pragma("unroll")                                                      \
        for (int j_ = 0; j_ < 4; j_++)                                         \
            ra[j_] = (gr_ < M && gk_ + j_ < K) ? A[(size_t)gr_ * K + gk_ + j_] : 0.f; \
        int gk2_ = k0_ + bRow, gn_ = bn0 + bN;                                 \
        _Pragma("unroll")                                                      \
        for (int j_ = 0; j_ < 4; j_++)                                         \
            rb[j_] = (gk2_ < K && gn_ + j_ < N) ? B[(size_t)gk2_ * ldb + gn_ + j_] : 0.f; \
    } while (0)

#define STS_AB2(buf) do {                                                      \
        _Pragma("unroll")                                                      \
        for (int j_ = 0; j_ < 4; j_++) As[buf][aK + j_][aRow] = ra[j_];        \
        _Pragma("unroll")                                                      \
        for (int j_ = 0; j_ < 4; j_++) Bs[buf][bRow][bN + j_] = rb[j_];        \
    } while (0)

    LOAD_AB(0);
    STS_AB2(0);
    __syncthreads();

    int cur = 0;
    for (int kt = 0; kt < ktiles; kt++) {
        const int hasNext = (kt + 1 < ktiles);
        if (hasNext) LOAD_AB(kt + 1);
#pragma unroll
        for (int kk = 0; kk < BK; kk++) {
            const float* as = As[cur][kk];
            const float* bs = Bs[cur][kk];
            float4 A0 = *(const float4*)(as + ty * 4);
            float4 A1 = *(const float4*)(as + 64 + ty * 4);
            float4 B0 = *(const float4*)(bs + tx * 4);
            float4 B1 = *(const float4*)(bs + 64 + tx * 4);
            float av[8] = {A0.x, A0.y, A0.z, A0.w, A1.x, A1.y, A1.z, A1.w};
            float bv[8] = {B0.x, B0.y, B0.z, B0.w, B1.x, B1.y, B1.z, B1.w};
#pragma unroll
            for (int i = 0; i < 8; i++)
#pragma unroll
                for (int j = 0; j < 8; j++)
                    acc[i][j] = fmaf(av[i], bv[j], acc[i][j]);
        }
        if (hasNext) { STS_AB2(cur ^ 1); __syncthreads(); cur ^= 1; }
    }

#pragma unroll
    for (int i = 0; i < 8; i++) {
        int gr = bm0 + ((i < 4) ? (ty * 4 + i) : (64 + ty * 4 + (i - 4)));
        if (gr >= M) continue;
#pragma unroll
        for (int j = 0; j < 8; j++) {
            int gc = bn0 + ((j < 4) ? (tx * 4 + j) : (64 + tx * 4 + (j - 4)));
            if (gc >= N) continue;
            float z = acc[i][j];
            float y;
            if (ep == 1) y = fmaxf(z + p1[gc], 0.f);
            else if (ep == 3) y = z + p1[gc];
            else y = z;
            C[(size_t)gr * N + gc] = y;
            if (Chi) {
                bf16 hb = __float2bfloat16_rn(y);
                Chi[(size_t)gr * 256 + gc] = hb;
                Clo[(size_t)gr * 256 + gc] = __float2bfloat16_rn(y - __bfloat162float(hb));
            }
        }
    }
}

// ---------------- row-normalize h -> hn (+ bf16 split) ----------------
__global__ void rownorm_kernel()
{
    int row = blockIdx.x;
    int tid = threadIdx.x;                   // 256 == H_
    float v = g_h[row * H_ + tid];
    float s = v * v;
#pragma unroll
    for (int o = 16; o > 0; o >>= 1) s += __shfl_xor_sync(0xffffffff, s, o);
    __shared__ float ws[8];
    if ((tid & 31) == 0) ws[tid >> 5] = s;
    __syncthreads();
    if (tid < 8) {
        float t = ws[tid];
#pragma unroll
        for (int o = 4; o > 0; o >>= 1) t += __shfl_xor_sync(0xff, t, o);
        if (tid == 0) ws[0] = t;
    }
    __syncthreads();
    float denom = fmaxf(sqrtf(ws[0]), 1e-12f);
    float y = v / denom;
    g_hn[row * H_ + tid] = y;
    bf16 hb = __float2bfloat16_rn(y);
    g_hn_hi[row * H_ + tid] = hb;
    g_hn_lo[row * H_ + tid] = __float2bfloat16_rn(y - __bfloat162float(hb));
}

// ---------------- per-row top-k over sim + adjacency normalize ----------------
__global__ void topk_kernel()
{
    const int row = blockIdx.x;
    const int tid = threadIdx.x;
    const float* srow = g_sim + (size_t)row * NN_;

    float lv[KNN_];
    int   li[KNN_];
#pragma unroll
    for (int r = 0; r < KNN_; r++) { lv[r] = -INFINITY; li[r] = 0x7fffffff; }

    for (int j = tid; j < NN_; j += 256) {
        float v = srow[j];
        if (v > lv[KNN_ - 1]) {
            int p = KNN_ - 1;
            while (p > 0 && v > lv[p - 1]) { lv[p] = lv[p - 1]; li[p] = li[p - 1]; p--; }
            lv[p] = v; li[p] = j;
        }
    }

    __shared__ float sv[256 * KNN_];
    __shared__ int   si[256 * KNN_];
#pragma unroll
    for (int r = 0; r < KNN_; r++) { sv[tid * KNN_ + r] = lv[r]; si[tid * KNN_ + r] = li[r]; }
    __syncthreads();

    __shared__ float rv[256];
    __shared__ int   ri[256];
    __shared__ int   rp[256];
    __shared__ float outv[KNN_];
    __shared__ int   outi[KNN_];

    const int TOT = 256 * KNN_;
    for (int r = 0; r < KNN_; r++) {
        float bv = -INFINITY; int bi = 0x7fffffff; int bp = -1;
        for (int t = tid; t < TOT; t += 256) {
            float v = sv[t]; int ii = si[t];
            if (v > bv || (v == bv && ii < bi)) { bv = v; bi = ii; bp = t; }
        }
        rv[tid] = bv; ri[tid] = bi; rp[tid] = bp;
        __syncthreads();
        for (int s = 128; s > 0; s >>= 1) {
            if (tid < s) {
                float v2 = rv[tid + s]; int i2 = ri[tid + s];
                if (v2 > rv[tid] || (v2 == rv[tid] && i2 < ri[tid])) {
                    rv[tid] = v2; ri[tid] = i2; rp[tid] = rp[tid + s];
                }
            }
            __syncthreads();
        }
        if (tid == 0) {
            outv[r] = rv[0]; outi[r] = ri[0];
            sv[rp[0]] = -INFINITY;
        }
        __syncthreads();
    }

    if (tid == 0) {
        float s = 0.f;
#pragma unroll
        for (int r = 0; r < KNN_; r++) s += outv[r];
        float inv = 1.f / fmaxf(s, 1.f);
#pragma unroll
        for (int r = 0; r < KNN_; r++) {
            g_nidx[row * KNN_ + r] = outi[r];
            g_nval[row * KNN_ + r] = outv[r] * inv;
        }
    }
}

// ---------------- sparse aggregation (+ bf16 split) ----------------
__global__ void agg_kernel()
{
    int row = blockIdx.x;
    int tid = threadIdx.x;                  // 256 == H_
    float acc = 0.f;
#pragma unroll
    for (int r = 0; r < KNN_; r++) {
        float w = g_nval[row * KNN_ + r];
        int   n = g_nidx[row * KNN_ + r];
        acc += w * g_h2[(size_t)n * H_ + tid];
    }
    g_agg[row * H_ + tid] = acc;
    bf16 hb = __float2bfloat16_rn(acc);
    g_ag_hi[row * H_ + tid] = hb;
    g_ag_lo[row * H_ + tid] = __float2bfloat16_rn(acc - __bfloat162float(hb));
}

// ---------------- weight transpose + split: W[K=256,N] -> [N,256] hi/lo ----------------
__global__ void wsplit_kernel(const float* __restrict__ W, int N, bf16* __restrict__ hi,
                              bf16* __restrict__ lo)
{
    int idx = blockIdx.x * 256 + threadIdx.x;      // over 256*N
    if (idx >= 256 * N) return;
    int k = idx / N, n = idx % N;
    float v = W[k * N + n];
    bf16 hb = __float2bfloat16_rn(v);
    hi[n * 256 + k] = hb;
    lo[n * 256 + k] = __float2bfloat16_rn(v - __bfloat162float(hb));
}

// ---------------- tiny precompute ----------------
__global__ void precompute_kernel(const float* __restrict__ bn_g, const float* __restrict__ bn_b,
                                  const float* __restrict__ bn_m, const float* __restrict__ bn_v,
                                  const float* __restrict__ t_w1, const float* __restrict__ t_b1,
                                  const float* __restrict__ t_w2, const float* __restrict__ t_b2,
                                  const float* __restrict__ gate_w, const float* __restrict__ gate_b,
                                  const float* __restrict__ sde_w1, const float* __restrict__ sde_b1)
{
    int b = blockIdx.x;
    int j = threadIdx.x;
    if (b == 0) {
        float s = bn_g[j] * rsqrtf(bn_v[j] + 1e-5f);
        g_bnscale[j] = s;
        g_bnshift[j] = bn_b[j] - bn_m[j] * s;
    } else if (b <= NL_) {
        int l = b - 1;
        float t = 0.5f * (float)l;
        __shared__ float te[TD_];
        __shared__ float te2[H_];
        if (j < TD_) te[j] = fmaxf(t * t_w1[l * TD_ + j] + t_b1[l * TD_ + j], 0.f);
        __syncthreads();
        float acc = t_b2[l * H_ + j];
#pragma unroll
        for (int k = 0; k < TD_; k++) acc += te[k] * t_w2[l * TD_ * H_ + k * H_ + j];
        te2[j] = acc;
        __syncthreads();
        float c = gate_b[l * H_ + j];
        const float* W = gate_w + (size_t)l * 2 * H_ * H_ + (size_t)H_ * H_;
        for (int k = 0; k < H_; k++) c += te2[k] * W[k * H_ + j];
        g_gatec[l * H_ + j] = c;
    } else {
        int s = b - 1 - NL_;
        float ts = (float)s * 0.1f;
        g_sdebias[s * H_ + j] = sde_b1[j] + ts * sde_w1[H_ * H_ + j];
    }
}

// ---------------- host ----------------
static inline void launch_mma(const bf16* Ahi, const bf16* Alo, const bf16* Bhi, const bf16* Blo,
                              float* C, int Ntot, int ep, int nterms, int mirror,
                              const float* p1 = nullptr, const float* p2 = nullptr,
                              const float* p3 = nullptr, float alpha = 0.f,
                              bf16* Chi = nullptr, bf16* Clo = nullptr)
{
    dim3 grid(Ntot / 128, NN_ / 128);
    mma_gemm<<<grid, 256, MG_SMEM>>>(Ahi, Alo, Bhi, Blo, C, Ntot, ep, nterms, mirror,
                                     p1, p2, p3, alpha, Chi, Clo);
}

extern "C" void kernel_launch(void* const* d_in, const int* in_sizes, int n_in,
                              void* d_out, int out_size)
{
    const float* x       = (const float*)d_in[0];
    const float* enc_w1  = (const float*)d_in[1];
    const float* enc_b1  = (const float*)d_in[2];
    const float* enc_w2  = (const float*)d_in[3];
    const float* enc_b2  = (const float*)d_in[4];
    const float* bn_g    = (const float*)d_in[5];
    const float* bn_b    = (const float*)d_in[6];
    const float* bn_m    = (const float*)d_in[7];
    const float* bn_v    = (const float*)d_in[8];
    const float* node_w  = (const float*)d_in[9];
    const float* node_b  = (const float*)d_in[10];
    const float* t_w1    = (const float*)d_in[11];
    const float* t_b1    = (const float*)d_in[12];
    const float* t_w2    = (const float*)d_in[13];
    const float* t_b2    = (const float*)d_in[14];
    const float* gate_w  = (const float*)d_in[15];
    const float* gate_b  = (const float*)d_in[16];
    const float* sde_w1  = (const float*)d_in[17];
    const float* sde_b1  = (const float*)d_in[18];
    const float* sde_w2  = (const float*)d_in[19];
    const float* sde_b2  = (const float*)d_in[20];
    const float* sde_w3  = (const float*)d_in[21];
    const float* sde_b3  = (const float*)d_in[22];
    const float* dec_w1  = (const float*)d_in[23];
    const float* dec_b1  = (const float*)d_in[24];
    const float* dec_w2  = (const float*)d_in[25];
    const float* dec_b2  = (const float*)d_in[26];
    float* out = (float*)d_out;

    cudaFuncSetAttribute(mma_gemm, cudaFuncAttributeMaxDynamicSharedMemorySize, MG_SMEM);

    float *sim, *h, *h2, *hn, *agg, *d1, *d2, *bns, *bnsh, *gatec, *sdeb;
    bf16 *hhi, *hlo, *h2hi, *h2lo, *hnhi, *hnlo, *aghi, *aglo, *d1hi, *d1lo, *d2hi, *d2lo, *whi, *wlo;
    cudaGetSymbolAddress((void**)&sim,   g_sim);
    cudaGetSymbolAddress((void**)&h,     g_h);
    cudaGetSymbolAddress((void**)&h2,    g_h2);
    cudaGetSymbolAddress((void**)&hn,    g_hn);
    cudaGetSymbolAddress((void**)&agg,   g_agg);
    cudaGetSymbolAddress((void**)&d1,    g_d1);
    cudaGetSymbolAddress((void**)&d2,    g_d2);
    cudaGetSymbolAddress((void**)&bns,   g_bnscale);
    cudaGetSymbolAddress((void**)&bnsh,  g_bnshift);
    cudaGetSymbolAddress((void**)&gatec, g_gatec);
    cudaGetSymbolAddress((void**)&sdeb,  g_sdebias);
    cudaGetSymbolAddress((void**)&hhi,  g_h_hi);  cudaGetSymbolAddress((void**)&hlo,  g_h_lo);
    cudaGetSymbolAddress((void**)&h2hi, g_h2_hi); cudaGetSymbolAddress((void**)&h2lo, g_h2_lo);
    cudaGetSymbolAddress((void**)&hnhi, g_hn_hi); cudaGetSymbolAddress((void**)&hnlo, g_hn_lo);
    cudaGetSymbolAddress((void**)&aghi, g_ag_hi); cudaGetSymbolAddress((void**)&aglo, g_ag_lo);
    cudaGetSymbolAddress((void**)&d1hi, g_d1_hi); cudaGetSymbolAddress((void**)&d1lo, g_d1_lo);
    cudaGetSymbolAddress((void**)&d2hi, g_d2_hi); cudaGetSymbolAddress((void**)&d2lo, g_d2_lo);
    cudaGetSymbolAddress((void**)&whi, g_w_hi);   cudaGetSymbolAddress((void**)&wlo, g_w_lo);

    precompute_kernel<<<1 + NL_ + NSTEPS_, 256>>>(bn_g, bn_b, bn_m, bn_v,
                                                  t_w1, t_b1, t_w2, t_b2,
                                                  gate_w, gate_b, sde_w1, sde_b1);

    // weight transpose + split (slot: 0 enc2, 1/2 node, 3/4 gate-top, 5/6/7 sde, 8 dec1)
    wsplit_kernel<<<256, 256>>>(enc_w2, 256, whi + 0 * WSLOT, wlo + 0 * WSLOT);
    wsplit_kernel<<<256, 256>>>(node_w,             256, whi + 1 * WSLOT, wlo + 1 * WSLOT);
    wsplit_kernel<<<256, 256>>>(node_w + H_ * H_,   256, whi + 2 * WSLOT, wlo + 2 * WSLOT);
    wsplit_kernel<<<256, 256>>>(gate_w,                     256, whi + 3 * WSLOT, wlo + 3 * WSLOT);
    wsplit_kernel<<<256, 256>>>(gate_w + 2 * H_ * H_,       256, whi + 4 * WSLOT, wlo + 4 * WSLOT);
    wsplit_kernel<<<256, 256>>>(sde_w1, 256, whi + 5 * WSLOT, wlo + 5 * WSLOT);
    wsplit_kernel<<<256, 256>>>(sde_w2, 256, whi + 6 * WSLOT, wlo + 6 * WSLOT);
    wsplit_kernel<<<256, 256>>>(sde_w3, 256, whi + 7 * WSLOT, wlo + 7 * WSLOT);
    wsplit_kernel<<<128, 256>>>(dec_w1, 128, whi + 8 * WSLOT, wlo + 8 * WSLOT);

    // encoder: enc1 SIMT (K=83) with split output; enc2 on tensor cores
    {
        dim3 grid((H_ + BN - 1) / BN, (NN_ + BM - 1) / BM);
        gemm_kernel<<<grid, 256>>>(x, enc_w1, h2, NN_, H_, DIN_, H_, 1, enc_b1, h2hi, h2lo);
    }
    launch_mma(h2hi, h2lo, whi + 0 * WSLOT, wlo + 0 * WSLOT, h, 256, /*ep=*/2, 3, 0,
               enc_b2, bns, bnsh, 0.f, hhi, hlo);

    // kNN graph (sim is symmetric: lower-triangle blocks + mirrored writes, 4-term split)
    rownorm_kernel<<<NN_, 256>>>();
    launch_mma(hnhi, hnlo, hnhi, hnlo, sim, NN_, /*ep=*/0, 4, 1);
    topk_kernel<<<NN_, 256>>>();

    // temporal gated graph conv layers
    for (int l = 0; l < NL_; l++) {
        launch_mma(hhi, hlo, whi + (1 + l) * WSLOT, wlo + (1 + l) * WSLOT, h2, 256, /*ep=*/3, 3, 0,
                   node_b + (size_t)l * H_);
        agg_kernel<<<NN_, 256>>>();
        launch_mma(aghi, aglo, whi + (3 + l) * WSLOT, wlo + (3 + l) * WSLOT, h, 256, /*ep=*/4, 3, 0,
                   gatec + (size_t)l * H_, agg, h2, 0.f, hhi, hlo);
    }

    // SDE (drift-only Euler, 10 steps)
    const float dt = 0.1f;
    for (int s = 0; s < NSTEPS_; s++) {
        launch_mma(hhi, hlo, whi + 5 * WSLOT, wlo + 5 * WSLOT, d1, 256, /*ep=*/5, 3, 0,
                   sdeb + (size_t)s * H_, nullptr, nullptr, 0.f, d1hi, d1lo);
        launch_mma(d1hi, d1lo, whi + 6 * WSLOT, wlo + 6 * WSLOT, d2, 256, /*ep=*/5, 3, 0,
                   sde_b2, nullptr, nullptr, 0.f, d2hi, d2lo);
        launch_mma(d2hi, d2lo, whi + 7 * WSLOT, wlo + 7 * WSLOT, h, 256, /*ep=*/6, 3, 0,
                   sde_b3, h, nullptr, dt, hhi, hlo);
    }

    // decoder: dec1 tensor (N=128), dec2 SIMT (K=128, N=34)
    launch_mma(hhi, hlo, whi + 8 * WSLOT, wlo + 8 * WSLOT, d1, 128, /*ep=*/1, 3, 0, dec_b1);
    {
        dim3 grid((C_ + BN - 1) / BN, (NN_ + BM - 1) / BM);
        gemm_kernel<<<grid, 256>>>(d1, dec_w2, out, NN_, C_, H_ / 2, C_, 3, dec_b2, nullptr, nullptr);
    }
}

// round 6
// speedup vs baseline: 2.1005x; 1.0769x over previous
#include <cuda_runtime.h>
#include <cuda_bf16.h>
#include <math.h>
#include <stdint.h>

// ---------------- problem constants ----------------
#define NN_   8192
#define DIN_  83
#define H_    256
#define C_    34
#define TD_   16
#define NL_   2
#define KNN_  11
#define NSTEPS_ 10

typedef __nv_bfloat16 bf16;

// ---------------- scratch (device globals; no allocation allowed) ----------------
__device__ float g_sim[(size_t)NN_ * NN_];          // 256 MB
__device__ float g_h  [NN_ * H_];
__device__ float g_h2 [NN_ * H_];
__device__ float g_hn [NN_ * H_];
__device__ float g_agg[NN_ * H_];
__device__ float g_d1 [NN_ * H_];
__device__ float g_d2 [NN_ * H_];
__device__ int   g_nidx[NN_ * KNN_];
__device__ float g_nval[NN_ * KNN_];
__device__ float g_bnscale[H_];
__device__ float g_bnshift[H_];
__device__ float g_gatec[NL_ * H_];
__device__ float g_sdebias[NSTEPS_ * H_];

// bf16 split copies of activations ([M,256] row-major hi/lo)
__device__ bf16 g_h_hi [NN_ * H_],  g_h_lo [NN_ * H_];
__device__ bf16 g_h2_hi[NN_ * H_],  g_h2_lo[NN_ * H_];
__device__ bf16 g_hn_hi[NN_ * H_],  g_hn_lo[NN_ * H_];
__device__ bf16 g_ag_hi[NN_ * H_],  g_ag_lo[NN_ * H_];
__device__ bf16 g_d1_hi[NN_ * H_],  g_d1_lo[NN_ * H_];
__device__ bf16 g_d2_hi[NN_ * H_],  g_d2_lo[NN_ * H_];

// transposed+split weights, [N,256] K-major; 9 slots of 64K elems
#define WSLOT 65536
__device__ bf16 g_w_hi[9 * WSLOT];
__device__ bf16 g_w_lo[9 * WSLOT];

// ================= helpers =================
__device__ __forceinline__ uint32_t smem_u32(const void* p) {
    uint32_t a;
    asm("{ .reg .u64 t; cvta.to.shared.u64 t, %1; cvt.u32.u64 %0, t; }" : "=r"(a) : "l"(p));
    return a;
}
__device__ __forceinline__ void ldsm4(uint32_t* r, uint32_t addr) {
    asm volatile("ldmatrix.sync.aligned.m8n8.x4.shared.b16 {%0,%1,%2,%3}, [%4];"
                 : "=r"(r[0]), "=r"(r[1]), "=r"(r[2]), "=r"(r[3]) : "r"(addr));
}
__device__ __forceinline__ void mma16816(float* d, const uint32_t* a, uint32_t b0, uint32_t b1) {
    asm volatile("mma.sync.aligned.m16n8k16.row.col.f32.bf16.bf16.f32 "
                 "{%0,%1,%2,%3}, {%4,%5,%6,%7}, {%8,%9}, {%0,%1,%2,%3};"
                 : "+f"(d[0]), "+f"(d[1]), "+f"(d[2]), "+f"(d[3])
                 : "r"(a[0]), "r"(a[1]), "r"(a[2]), "r"(a[3]), "r"(b0), "r"(b1));
}

// ================= tensor-core split-bf16 GEMM (mma.sync, cp.async pipelined) =================
// C[M=8192, Ntot] = (Ahi+Alo) @ (Bhi+Blo)^T, 4 split terms, fp32 accum.
// CTA tile 128x128, 512 threads / 16 warps, warp tile 32x32.
// K chunked 8 x 32, cp.async double buffered.
// mirror=1 (A==B symmetric): lower-triangle blocks only; off-diagonal writes
// the transposed tile too (smem staged).
// Epilogues: 0 y=z; 1 relu(z+p1); 2 relu(z+p1)*p2+p3; 3 z+p1;
//            4 gate; 5 tanh(z+p1); 6 p2[i,n]+tanh(z+p1)*alpha.

#define TILE_B   8192                    // 128 rows * 32 bf16 * 2B
#define BUF_B    (4 * TILE_B)            // Ah,Al,Bh,Bl
#define MG_SMEM  (2 * BUF_B)             // 64 KB double buffered

__device__ __forceinline__ void cpa_tile(const bf16* __restrict__ src, int r0, int k0,
                                         char* __restrict__ dst, int tid)
{
    int row = tid >> 2;                      // 0..127
    int seg = tid & 3;                       // 0..3 (16B each)
    const void* gp = src + (size_t)(r0 + row) * 256 + k0 + seg * 8;
    uint32_t off = (uint32_t)row * 64u + (uint32_t)((seg ^ ((row >> 1) & 3)) << 4);
    uint32_t sa = smem_u32(dst + off);
    asm volatile("cp.async.cg.shared.global [%0], [%1], 16;" :: "r"(sa), "l"(gp));
}

__global__ __launch_bounds__(512) void mma_gemm(
    const bf16* __restrict__ Ahi, const bf16* __restrict__ Alo,
    const bf16* __restrict__ Bhi, const bf16* __restrict__ Blo,
    float* __restrict__ C, int Ntot, int ep, int mirror,
    const float* __restrict__ p1, const float* __restrict__ p2,
    const float* __restrict__ p3, float alpha,
    bf16* __restrict__ Chi, bf16* __restrict__ Clo)
{
    const int bn0 = blockIdx.x * 128;
    const int bm0 = blockIdx.y * 128;
    if (mirror && bn0 > bm0) return;            // symmetric: lower triangle only

    extern __shared__ char smem[];
    char* bufp[2] = {smem, smem + BUF_B};

    const int tid  = threadIdx.x;
    const int wid  = tid >> 5;
    const int lane = tid & 31;
    const int warp_m = wid & 3;                 // rows  [warp_m*32, +32)
    const int warp_n = wid >> 2;                // cols  [warp_n*32, +32)

    float acc[2][4][4];
#pragma unroll
    for (int i = 0; i < 2; i++)
#pragma unroll
        for (int j = 0; j < 4; j++)
#pragma unroll
            for (int q = 0; q < 4; q++) acc[i][j][q] = 0.f;

    const int lrow  = lane & 15;
    const int lhalf = lane >> 4;

    // prologue: chunk 0 into buf 0
    cpa_tile(Ahi, bm0, 0, bufp[0] + 0 * TILE_B, tid);
    cpa_tile(Alo, bm0, 0, bufp[0] + 1 * TILE_B, tid);
    cpa_tile(Bhi, bn0, 0, bufp[0] + 2 * TILE_B, tid);
    cpa_tile(Blo, bn0, 0, bufp[0] + 3 * TILE_B, tid);
    asm volatile("cp.async.commit_group;" ::: "memory");

    int buf = 0;
    for (int chunk = 0; chunk < 8; chunk++) {
        if (chunk + 1 < 8) {
            const int k1 = (chunk + 1) * 32;
            char* nb = bufp[buf ^ 1];
            cpa_tile(Ahi, bm0, k1, nb + 0 * TILE_B, tid);
            cpa_tile(Alo, bm0, k1, nb + 1 * TILE_B, tid);
            cpa_tile(Bhi, bn0, k1, nb + 2 * TILE_B, tid);
            cpa_tile(Blo, bn0, k1, nb + 3 * TILE_B, tid);
            asm volatile("cp.async.commit_group;" ::: "memory");
            asm volatile("cp.async.wait_group 1;" ::: "memory");
        } else {
            asm volatile("cp.async.wait_group 0;" ::: "memory");
        }
        __syncthreads();

        const uint32_t sAh_b = smem_u32(bufp[buf] + 0 * TILE_B);
        const uint32_t sAl_b = smem_u32(bufp[buf] + 1 * TILE_B);
        const uint32_t sBh_b = smem_u32(bufp[buf] + 2 * TILE_B);
        const uint32_t sBl_b = smem_u32(bufp[buf] + 3 * TILE_B);

#pragma unroll
        for (int kk = 0; kk < 2; kk++) {
            const int segq = kk * 2 + lhalf;

            uint32_t aH[2][4], aL[2][4], bH[2][4], bL[2][4];
#pragma unroll
            for (int mt = 0; mt < 2; mt++) {
                int row = warp_m * 32 + mt * 16 + lrow;
                uint32_t off = (uint32_t)row * 64u + (uint32_t)((segq ^ ((row >> 1) & 3)) << 4);
                ldsm4(aH[mt], sAh_b + off);
                ldsm4(aL[mt], sAl_b + off);
            }
#pragma unroll
            for (int gg = 0; gg < 2; gg++) {
                int row = warp_n * 32 + gg * 16 + lrow;
                uint32_t off = (uint32_t)row * 64u + (uint32_t)((segq ^ ((row >> 1) & 3)) << 4);
                ldsm4(bH[gg], sBh_b + off);
                ldsm4(bL[gg], sBl_b + off);
            }

            // term-outer ordering: each acc reused at distance 8 MMAs
#define DO_TERM(Af, Bf)                                                        \
            _Pragma("unroll")                                                  \
            for (int mt = 0; mt < 2; mt++)                                     \
                _Pragma("unroll")                                              \
                for (int gg = 0; gg < 2; gg++) {                               \
                    mma16816(acc[mt][2 * gg + 0], Af[mt], Bf[gg][0], Bf[gg][2]); \
                    mma16816(acc[mt][2 * gg + 1], Af[mt], Bf[gg][1], Bf[gg][3]); \
                }
            DO_TERM(aH, bH)
            DO_TERM(aH, bL)
            DO_TERM(aL, bH)
            DO_TERM(aL, bL)
#undef DO_TERM
        }
        __syncthreads();
        buf ^= 1;
    }

    // ---- epilogue ----
    auto epi = [&](float z, int gr, int gc) -> float {
        if (ep == 0) return z;
        if (ep == 1) return fmaxf(z + p1[gc], 0.f);
        if (ep == 2) return fmaxf(z + p1[gc], 0.f) * p2[gc] + p3[gc];
        if (ep == 3) return z + p1[gc];
        if (ep == 4) {
            float g = 1.f / (1.f + expf(-(z + p1[gc])));
            float a = p2[(size_t)gr * Ntot + gc];
            float hh = p3[(size_t)gr * Ntot + gc];
            return fmaxf(g * a + (1.f - g) * hh, 0.f);
        }
        if (ep == 5) return tanhf(z + p1[gc]);
        return p2[(size_t)gr * Ntot + gc] + tanhf(z + p1[gc]) * alpha;  // 6
    };

#pragma unroll
    for (int mt = 0; mt < 2; mt++) {
#pragma unroll
        for (int half = 0; half < 2; half++) {
            int gr = bm0 + warp_m * 32 + mt * 16 + (lane >> 2) + half * 8;
#pragma unroll
            for (int nt = 0; nt < 4; nt++) {
                int gc = bn0 + warp_n * 32 + nt * 8 + (lane & 3) * 2;
                float y0 = epi(acc[mt][nt][half * 2 + 0], gr, gc);
                float y1 = epi(acc[mt][nt][half * 2 + 1], gr, gc + 1);
                float2 o; o.x = y0; o.y = y1;
                *(float2*)(C + (size_t)gr * Ntot + gc) = o;
                if (Chi) {
                    bf16 h0 = __float2bfloat16_rn(y0);
                    bf16 h1 = __float2bfloat16_rn(y1);
                    __nv_bfloat162 hp; hp.x = h0; hp.y = h1;
                    __nv_bfloat162 lp;
                    lp.x = __float2bfloat16_rn(y0 - __bfloat162float(h0));
                    lp.y = __float2bfloat16_rn(y1 - __bfloat162float(h1));
                    *(__nv_bfloat162*)(Chi + (size_t)gr * 256 + gc) = hp;
                    *(__nv_bfloat162*)(Clo + (size_t)gr * 256 + gc) = lp;
                }
            }
        }
    }

    // ---- mirror write (symmetric sim): C[bn0+j, bm0+i] = acc[i][j], smem-staged ----
    if (mirror && bm0 != bn0) {
        float* ts = (float*)smem;     // 32 x 132 floats per pass = 16.9 KB
#pragma unroll 1
        for (int p = 0; p < 4; p++) {
            __syncthreads();
            if (warp_n == p) {
#pragma unroll
                for (int mt = 0; mt < 2; mt++)
#pragma unroll
                    for (int half = 0; half < 2; half++) {
                        int grl = warp_m * 32 + mt * 16 + (lane >> 2) + half * 8;
#pragma unroll
                        for (int nt = 0; nt < 4; nt++) {
                            int gcl = nt * 8 + (lane & 3) * 2;     // 0..31 within group
                            ts[(gcl + 0) * 132 + grl] = acc[mt][nt][half * 2 + 0];
                            ts[(gcl + 1) * 132 + grl] = acc[mt][nt][half * 2 + 1];
                        }
                    }
            }
            __syncthreads();
            // write 32 rows x 128 cols, coalesced float4
#pragma unroll
            for (int u = 0; u < 2; u++) {
                int i = tid + u * 512;           // 0..1023 float4 segments
                int j = i >> 5;                  // row 0..31
                int q = i & 31;                  // float4 col 0..31
                float4 v;
                v.x = ts[j * 132 + q * 4 + 0];
                v.y = ts[j * 132 + q * 4 + 1];
                v.z = ts[j * 132 + q * 4 + 2];
                v.w = ts[j * 132 + q * 4 + 3];
                *(float4*)(C + (size_t)(bn0 + p * 32 + j) * Ntot + bm0 + q * 4) = v;
            }
        }
    }
}

// ================= SIMT fp32 GEMM (odd shapes: enc1 K=83, dec2 N=34) =================
#define BM 128
#define BN 128
#define BK 8

__global__ __launch_bounds__(256) void gemm_kernel(
    const float* __restrict__ A, const float* __restrict__ B, float* __restrict__ C,
    int M, int N, int K, int ldb, int ep,
    const float* __restrict__ p1, bf16* __restrict__ Chi, bf16* __restrict__ Clo)
{
    __shared__ float As[2][BK][BM + 4];
    __shared__ float Bs[2][BK][BN + 4];

    const int tid = threadIdx.x;
    const int tx  = tid & 15;
    const int ty  = tid >> 4;
    const int bn0 = blockIdx.x * BN;
    const int bm0 = blockIdx.y * BM;

    float acc[8][8];
#pragma unroll
    for (int i = 0; i < 8; i++)
#pragma unroll
        for (int j = 0; j < 8; j++) acc[i][j] = 0.f;

    const int aRow = tid >> 1;
    const int aK   = (tid & 1) * 4;
    const int bRow = tid >> 5;
    const int bN   = (tid & 31) * 4;

    float ra[4], rb[4];
    const int ktiles = (K + BK - 1) / BK;

#define LOAD_AB(kt) do {                                                       \
        int k0_ = (kt) * BK;                                                   \
        int gr_ = bm0 + aRow, gk_ = k0_ + aK;                                  \
        _Pragma("unroll")                                                      \
        for (int j_ = 0; j_ < 4; j_++)                                         \
            ra[j_] = (gr_ < M && gk_ + j_ < K) ? A[(size_t)gr_ * K + gk_ + j_] : 0.f; \
        int gk2_ = k0_ + bRow, gn_ = bn0 + bN;                                 \
        _Pragma("unroll")                                                      \
        for (int j_ = 0; j_ < 4; j_++)                                         \
            rb[j_] = (gk2_ < K && gn_ + j_ < N) ? B[(size_t)gk2_ * ldb + gn_ + j_] : 0.f; \
    } while (0)

#define STS_AB2(buf) do {                                                      \
        _Pragma("unroll")                                                      \
        for (int j_ = 0; j_ < 4; j_++) As[buf][aK + j_][aRow] = ra[j_];        \
        _Pragma("unroll")                                                      \
        for (int j_ = 0; j_ < 4; j_++) Bs[buf][bRow][bN + j_] = rb[j_];        \
    } while (0)

    LOAD_AB(0);
    STS_AB2(0);
    __syncthreads();

    int cur = 0;
    for (int kt = 0; kt < ktiles; kt++) {
        const int hasNext = (kt + 1 < ktiles);
        if (hasNext) LOAD_AB(kt + 1);
#pragma unroll
        for (int kk = 0; kk < BK; kk++) {
            const float* as = As[cur][kk];
            const float* bs = Bs[cur][kk];
            float4 A0 = *(const float4*)(as + ty * 4);
            float4 A1 = *(const float4*)(as + 64 + ty * 4);
            float4 B0 = *(const float4*)(bs + tx * 4);
            float4 B1 = *(const float4*)(bs + 64 + tx * 4);
            float av[8] = {A0.x, A0.y, A0.z, A0.w, A1.x, A1.y, A1.z, A1.w};
            float bv[8] = {B0.x, B0.y, B0.z, B0.w, B1.x, B1.y, B1.z, B1.w};
#pragma unroll
            for (int i = 0; i < 8; i++)
#pragma unroll
                for (int j = 0; j < 8; j++)
                    acc[i][j] = fmaf(av[i], bv[j], acc[i][j]);
        }
        if (hasNext) { STS_AB2(cur ^ 1); __syncthreads(); cur ^= 1; }
    }

#pragma unroll
    for (int i = 0; i < 8; i++) {
        int gr = bm0 + ((i < 4) ? (ty * 4 + i) : (64 + ty * 4 + (i - 4)));
        if (gr >= M) continue;
#pragma unroll
        for (int j = 0; j < 8; j++) {
            int gc = bn0 + ((j < 4) ? (tx * 4 + j) : (64 + tx * 4 + (j - 4)));
            if (gc >= N) continue;
            float z = acc[i][j];
            float y;
            if (ep == 1) y = fmaxf(z + p1[gc], 0.f);
            else if (ep == 3) y = z + p1[gc];
            else y = z;
            C[(size_t)gr * N + gc] = y;
            if (Chi) {
                bf16 hb = __float2bfloat16_rn(y);
                Chi[(size_t)gr * 256 + gc] = hb;
                Clo[(size_t)gr * 256 + gc] = __float2bfloat16_rn(y - __bfloat162float(hb));
            }
        }
    }
}

// ---------------- row-normalize h -> hn (+ bf16 split) ----------------
__global__ void rownorm_kernel()
{
    int row = blockIdx.x;
    int tid = threadIdx.x;                   // 256 == H_
    float v = g_h[row * H_ + tid];
    float s = v * v;
#pragma unroll
    for (int o = 16; o > 0; o >>= 1) s += __shfl_xor_sync(0xffffffff, s, o);
    __shared__ float ws[8];
    if ((tid & 31) == 0) ws[tid >> 5] = s;
    __syncthreads();
    if (tid < 8) {
        float t = ws[tid];
#pragma unroll
        for (int o = 4; o > 0; o >>= 1) t += __shfl_xor_sync(0xff, t, o);
        if (tid == 0) ws[0] = t;
    }
    __syncthreads();
    float denom = fmaxf(sqrtf(ws[0]), 1e-12f);
    float y = v / denom;
    g_hn[row * H_ + tid] = y;
    bf16 hb = __float2bfloat16_rn(y);
    g_hn_hi[row * H_ + tid] = hb;
    g_hn_lo[row * H_ + tid] = __float2bfloat16_rn(y - __bfloat162float(hb));
}

// ---------------- per-row top-k over sim + adjacency normalize ----------------
__global__ void topk_kernel()
{
    const int row = blockIdx.x;
    const int tid = threadIdx.x;
    const float* srow = g_sim + (size_t)row * NN_;

    float lv[KNN_];
    int   li[KNN_];
#pragma unroll
    for (int r = 0; r < KNN_; r++) { lv[r] = -INFINITY; li[r] = 0x7fffffff; }

    for (int j = tid; j < NN_; j += 256) {
        float v = srow[j];
        if (v > lv[KNN_ - 1]) {
            int p = KNN_ - 1;
            while (p > 0 && v > lv[p - 1]) { lv[p] = lv[p - 1]; li[p] = li[p - 1]; p--; }
            lv[p] = v; li[p] = j;
        }
    }

    __shared__ float sv[256 * KNN_];
    __shared__ int   si[256 * KNN_];
#pragma unroll
    for (int r = 0; r < KNN_; r++) { sv[tid * KNN_ + r] = lv[r]; si[tid * KNN_ + r] = li[r]; }
    __syncthreads();

    __shared__ float rv[256];
    __shared__ int   ri[256];
    __shared__ int   rp[256];
    __shared__ float outv[KNN_];
    __shared__ int   outi[KNN_];

    const int TOT = 256 * KNN_;
    for (int r = 0; r < KNN_; r++) {
        float bv = -INFINITY; int bi = 0x7fffffff; int bp = -1;
        for (int t = tid; t < TOT; t += 256) {
            float v = sv[t]; int ii = si[t];
            if (v > bv || (v == bv && ii < bi)) { bv = v; bi = ii; bp = t; }
        }
        rv[tid] = bv; ri[tid] = bi; rp[tid] = bp;
        __syncthreads();
        for (int s = 128; s > 0; s >>= 1) {
            if (tid < s) {
                float v2 = rv[tid + s]; int i2 = ri[tid + s];
                if (v2 > rv[tid] || (v2 == rv[tid] && i2 < ri[tid])) {
                    rv[tid] = v2; ri[tid] = i2; rp[tid] = rp[tid + s];
                }
            }
            __syncthreads();
        }
        if (tid == 0) {
            outv[r] = rv[0]; outi[r] = ri[0];
            sv[rp[0]] = -INFINITY;
        }
        __syncthreads();
    }

    if (tid == 0) {
        float s = 0.f;
#pragma unroll
        for (int r = 0; r < KNN_; r++) s += outv[r];
        float inv = 1.f / fmaxf(s, 1.f);
#pragma unroll
        for (int r = 0; r < KNN_; r++) {
            g_nidx[row * KNN_ + r] = outi[r];
            g_nval[row * KNN_ + r] = outv[r] * inv;
        }
    }
}

// ---------------- sparse aggregation (+ bf16 split) ----------------
__global__ void agg_kernel()
{
    int row = blockIdx.x;
    int tid = threadIdx.x;                  // 256 == H_
    float acc = 0.f;
#pragma unroll
    for (int r = 0; r < KNN_; r++) {
        float w = g_nval[row * KNN_ + r];
        int   n = g_nidx[row * KNN_ + r];
        acc += w * g_h2[(size_t)n * H_ + tid];
    }
    g_agg[row * H_ + tid] = acc;
    bf16 hb = __float2bfloat16_rn(acc);
    g_ag_hi[row * H_ + tid] = hb;
    g_ag_lo[row * H_ + tid] = __float2bfloat16_rn(acc - __bfloat162float(hb));
}

// ---------------- weight transpose + split: W[K=256,N] -> [N,256] hi/lo ----------------
__global__ void wsplit_kernel(const float* __restrict__ W, int N, bf16* __restrict__ hi,
                              bf16* __restrict__ lo)
{
    int idx = blockIdx.x * 256 + threadIdx.x;      // over 256*N
    if (idx >= 256 * N) return;
    int k = idx / N, n = idx % N;
    float v = W[k * N + n];
    bf16 hb = __float2bfloat16_rn(v);
    hi[n * 256 + k] = hb;
    lo[n * 256 + k] = __float2bfloat16_rn(v - __bfloat162float(hb));
}

// ---------------- tiny precompute ----------------
__global__ void precompute_kernel(const float* __restrict__ bn_g, const float* __restrict__ bn_b,
                                  const float* __restrict__ bn_m, const float* __restrict__ bn_v,
                                  const float* __restrict__ t_w1, const float* __restrict__ t_b1,
                                  const float* __restrict__ t_w2, const float* __restrict__ t_b2,
                                  const float* __restrict__ gate_w, const float* __restrict__ gate_b,
                                  const float* __restrict__ sde_w1, const float* __restrict__ sde_b1)
{
    int b = blockIdx.x;
    int j = threadIdx.x;
    if (b == 0) {
        float s = bn_g[j] * rsqrtf(bn_v[j] + 1e-5f);
        g_bnscale[j] = s;
        g_bnshift[j] = bn_b[j] - bn_m[j] * s;
    } else if (b <= NL_) {
        int l = b - 1;
        float t = 0.5f * (float)l;
        __shared__ float te[TD_];
        __shared__ float te2[H_];
        if (j < TD_) te[j] = fmaxf(t * t_w1[l * TD_ + j] + t_b1[l * TD_ + j], 0.f);
        __syncthreads();
        float acc = t_b2[l * H_ + j];
#pragma unroll
        for (int k = 0; k < TD_; k++) acc += te[k] * t_w2[l * TD_ * H_ + k * H_ + j];
        te2[j] = acc;
        __syncthreads();
        float c = gate_b[l * H_ + j];
        const float* W = gate_w + (size_t)l * 2 * H_ * H_ + (size_t)H_ * H_;
        for (int k = 0; k < H_; k++) c += te2[k] * W[k * H_ + j];
        g_gatec[l * H_ + j] = c;
    } else {
        int s = b - 1 - NL_;
        float ts = (float)s * 0.1f;
        g_sdebias[s * H_ + j] = sde_b1[j] + ts * sde_w1[H_ * H_ + j];
    }
}

// ---------------- host ----------------
static inline void launch_mma(const bf16* Ahi, const bf16* Alo, const bf16* Bhi, const bf16* Blo,
                              float* C, int Ntot, int ep, int mirror,
                              const float* p1 = nullptr, const float* p2 = nullptr,
                              const float* p3 = nullptr, float alpha = 0.f,
                              bf16* Chi = nullptr, bf16* Clo = nullptr)
{
    dim3 grid(Ntot / 128, NN_ / 128);
    mma_gemm<<<grid, 512, MG_SMEM>>>(Ahi, Alo, Bhi, Blo, C, Ntot, ep, mirror,
                                     p1, p2, p3, alpha, Chi, Clo);
}

extern "C" void kernel_launch(void* const* d_in, const int* in_sizes, int n_in,
                              void* d_out, int out_size)
{
    const float* x       = (const float*)d_in[0];
    const float* enc_w1  = (const float*)d_in[1];
    const float* enc_b1  = (const float*)d_in[2];
    const float* enc_w2  = (const float*)d_in[3];
    const float* enc_b2  = (const float*)d_in[4];
    const float* bn_g    = (const float*)d_in[5];
    const float* bn_b    = (const float*)d_in[6];
    const float* bn_m    = (const float*)d_in[7];
    const float* bn_v    = (const float*)d_in[8];
    const float* node_w  = (const float*)d_in[9];
    const float* node_b  = (const float*)d_in[10];
    const float* t_w1    = (const float*)d_in[11];
    const float* t_b1    = (const float*)d_in[12];
    const float* t_w2    = (const float*)d_in[13];
    const float* t_b2    = (const float*)d_in[14];
    const float* gate_w  = (const float*)d_in[15];
    const float* gate_b  = (const float*)d_in[16];
    const float* sde_w1  = (const float*)d_in[17];
    const float* sde_b1  = (const float*)d_in[18];
    const float* sde_w2  = (const float*)d_in[19];
    const float* sde_b2  = (const float*)d_in[20];
    const float* sde_w3  = (const float*)d_in[21];
    const float* sde_b3  = (const float*)d_in[22];
    const float* dec_w1  = (const float*)d_in[23];
    const float* dec_b1  = (const float*)d_in[24];
    const float* dec_w2  = (const float*)d_in[25];
    const float* dec_b2  = (const float*)d_in[26];
    float* out = (float*)d_out;

    cudaFuncSetAttribute(mma_gemm, cudaFuncAttributeMaxDynamicSharedMemorySize, MG_SMEM);

    float *sim, *h, *h2, *hn, *agg, *d1, *d2, *bns, *bnsh, *gatec, *sdeb;
    bf16 *hhi, *hlo, *h2hi, *h2lo, *hnhi, *hnlo, *aghi, *aglo, *d1hi, *d1lo, *d2hi, *d2lo, *whi, *wlo;
    cudaGetSymbolAddress((void**)&sim,   g_sim);
    cudaGetSymbolAddress((void**)&h,     g_h);
    cudaGetSymbolAddress((void**)&h2,    g_h2);
    cudaGetSymbolAddress((void**)&hn,    g_hn);
    cudaGetSymbolAddress((void**)&agg,   g_agg);
    cudaGetSymbolAddress((void**)&d1,    g_d1);
    cudaGetSymbolAddress((void**)&d2,    g_d2);
    cudaGetSymbolAddress((void**)&bns,   g_bnscale);
    cudaGetSymbolAddress((void**)&bnsh,  g_bnshift);
    cudaGetSymbolAddress((void**)&gatec, g_gatec);
    cudaGetSymbolAddress((void**)&sdeb,  g_sdebias);
    cudaGetSymbolAddress((void**)&hhi,  g_h_hi);  cudaGetSymbolAddress((void**)&hlo,  g_h_lo);
    cudaGetSymbolAddress((void**)&h2hi, g_h2_hi); cudaGetSymbolAddress((void**)&h2lo, g_h2_lo);
    cudaGetSymbolAddress((void**)&hnhi, g_hn_hi); cudaGetSymbolAddress((void**)&hnlo, g_hn_lo);
    cudaGetSymbolAddress((void**)&aghi, g_ag_hi); cudaGetSymbolAddress((void**)&aglo, g_ag_lo);
    cudaGetSymbolAddress((void**)&d1hi, g_d1_hi); cudaGetSymbolAddress((void**)&d1lo, g_d1_lo);
    cudaGetSymbolAddress((void**)&d2hi, g_d2_hi); cudaGetSymbolAddress((void**)&d2lo, g_d2_lo);
    cudaGetSymbolAddress((void**)&whi, g_w_hi);   cudaGetSymbolAddress((void**)&wlo, g_w_lo);

    precompute_kernel<<<1 + NL_ + NSTEPS_, 256>>>(bn_g, bn_b, bn_m, bn_v,
                                                  t_w1, t_b1, t_w2, t_b2,
                                                  gate_w, gate_b, sde_w1, sde_b1);

    // weight transpose + split (slot: 0 enc2, 1/2 node, 3/4 gate-top, 5/6/7 sde, 8 dec1)
    wsplit_kernel<<<256, 256>>>(enc_w2, 256, whi + 0 * WSLOT, wlo + 0 * WSLOT);
    wsplit_kernel<<<256, 256>>>(node_w,             256, whi + 1 * WSLOT, wlo + 1 * WSLOT);
    wsplit_kernel<<<256, 256>>>(node_w + H_ * H_,   256, whi + 2 * WSLOT, wlo + 2 * WSLOT);
    wsplit_kernel<<<256, 256>>>(gate_w,                     256, whi + 3 * WSLOT, wlo + 3 * WSLOT);
    wsplit_kernel<<<256, 256>>>(gate_w + 2 * H_ * H_,       256, whi + 4 * WSLOT, wlo + 4 * WSLOT);
    wsplit_kernel<<<256, 256>>>(sde_w1, 256, whi + 5 * WSLOT, wlo + 5 * WSLOT);
    wsplit_kernel<<<256, 256>>>(sde_w2, 256, whi + 6 * WSLOT, wlo + 6 * WSLOT);
    wsplit_kernel<<<256, 256>>>(sde_w3, 256, whi + 7 * WSLOT, wlo + 7 * WSLOT);
    wsplit_kernel<<<128, 256>>>(dec_w1, 128, whi + 8 * WSLOT, wlo + 8 * WSLOT);

    // encoder: enc1 SIMT (K=83) with split output; enc2 on tensor cores
    {
        dim3 grid((H_ + BN - 1) / BN, (NN_ + BM - 1) / BM);
        gemm_kernel<<<grid, 256>>>(x, enc_w1, h2, NN_, H_, DIN_, H_, 1, enc_b1, h2hi, h2lo);
    }
    launch_mma(h2hi, h2lo, whi + 0 * WSLOT, wlo + 0 * WSLOT, h, 256, /*ep=*/2, 0,
               enc_b2, bns, bnsh, 0.f, hhi, hlo);

    // kNN graph (sim is symmetric: lower-triangle blocks + mirrored writes)
    rownorm_kernel<<<NN_, 256>>>();
    launch_mma(hnhi, hnlo, hnhi, hnlo, sim, NN_, /*ep=*/0, 1);
    topk_kernel<<<NN_, 256>>>();

    // temporal gated graph conv layers
    for (int l = 0; l < NL_; l++) {
        launch_mma(hhi, hlo, whi + (1 + l) * WSLOT, wlo + (1 + l) * WSLOT, h2, 256, /*ep=*/3, 0,
                   node_b + (size_t)l * H_);
        agg_kernel<<<NN_, 256>>>();
        launch_mma(aghi, aglo, whi + (3 + l) * WSLOT, wlo + (3 + l) * WSLOT, h, 256, /*ep=*/4, 0,
                   gatec + (size_t)l * H_, agg, h2, 0.f, hhi, hlo);
    }

    // SDE (drift-only Euler, 10 steps)
    const float dt = 0.1f;
    for (int s = 0; s < NSTEPS_; s++) {
        launch_mma(hhi, hlo, whi + 5 * WSLOT, wlo + 5 * WSLOT, d1, 256, /*ep=*/5, 0,
                   sdeb + (size_t)s * H_, nullptr, nullptr, 0.f, d1hi, d1lo);
        launch_mma(d1hi, d1lo, whi + 6 * WSLOT, wlo + 6 * WSLOT, d2, 256, /*ep=*/5, 0,
                   sde_b2, nullptr, nullptr, 0.f, d2hi, d2lo);
        launch_mma(d2hi, d2lo, whi + 7 * WSLOT, wlo + 7 * WSLOT, h, 256, /*ep=*/6, 0,
                   sde_b3, h, nullptr, dt, hhi, hlo);
    }

    // decoder: dec1 tensor (N=128), dec2 SIMT (K=128, N=34)
    launch_mma(hhi, hlo, whi + 8 * WSLOT, wlo + 8 * WSLOT, d1, 128, /*ep=*/1, 0, dec_b1);
    {
        dim3 grid((C_ + BN - 1) / BN, (NN_ + BM - 1) / BM);
        gemm_kernel<<<grid, 256>>>(d1, dec_w2, out, NN_, C_, H_ / 2, C_, 3, dec_b2, nullptr, nullptr);
    }
}

// round 7
// speedup vs baseline: 2.1040x; 1.0017x over previous
#include <cuda_runtime.h>
#include <cuda_bf16.h>
#include <math.h>
#include <stdint.h>

// ---------------- problem constants ----------------
#define NN_   8192
#define DIN_  83
#define H_    256
#define C_    34
#define TD_   16
#define NL_   2
#define KNN_  11
#define NSTEPS_ 10

typedef __nv_bfloat16 bf16;

// ---------------- scratch (device globals; no allocation allowed) ----------------
__device__ float g_sim[(size_t)NN_ * NN_];          // 256 MB
__device__ float g_h  [NN_ * H_];
__device__ float g_h2 [NN_ * H_];
__device__ float g_hn [NN_ * H_];
__device__ float g_agg[NN_ * H_];
__device__ float g_d1 [NN_ * H_];
__device__ float g_d2 [NN_ * H_];
__device__ int   g_nidx[NN_ * KNN_];
__device__ float g_nval[NN_ * KNN_];
__device__ float g_bnscale[H_];
__device__ float g_bnshift[H_];
__device__ float g_gatec[NL_ * H_];
__device__ float g_sdebias[NSTEPS_ * H_];

// bf16 split copies of activations ([M,256] row-major hi/lo)
__device__ bf16 g_h_hi [NN_ * H_],  g_h_lo [NN_ * H_];
__device__ bf16 g_h2_hi[NN_ * H_],  g_h2_lo[NN_ * H_];
__device__ bf16 g_hn_hi[NN_ * H_],  g_hn_lo[NN_ * H_];
__device__ bf16 g_ag_hi[NN_ * H_],  g_ag_lo[NN_ * H_];
__device__ bf16 g_d1_hi[NN_ * H_],  g_d1_lo[NN_ * H_];
__device__ bf16 g_d2_hi[NN_ * H_],  g_d2_lo[NN_ * H_];

// transposed+split weights, [N,256] K-major; 9 slots of 64K elems
#define WSLOT 65536
__device__ bf16 g_w_hi[9 * WSLOT];
__device__ bf16 g_w_lo[9 * WSLOT];

// ================= helpers =================
__device__ __forceinline__ uint32_t smem_u32(const void* p) {
    uint32_t a;
    asm("{ .reg .u64 t; cvta.to.shared.u64 t, %1; cvt.u32.u64 %0, t; }" : "=r"(a) : "l"(p));
    return a;
}
__device__ __forceinline__ void ldsm4(uint32_t* r, uint32_t addr) {
    asm volatile("ldmatrix.sync.aligned.m8n8.x4.shared.b16 {%0,%1,%2,%3}, [%4];"
                 : "=r"(r[0]), "=r"(r[1]), "=r"(r[2]), "=r"(r[3]) : "r"(addr));
}
__device__ __forceinline__ void mma16816(float* d, const uint32_t* a, uint32_t b0, uint32_t b1) {
    asm volatile("mma.sync.aligned.m16n8k16.row.col.f32.bf16.bf16.f32 "
                 "{%0,%1,%2,%3}, {%4,%5,%6,%7}, {%8,%9}, {%0,%1,%2,%3};"
                 : "+f"(d[0]), "+f"(d[1]), "+f"(d[2]), "+f"(d[3])
                 : "r"(a[0]), "r"(a[1]), "r"(a[2]), "r"(a[3]), "r"(b0), "r"(b1));
}
__device__ __forceinline__ float fast_tanh(float x) {
    float ax = fabsf(x);
    float t = __expf(-2.f * ax);
    float r = __fdividef(1.f - t, 1.f + t);
    return copysignf(r, x);
}
__device__ __forceinline__ float fast_sigmoid(float x) {
    return __fdividef(1.f, 1.f + __expf(-x));
}

// ================= tensor-core split-bf16 GEMM (mma.sync, cp.async pipelined) =================
// C[M=8192, Ntot] = (Ahi+Alo) @ (Bhi+Blo)^T, 4 split terms, fp32 accum.
// CTA tile 128x128, 512 threads / 16 warps, warp tile 32x32.
// K chunked 8 x 32, cp.async double buffered.
// mirror=1 (A==B symmetric): lower-triangle blocks only; off-diagonal writes
// the transposed tile too (smem staged).
// C may be nullptr (skip fp32 store; splits only).
// Epilogues: 0 y=z; 1 relu(z+p1); 2 relu(z+p1)*p2+p3; 3 z+p1;
//            4 gate; 5 tanh(z+p1); 6 p2[i,n]+tanh(z+p1)*alpha.

#define TILE_B   8192                    // 128 rows * 32 bf16 * 2B
#define BUF_B    (4 * TILE_B)            // Ah,Al,Bh,Bl
#define MG_SMEM  (2 * BUF_B)             // 64 KB double buffered

__device__ __forceinline__ void cpa_tile(const bf16* __restrict__ src, int r0, int k0,
                                         char* __restrict__ dst, int tid)
{
    int row = tid >> 2;                      // 0..127
    int seg = tid & 3;                       // 0..3 (16B each)
    const void* gp = src + (size_t)(r0 + row) * 256 + k0 + seg * 8;
    uint32_t off = (uint32_t)row * 64u + (uint32_t)((seg ^ ((row >> 1) & 3)) << 4);
    uint32_t sa = smem_u32(dst + off);
    asm volatile("cp.async.cg.shared.global [%0], [%1], 16;" :: "r"(sa), "l"(gp));
}

__global__ __launch_bounds__(512) void mma_gemm(
    const bf16* __restrict__ Ahi, const bf16* __restrict__ Alo,
    const bf16* __restrict__ Bhi, const bf16* __restrict__ Blo,
    float* __restrict__ C, int Ntot, int ep, int mirror,
    const float* __restrict__ p1, const float* __restrict__ p2,
    const float* __restrict__ p3, float alpha,
    bf16* __restrict__ Chi, bf16* __restrict__ Clo)
{
    const int bn0 = blockIdx.x * 128;
    const int bm0 = blockIdx.y * 128;
    if (mirror && bn0 > bm0) return;            // symmetric: lower triangle only

    extern __shared__ char smem[];
    char* bufp[2] = {smem, smem + BUF_B};

    const int tid  = threadIdx.x;
    const int wid  = tid >> 5;
    const int lane = tid & 31;
    const int warp_m = wid & 3;                 // rows  [warp_m*32, +32)
    const int warp_n = wid >> 2;                // cols  [warp_n*32, +32)

    float acc[2][4][4];
#pragma unroll
    for (int i = 0; i < 2; i++)
#pragma unroll
        for (int j = 0; j < 4; j++)
#pragma unroll
            for (int q = 0; q < 4; q++) acc[i][j][q] = 0.f;

    const int lrow  = lane & 15;
    const int lhalf = lane >> 4;

    // prologue: chunk 0 into buf 0
    cpa_tile(Ahi, bm0, 0, bufp[0] + 0 * TILE_B, tid);
    cpa_tile(Alo, bm0, 0, bufp[0] + 1 * TILE_B, tid);
    cpa_tile(Bhi, bn0, 0, bufp[0] + 2 * TILE_B, tid);
    cpa_tile(Blo, bn0, 0, bufp[0] + 3 * TILE_B, tid);
    asm volatile("cp.async.commit_group;" ::: "memory");

    int buf = 0;
    for (int chunk = 0; chunk < 8; chunk++) {
        if (chunk + 1 < 8) {
            const int k1 = (chunk + 1) * 32;
            char* nb = bufp[buf ^ 1];
            cpa_tile(Ahi, bm0, k1, nb + 0 * TILE_B, tid);
            cpa_tile(Alo, bm0, k1, nb + 1 * TILE_B, tid);
            cpa_tile(Bhi, bn0, k1, nb + 2 * TILE_B, tid);
            cpa_tile(Blo, bn0, k1, nb + 3 * TILE_B, tid);
            asm volatile("cp.async.commit_group;" ::: "memory");
            asm volatile("cp.async.wait_group 1;" ::: "memory");
        } else {
            asm volatile("cp.async.wait_group 0;" ::: "memory");
        }
        __syncthreads();

        const uint32_t sAh_b = smem_u32(bufp[buf] + 0 * TILE_B);
        const uint32_t sAl_b = smem_u32(bufp[buf] + 1 * TILE_B);
        const uint32_t sBh_b = smem_u32(bufp[buf] + 2 * TILE_B);
        const uint32_t sBl_b = smem_u32(bufp[buf] + 3 * TILE_B);

#pragma unroll
        for (int kk = 0; kk < 2; kk++) {
            const int segq = kk * 2 + lhalf;

            uint32_t aH[2][4], aL[2][4], bH[2][4], bL[2][4];
#pragma unroll
            for (int mt = 0; mt < 2; mt++) {
                int row = warp_m * 32 + mt * 16 + lrow;
                uint32_t off = (uint32_t)row * 64u + (uint32_t)((segq ^ ((row >> 1) & 3)) << 4);
                ldsm4(aH[mt], sAh_b + off);
                ldsm4(aL[mt], sAl_b + off);
            }
#pragma unroll
            for (int gg = 0; gg < 2; gg++) {
                int row = warp_n * 32 + gg * 16 + lrow;
                uint32_t off = (uint32_t)row * 64u + (uint32_t)((segq ^ ((row >> 1) & 3)) << 4);
                ldsm4(bH[gg], sBh_b + off);
                ldsm4(bL[gg], sBl_b + off);
            }

            // term-outer ordering: each acc reused at distance 8 MMAs
#define DO_TERM(Af, Bf)                                                        \
            _Pragma("unroll")                                                  \
            for (int mt = 0; mt < 2; mt++)                                     \
                _Pragma("unroll")                                              \
                for (int gg = 0; gg < 2; gg++) {                               \
                    mma16816(acc[mt][2 * gg + 0], Af[mt], Bf[gg][0], Bf[gg][2]); \
                    mma16816(acc[mt][2 * gg + 1], Af[mt], Bf[gg][1], Bf[gg][3]); \
                }
            DO_TERM(aH, bH)
            DO_TERM(aH, bL)
            DO_TERM(aL, bH)
            DO_TERM(aL, bL)
#undef DO_TERM
        }
        __syncthreads();
        buf ^= 1;
    }

    // ---- epilogue ----
    auto epi = [&](float z, int gr, int gc) -> float {
        if (ep == 0) return z;
        if (ep == 1) return fmaxf(z + p1[gc], 0.f);
        if (ep == 2) return fmaxf(z + p1[gc], 0.f) * p2[gc] + p3[gc];
        if (ep == 3) return z + p1[gc];
        if (ep == 4) {
            float g = fast_sigmoid(z + p1[gc]);
            float a = p2[(size_t)gr * Ntot + gc];
            float hh = p3[(size_t)gr * Ntot + gc];
            return fmaxf(g * a + (1.f - g) * hh, 0.f);
        }
        if (ep == 5) return fast_tanh(z + p1[gc]);
        return p2[(size_t)gr * Ntot + gc] + fast_tanh(z + p1[gc]) * alpha;  // 6
    };

#pragma unroll
    for (int mt = 0; mt < 2; mt++) {
#pragma unroll
        for (int half = 0; half < 2; half++) {
            int gr = bm0 + warp_m * 32 + mt * 16 + (lane >> 2) + half * 8;
#pragma unroll
            for (int nt = 0; nt < 4; nt++) {
                int gc = bn0 + warp_n * 32 + nt * 8 + (lane & 3) * 2;
                float y0 = epi(acc[mt][nt][half * 2 + 0], gr, gc);
                float y1 = epi(acc[mt][nt][half * 2 + 1], gr, gc + 1);
                if (C) {
                    float2 o; o.x = y0; o.y = y1;
                    *(float2*)(C + (size_t)gr * Ntot + gc) = o;
                }
                if (Chi) {
                    bf16 h0 = __float2bfloat16_rn(y0);
                    bf16 h1 = __float2bfloat16_rn(y1);
                    __nv_bfloat162 hp; hp.x = h0; hp.y = h1;
                    __nv_bfloat162 lp;
                    lp.x = __float2bfloat16_rn(y0 - __bfloat162float(h0));
                    lp.y = __float2bfloat16_rn(y1 - __bfloat162float(h1));
                    *(__nv_bfloat162*)(Chi + (size_t)gr * 256 + gc) = hp;
                    *(__nv_bfloat162*)(Clo + (size_t)gr * 256 + gc) = lp;
                }
            }
        }
    }

    // ---- mirror write (symmetric sim): C[bn0+j, bm0+i] = acc[i][j], smem-staged ----
    if (mirror && bm0 != bn0) {
        float* ts = (float*)smem;     // 32 x 132 floats per pass = 16.9 KB
#pragma unroll 1
        for (int p = 0; p < 4; p++) {
            __syncthreads();
            if (warp_n == p) {
#pragma unroll
                for (int mt = 0; mt < 2; mt++)
#pragma unroll
                    for (int half = 0; half < 2; half++) {
                        int grl = warp_m * 32 + mt * 16 + (lane >> 2) + half * 8;
#pragma unroll
                        for (int nt = 0; nt < 4; nt++) {
                            int gcl = nt * 8 + (lane & 3) * 2;     // 0..31 within group
                            ts[(gcl + 0) * 132 + grl] = acc[mt][nt][half * 2 + 0];
                            ts[(gcl + 1) * 132 + grl] = acc[mt][nt][half * 2 + 1];
                        }
                    }
            }
            __syncthreads();
            // write 32 rows x 128 cols, coalesced float4
#pragma unroll
            for (int u = 0; u < 2; u++) {
                int i = tid + u * 512;           // 0..1023 float4 segments
                int j = i >> 5;                  // row 0..31
                int q = i & 31;                  // float4 col 0..31
                float4 v;
                v.x = ts[j * 132 + q * 4 + 0];
                v.y = ts[j * 132 + q * 4 + 1];
                v.z = ts[j * 132 + q * 4 + 2];
                v.w = ts[j * 132 + q * 4 + 3];
                *(float4*)(C + (size_t)(bn0 + p * 32 + j) * Ntot + bm0 + q * 4) = v;
            }
        }
    }
}

// ================= SIMT fp32 GEMM (odd shapes: enc1 K=83, dec2 N=34) =================
#define BM 128
#define BN 128
#define BK 8

__global__ __launch_bounds__(256) void gemm_kernel(
    const float* __restrict__ A, const float* __restrict__ B, float* __restrict__ C,
    int M, int N, int K, int ldb, int ep,
    const float* __restrict__ p1, bf16* __restrict__ Chi, bf16* __restrict__ Clo)
{
    __shared__ float As[2][BK][BM + 4];
    __shared__ float Bs[2][BK][BN + 4];

    const int tid = threadIdx.x;
    const int tx  = tid & 15;
    const int ty  = tid >> 4;
    const int bn0 = blockIdx.x * BN;
    const int bm0 = blockIdx.y * BM;

    float acc[8][8];
#pragma unroll
    for (int i = 0; i < 8; i++)
#pragma unroll
        for (int j = 0; j < 8; j++) acc[i][j] = 0.f;

    const int aRow = tid >> 1;
    const int aK   = (tid & 1) * 4;
    const int bRow = tid >> 5;
    const int bN   = (tid & 31) * 4;

    float ra[4], rb[4];
    const int ktiles = (K + BK - 1) / BK;

#define LOAD_AB(kt) do {                                                       \
        int k0_ = (kt) * BK;                                                   \
        int gr_ = bm0 + aRow, gk_ = k0_ + aK;                                  \
        _Pragma("unroll")                                                      \
        for (int j_ = 0; j_ < 4; j_++)                                         \
            ra[j_] = (gr_ < M && gk_ + j_ < K) ? A[(size_t)gr_ * K + gk_ + j_] : 0.f; \
        int gk2_ = k0_ + bRow, gn_ = bn0 + bN;                                 \
        _Pragma("unroll")                                                      \
        for (int j_ = 0; j_ < 4; j_++)                                         \
            rb[j_] = (gk2_ < K && gn_ + j_ < N) ? B[(size_t)gk2_ * ldb + gn_ + j_] : 0.f; \
    } while (0)

#define STS_AB2(buf) do {                                                      \
        _Pragma("unroll")                                                      \
        for (int j_ = 0; j_ < 4; j_++) As[buf][aK + j_][aRow] = ra[j_];        \
        _Pragma("unroll")                                                      \
        for (int j_ = 0; j_ < 4; j_++) Bs[buf][bRow][bN + j_] = rb[j_];        \
    } while (0)

    LOAD_AB(0);
    STS_AB2(0);
    __syncthreads();

    int cur = 0;
    for (int kt = 0; kt < ktiles; kt++) {
        const int hasNext = (kt + 1 < ktiles);
        if (hasNext) LOAD_AB(kt + 1);
#pragma unroll
        for (int kk = 0; kk < BK; kk++) {
            const float* as = As[cur][kk];
            const float* bs = Bs[cur][kk];
            float4 A0 = *(const float4*)(as + ty * 4);
            float4 A1 = *(const float4*)(as + 64 + ty * 4);
            float4 B0 = *(const float4*)(bs + tx * 4);
            float4 B1 = *(const float4*)(bs + 64 + tx * 4);
            float av[8] = {A0.x, A0.y, A0.z, A0.w, A1.x, A1.y, A1.z, A1.w};
            float bv[8] = {B0.x, B0.y, B0.z, B0.w, B1.x, B1.y, B1.z, B1.w};
#pragma unroll
            for (int i = 0; i < 8; i++)
#pragma unroll
                for (int j = 0; j < 8; j++)
                    acc[i][j] = fmaf(av[i], bv[j], acc[i][j]);
        }
        if (hasNext) { STS_AB2(cur ^ 1); __syncthreads(); cur ^= 1; }
    }

#pragma unroll
    for (int i = 0; i < 8; i++) {
        int gr = bm0 + ((i < 4) ? (ty * 4 + i) : (64 + ty * 4 + (i - 4)));
        if (gr >= M) continue;
#pragma unroll
        for (int j = 0; j < 8; j++) {
            int gc = bn0 + ((j < 4) ? (tx * 4 + j) : (64 + tx * 4 + (j - 4)));
            if (gc >= N) continue;
            float z = acc[i][j];
            float y;
            if (ep == 1) y = fmaxf(z + p1[gc], 0.f);
            else if (ep == 3) y = z + p1[gc];
            else y = z;
            if (C) C[(size_t)gr * N + gc] = y;
            if (Chi) {
                bf16 hb = __float2bfloat16_rn(y);
                Chi[(size_t)gr * 256 + gc] = hb;
                Clo[(size_t)gr * 256 + gc] = __float2bfloat16_rn(y - __bfloat162float(hb));
            }
        }
    }
}

// ---------------- row-normalize h -> hn (+ bf16 split) ----------------
__global__ void rownorm_kernel()
{
    int row = blockIdx.x;
    int tid = threadIdx.x;                   // 256 == H_
    float v = g_h[row * H_ + tid];
    float s = v * v;
#pragma unroll
    for (int o = 16; o > 0; o >>= 1) s += __shfl_xor_sync(0xffffffff, s, o);
    __shared__ float ws[8];
    if ((tid & 31) == 0) ws[tid >> 5] = s;
    __syncthreads();
    if (tid < 8) {
        float t = ws[tid];
#pragma unroll
        for (int o = 4; o > 0; o >>= 1) t += __shfl_xor_sync(0xff, t, o);
        if (tid == 0) ws[0] = t;
    }
    __syncthreads();
    float denom = fmaxf(sqrtf(ws[0]), 1e-12f);
    float y = v / denom;
    g_hn[row * H_ + tid] = y;
    bf16 hb = __float2bfloat16_rn(y);
    g_hn_hi[row * H_ + tid] = hb;
    g_hn_lo[row * H_ + tid] = __float2bfloat16_rn(y - __bfloat162float(hb));
}

// ---------------- per-row top-k over sim + adjacency normalize ----------------
__global__ void topk_kernel()
{
    const int row = blockIdx.x;
    const int tid = threadIdx.x;
    const float* srow = g_sim + (size_t)row * NN_;

    float lv[KNN_];
    int   li[KNN_];
#pragma unroll
    for (int r = 0; r < KNN_; r++) { lv[r] = -INFINITY; li[r] = 0x7fffffff; }

    for (int j = tid; j < NN_; j += 256) {
        float v = srow[j];
        if (v > lv[KNN_ - 1]) {
            int p = KNN_ - 1;
            while (p > 0 && v > lv[p - 1]) { lv[p] = lv[p - 1]; li[p] = li[p - 1]; p--; }
            lv[p] = v; li[p] = j;
        }
    }

    __shared__ float sv[256 * KNN_];
    __shared__ int   si[256 * KNN_];
#pragma unroll
    for (int r = 0; r < KNN_; r++) { sv[tid * KNN_ + r] = lv[r]; si[tid * KNN_ + r] = li[r]; }
    __syncthreads();

    __shared__ float rv[256];
    __shared__ int   ri[256];
    __shared__ int   rp[256];
    __shared__ float outv[KNN_];
    __shared__ int   outi[KNN_];

    const int TOT = 256 * KNN_;
    for (int r = 0; r < KNN_; r++) {
        float bv = -INFINITY; int bi = 0x7fffffff; int bp = -1;
        for (int t = tid; t < TOT; t += 256) {
            float v = sv[t]; int ii = si[t];
            if (v > bv || (v == bv && ii < bi)) { bv = v; bi = ii; bp = t; }
        }
        rv[tid] = bv; ri[tid] = bi; rp[tid] = bp;
        __syncthreads();
        for (int s = 128; s > 0; s >>= 1) {
            if (tid < s) {
                float v2 = rv[tid + s]; int i2 = ri[tid + s];
                if (v2 > rv[tid] || (v2 == rv[tid] && i2 < ri[tid])) {
                    rv[tid] = v2; ri[tid] = i2; rp[tid] = rp[tid + s];
                }
            }
            __syncthreads();
        }
        if (tid == 0) {
            outv[r] = rv[0]; outi[r] = ri[0];
            sv[rp[0]] = -INFINITY;
        }
        __syncthreads();
    }

    if (tid == 0) {
        float s = 0.f;
#pragma unroll
        for (int r = 0; r < KNN_; r++) s += outv[r];
        float inv = 1.f / fmaxf(s, 1.f);
#pragma unroll
        for (int r = 0; r < KNN_; r++) {
            g_nidx[row * KNN_ + r] = outi[r];
            g_nval[row * KNN_ + r] = outv[r] * inv;
        }
    }
}

// ---------------- sparse aggregation (+ bf16 split) ----------------
__global__ void agg_kernel()
{
    int row = blockIdx.x;
    int tid = threadIdx.x;                  // 256 == H_
    float acc = 0.f;
#pragma unroll
    for (int r = 0; r < KNN_; r++) {
        float w = g_nval[row * KNN_ + r];
        int   n = g_nidx[row * KNN_ + r];
        acc += w * g_h2[(size_t)n * H_ + tid];
    }
    g_agg[row * H_ + tid] = acc;
    bf16 hb = __float2bfloat16_rn(acc);
    g_ag_hi[row * H_ + tid] = hb;
    g_ag_lo[row * H_ + tid] = __float2bfloat16_rn(acc - __bfloat162float(hb));
}

// ---------------- weight transpose + split (tiled, coalesced both ways) ----------------
// W: [256, N] row-major -> hi/lo: [N, 256]
__global__ void wsplit_kernel(const float* __restrict__ W, int N, bf16* __restrict__ hi,
                              bf16* __restrict__ lo)
{
    __shared__ float t[32][33];
    const int n0 = blockIdx.x * 32;
    const int k0 = blockIdx.y * 32;
    const int tx = threadIdx.x;              // 32
    const int ty = threadIdx.y;              // 8
#pragma unroll
    for (int i = ty; i < 32; i += 8)
        t[i][tx] = W[(size_t)(k0 + i) * N + n0 + tx];
    __syncthreads();
#pragma unroll
    for (int i = ty; i < 32; i += 8) {
        float v = t[tx][i];                  // = W[k0+tx][n0+i]
        bf16 hb = __float2bfloat16_rn(v);
        hi[(size_t)(n0 + i) * 256 + k0 + tx] = hb;
        lo[(size_t)(n0 + i) * 256 + k0 + tx] = __float2bfloat16_rn(v - __bfloat162float(hb));
    }
}

// ---------------- tiny precompute ----------------
__global__ void precompute_kernel(const float* __restrict__ bn_g, const float* __restrict__ bn_b,
                                  const float* __restrict__ bn_m, const float* __restrict__ bn_v,
                                  const float* __restrict__ t_w1, const float* __restrict__ t_b1,
                                  const float* __restrict__ t_w2, const float* __restrict__ t_b2,
                                  const float* __restrict__ gate_w, const float* __restrict__ gate_b,
                                  const float* __restrict__ sde_w1, const float* __restrict__ sde_b1)
{
    int b = blockIdx.x;
    int j = threadIdx.x;
    if (b == 0) {
        float s = bn_g[j] * rsqrtf(bn_v[j] + 1e-5f);
        g_bnscale[j] = s;
        g_bnshift[j] = bn_b[j] - bn_m[j] * s;
    } else if (b <= NL_) {
        int l = b - 1;
        float t = 0.5f * (float)l;
        __shared__ float te[TD_];
        __shared__ float te2[H_];
        if (j < TD_) te[j] = fmaxf(t * t_w1[l * TD_ + j] + t_b1[l * TD_ + j], 0.f);
        __syncthreads();
        float acc = t_b2[l * H_ + j];
#pragma unroll
        for (int k = 0; k < TD_; k++) acc += te[k] * t_w2[l * TD_ * H_ + k * H_ + j];
        te2[j] = acc;
        __syncthreads();
        float c = gate_b[l * H_ + j];
        const float* W = gate_w + (size_t)l * 2 * H_ * H_ + (size_t)H_ * H_;
        for (int k = 0; k < H_; k++) c += te2[k] * W[k * H_ + j];
        g_gatec[l * H_ + j] = c;
    } else {
        int s = b - 1 - NL_;
        float ts = (float)s * 0.1f;
        g_sdebias[s * H_ + j] = sde_b1[j] + ts * sde_w1[H_ * H_ + j];
    }
}

// ---------------- host ----------------
static inline void launch_mma(const bf16* Ahi, const bf16* Alo, const bf16* Bhi, const bf16* Blo,
                              float* C, int Ntot, int ep, int mirror,
                              const float* p1 = nullptr, const float* p2 = nullptr,
                              const float* p3 = nullptr, float alpha = 0.f,
                              bf16* Chi = nullptr, bf16* Clo = nullptr)
{
    dim3 grid(Ntot / 128, NN_ / 128);
    mma_gemm<<<grid, 512, MG_SMEM>>>(Ahi, Alo, Bhi, Blo, C, Ntot, ep, mirror,
                                     p1, p2, p3, alpha, Chi, Clo);
}
static inline void launch_wsplit(const float* W, int N, bf16* hi, bf16* lo)
{
    dim3 grid(N / 32, 8);
    wsplit_kernel<<<grid, dim3(32, 8)>>>(W, N, hi, lo);
}

extern "C" void kernel_launch(void* const* d_in, const int* in_sizes, int n_in,
                              void* d_out, int out_size)
{
    const float* x       = (const float*)d_in[0];
    const float* enc_w1  = (const float*)d_in[1];
    const float* enc_b1  = (const float*)d_in[2];
    const float* enc_w2  = (const float*)d_in[3];
    const float* enc_b2  = (const float*)d_in[4];
    const float* bn_g    = (const float*)d_in[5];
    const float* bn_b    = (const float*)d_in[6];
    const float* bn_m    = (const float*)d_in[7];
    const float* bn_v    = (const float*)d_in[8];
    const float* node_w  = (const float*)d_in[9];
    const float* node_b  = (const float*)d_in[10];
    const float* t_w1    = (const float*)d_in[11];
    const float* t_b1    = (const float*)d_in[12];
    const float* t_w2    = (const float*)d_in[13];
    const float* t_b2    = (const float*)d_in[14];
    const float* gate_w  = (const float*)d_in[15];
    const float* gate_b  = (const float*)d_in[16];
    const float* sde_w1  = (const float*)d_in[17];
    const float* sde_b1  = (const float*)d_in[18];
    const float* sde_w2  = (const float*)d_in[19];
    const float* sde_b2  = (const float*)d_in[20];
    const float* sde_w3  = (const float*)d_in[21];
    const float* sde_b3  = (const float*)d_in[22];
    const float* dec_w1  = (const float*)d_in[23];
    const float* dec_b1  = (const float*)d_in[24];
    const float* dec_w2  = (const float*)d_in[25];
    const float* dec_b2  = (const float*)d_in[26];
    float* out = (float*)d_out;

    cudaFuncSetAttribute(mma_gemm, cudaFuncAttributeMaxDynamicSharedMemorySize, MG_SMEM);

    float *sim, *h, *h2, *hn, *agg, *d1, *d2, *bns, *bnsh, *gatec, *sdeb;
    bf16 *hhi, *hlo, *h2hi, *h2lo, *hnhi, *hnlo, *aghi, *aglo, *d1hi, *d1lo, *d2hi, *d2lo, *whi, *wlo;
    cudaGetSymbolAddress((void**)&sim,   g_sim);
    cudaGetSymbolAddress((void**)&h,     g_h);
    cudaGetSymbolAddress((void**)&h2,    g_h2);
    cudaGetSymbolAddress((void**)&hn,    g_hn);
    cudaGetSymbolAddress((void**)&agg,   g_agg);
    cudaGetSymbolAddress((void**)&d1,    g_d1);
    cudaGetSymbolAddress((void**)&d2,    g_d2);
    cudaGetSymbolAddress((void**)&bns,   g_bnscale);
    cudaGetSymbolAddress((void**)&bnsh,  g_bnshift);
    cudaGetSymbolAddress((void**)&gatec, g_gatec);
    cudaGetSymbolAddress((void**)&sdeb,  g_sdebias);
    cudaGetSymbolAddress((void**)&hhi,  g_h_hi);  cudaGetSymbolAddress((void**)&hlo,  g_h_lo);
    cudaGetSymbolAddress((void**)&h2hi, g_h2_hi); cudaGetSymbolAddress((void**)&h2lo, g_h2_lo);
    cudaGetSymbolAddress((void**)&hnhi, g_hn_hi); cudaGetSymbolAddress((void**)&hnlo, g_hn_lo);
    cudaGetSymbolAddress((void**)&aghi, g_ag_hi); cudaGetSymbolAddress((void**)&aglo, g_ag_lo);
    cudaGetSymbolAddress((void**)&d1hi, g_d1_hi); cudaGetSymbolAddress((void**)&d1lo, g_d1_lo);
    cudaGetSymbolAddress((void**)&d2hi, g_d2_hi); cudaGetSymbolAddress((void**)&d2lo, g_d2_lo);
    cudaGetSymbolAddress((void**)&whi, g_w_hi);   cudaGetSymbolAddress((void**)&wlo, g_w_lo);

    // Launch order chosen so ncu (-s 5 -c 1) profiles the 6th launch = enc2 mma_gemm.
    // (1) precompute
    precompute_kernel<<<1 + NL_ + NSTEPS_, 256>>>(bn_g, bn_b, bn_m, bn_v,
                                                  t_w1, t_b1, t_w2, t_b2,
                                                  gate_w, gate_b, sde_w1, sde_b1);
    // (2) wsplit enc2
    launch_wsplit(enc_w2, 256, whi + 0 * WSLOT, wlo + 0 * WSLOT);
    // (3) enc1 SIMT (K=83), splits only (h2 fp32 dead)
    {
        dim3 grid((H_ + BN - 1) / BN, (NN_ + BM - 1) / BM);
        gemm_kernel<<<grid, 256>>>(x, enc_w1, nullptr, NN_, H_, DIN_, H_, 1, enc_b1, h2hi, h2lo);
    }
    // (4,5) two wsplits
    launch_wsplit(node_w,           256, whi + 1 * WSLOT, wlo + 1 * WSLOT);
    launch_wsplit(node_w + H_ * H_, 256, whi + 2 * WSLOT, wlo + 2 * WSLOT);
    // (6) enc2 mma  <-- ncu target
    launch_mma(h2hi, h2lo, whi + 0 * WSLOT, wlo + 0 * WSLOT, h, 256, /*ep=*/2, 0,
               enc_b2, bns, bnsh, 0.f, hhi, hlo);
    // remaining wsplits
    launch_wsplit(gate_w,               256, whi + 3 * WSLOT, wlo + 3 * WSLOT);
    launch_wsplit(gate_w + 2 * H_ * H_, 256, whi + 4 * WSLOT, wlo + 4 * WSLOT);
    launch_wsplit(sde_w1, 256, whi + 5 * WSLOT, wlo + 5 * WSLOT);
    launch_wsplit(sde_w2, 256, whi + 6 * WSLOT, wlo + 6 * WSLOT);
    launch_wsplit(sde_w3, 256, whi + 7 * WSLOT, wlo + 7 * WSLOT);
    launch_wsplit(dec_w1, 128, whi + 8 * WSLOT, wlo + 8 * WSLOT);

    // kNN graph (sim is symmetric: lower-triangle blocks + mirrored writes)
    rownorm_kernel<<<NN_, 256>>>();
    launch_mma(hnhi, hnlo, hnhi, hnlo, sim, NN_, /*ep=*/0, 1);
    topk_kernel<<<NN_, 256>>>();

    // temporal gated graph conv layers
    for (int l = 0; l < NL_; l++) {
        launch_mma(hhi, hlo, whi + (1 + l) * WSLOT, wlo + (1 + l) * WSLOT, h2, 256, /*ep=*/3, 0,
                   node_b + (size_t)l * H_);
        agg_kernel<<<NN_, 256>>>();
        launch_mma(aghi, aglo, whi + (3 + l) * WSLOT, wlo + (3 + l) * WSLOT, h, 256, /*ep=*/4, 0,
                   gatec + (size_t)l * H_, agg, h2, 0.f, hhi, hlo);
    }

    // SDE (drift-only Euler, 10 steps); d1/d2 fp32 stores are dead -> skipped
    const float dt = 0.1f;
    for (int s = 0; s < NSTEPS_; s++) {
        launch_mma(hhi, hlo, whi + 5 * WSLOT, wlo + 5 * WSLOT, nullptr, 256, /*ep=*/5, 0,
                   sdeb + (size_t)s * H_, nullptr, nullptr, 0.f, d1hi, d1lo);
        launch_mma(d1hi, d1lo, whi + 6 * WSLOT, wlo + 6 * WSLOT, nullptr, 256, /*ep=*/5, 0,
                   sde_b2, nullptr, nullptr, 0.f, d2hi, d2lo);
        launch_mma(d2hi, d2lo, whi + 7 * WSLOT, wlo + 7 * WSLOT, h, 256, /*ep=*/6, 0,
                   sde_b3, h, nullptr, dt, hhi, hlo);
    }

    // decoder: dec1 tensor (N=128), dec2 SIMT (K=128, N=34)
    launch_mma(hhi, hlo, whi + 8 * WSLOT, wlo + 8 * WSLOT, d1, 128, /*ep=*/1, 0, dec_b1);
    {
        dim3 grid((C_ + BN - 1) / BN, (NN_ + BM - 1) / BM);
        gemm_kernel<<<grid, 256>>>(d1, dec_w2, out, NN_, C_, H_ / 2, C_, 3, dec_b2, nullptr, nullptr);
    }
}

// round 8
// speedup vs baseline: 2.1994x; 1.0454x over previous
#include <cuda_runtime.h>
#include <cuda_bf16.h>
#include <cuda_fp16.h>
#include <math.h>
#include <stdint.h>

// ---------------- problem constants ----------------
#define NN_   8192
#define DIN_  83
#define H_    256
#define C_    34
#define TD_   16
#define NL_   2
#define KNN_  11
#define NSTEPS_ 10

typedef __half hf;

// ---------------- scratch (device globals; no allocation allowed) ----------------
__device__ float g_sim[(size_t)NN_ * NN_];          // 256 MB
__device__ float g_h  [NN_ * H_];
__device__ float g_h2 [NN_ * H_];
__device__ float g_hn [NN_ * H_];
__device__ float g_agg[NN_ * H_];
__device__ float g_d1 [NN_ * H_];
__device__ float g_d2 [NN_ * H_];
__device__ int   g_nidx[NN_ * KNN_];
__device__ float g_nval[NN_ * KNN_];
__device__ float g_bnscale[H_];
__device__ float g_bnshift[H_];
__device__ float g_gatec[NL_ * H_];
__device__ float g_sdebias[NSTEPS_ * H_];

// fp16 split copies of activations ([M,256] row-major hi/lo)
__device__ hf g_h_hi [NN_ * H_],  g_h_lo [NN_ * H_];
__device__ hf g_h2_hi[NN_ * H_],  g_h2_lo[NN_ * H_];
__device__ hf g_hn_hi[NN_ * H_],  g_hn_lo[NN_ * H_];
__device__ hf g_ag_hi[NN_ * H_],  g_ag_lo[NN_ * H_];
__device__ hf g_d1_hi[NN_ * H_],  g_d1_lo[NN_ * H_];
__device__ hf g_d2_hi[NN_ * H_],  g_d2_lo[NN_ * H_];

// transposed+split weights, [N,256] K-major; 9 slots of 64K elems
#define WSLOT 65536
__device__ hf g_w_hi[9 * WSLOT];
__device__ hf g_w_lo[9 * WSLOT];

// ================= helpers =================
__device__ __forceinline__ uint32_t smem_u32(const void* p) {
    uint32_t a;
    asm("{ .reg .u64 t; cvta.to.shared.u64 t, %1; cvt.u32.u64 %0, t; }" : "=r"(a) : "l"(p));
    return a;
}
__device__ __forceinline__ void ldsm4(uint32_t* r, uint32_t addr) {
    asm volatile("ldmatrix.sync.aligned.m8n8.x4.shared.b16 {%0,%1,%2,%3}, [%4];"
                 : "=r"(r[0]), "=r"(r[1]), "=r"(r[2]), "=r"(r[3]) : "r"(addr));
}
__device__ __forceinline__ void mma16816(float* d, const uint32_t* a, uint32_t b0, uint32_t b1) {
    asm volatile("mma.sync.aligned.m16n8k16.row.col.f32.f16.f16.f32 "
                 "{%0,%1,%2,%3}, {%4,%5,%6,%7}, {%8,%9}, {%0,%1,%2,%3};"
                 : "+f"(d[0]), "+f"(d[1]), "+f"(d[2]), "+f"(d[3])
                 : "r"(a[0]), "r"(a[1]), "r"(a[2]), "r"(a[3]), "r"(b0), "r"(b1));
}
__device__ __forceinline__ float fast_tanh(float x) {
    float ax = fabsf(x);
    float t = __expf(-2.f * ax);
    float r = __fdividef(1.f - t, 1.f + t);
    return copysignf(r, x);
}
__device__ __forceinline__ float fast_sigmoid(float x) {
    return __fdividef(1.f, 1.f + __expf(-x));
}
__device__ __forceinline__ void split2(float y0, float y1, hf* hi, hf* lo) {
    hf h0 = __float2half_rn(y0);
    hf h1 = __float2half_rn(y1);
    __half2 hp; hp.x = h0; hp.y = h1;
    __half2 lp;
    lp.x = __float2half_rn(y0 - __half2float(h0));
    lp.y = __float2half_rn(y1 - __half2float(h1));
    *(__half2*)hi = hp;
    *(__half2*)lo = lp;
}

// ================= tensor-core split-fp16 GEMM (mma.sync, cp.async pipelined) =================
// C[M=8192, Ntot] = (Ahi+Alo) @ (Bhi+Blo)^T, 3 split terms (AhBh+AhBl+AlBh), fp32 accum.
// fp16 split: representation err 2^-22, dropped AlBl term 2^-24.
// CTA tile 128x128, 512 threads / 16 warps, warp tile 32x32.
// K chunked 8 x 32, cp.async double buffered.
// mirror=1 (A==B symmetric): lower-triangle blocks only; off-diagonal writes
// the transposed tile too (smem staged).
// C may be nullptr (skip fp32 store; splits only).
// Epilogues: 0 y=z; 1 relu(z+p1); 2 relu(z+p1)*p2+p3; 3 z+p1;
//            4 gate; 5 tanh(z+p1); 6 p2[i,n]+tanh(z+p1)*alpha.

#define TILE_B   8192                    // 128 rows * 32 hf * 2B
#define BUF_B    (4 * TILE_B)            // Ah,Al,Bh,Bl
#define MG_SMEM  (2 * BUF_B)             // 64 KB double buffered

__device__ __forceinline__ void cpa_tile(const hf* __restrict__ src, int r0, int k0,
                                         char* __restrict__ dst, int tid)
{
    int row = tid >> 2;                      // 0..127
    int seg = tid & 3;                       // 0..3 (16B each)
    const void* gp = src + (size_t)(r0 + row) * 256 + k0 + seg * 8;
    uint32_t off = (uint32_t)row * 64u + (uint32_t)((seg ^ ((row >> 1) & 3)) << 4);
    uint32_t sa = smem_u32(dst + off);
    asm volatile("cp.async.cg.shared.global [%0], [%1], 16;" :: "r"(sa), "l"(gp));
}

__global__ __launch_bounds__(512) void mma_gemm(
    const hf* __restrict__ Ahi, const hf* __restrict__ Alo,
    const hf* __restrict__ Bhi, const hf* __restrict__ Blo,
    float* __restrict__ C, int Ntot, int ep, int mirror,
    const float* __restrict__ p1, const float* __restrict__ p2,
    const float* __restrict__ p3, float alpha,
    hf* __restrict__ Chi, hf* __restrict__ Clo)
{
    const int bn0 = blockIdx.x * 128;
    const int bm0 = blockIdx.y * 128;
    if (mirror && bn0 > bm0) return;            // symmetric: lower triangle only

    extern __shared__ char smem[];
    char* bufp[2] = {smem, smem + BUF_B};

    const int tid  = threadIdx.x;
    const int wid  = tid >> 5;
    const int lane = tid & 31;
    const int warp_m = wid & 3;                 // rows  [warp_m*32, +32)
    const int warp_n = wid >> 2;                // cols  [warp_n*32, +32)

    float acc[2][4][4];
#pragma unroll
    for (int i = 0; i < 2; i++)
#pragma unroll
        for (int j = 0; j < 4; j++)
#pragma unroll
            for (int q = 0; q < 4; q++) acc[i][j][q] = 0.f;

    const int lrow  = lane & 15;
    const int lhalf = lane >> 4;

    // prologue: chunk 0 into buf 0
    cpa_tile(Ahi, bm0, 0, bufp[0] + 0 * TILE_B, tid);
    cpa_tile(Alo, bm0, 0, bufp[0] + 1 * TILE_B, tid);
    cpa_tile(Bhi, bn0, 0, bufp[0] + 2 * TILE_B, tid);
    cpa_tile(Blo, bn0, 0, bufp[0] + 3 * TILE_B, tid);
    asm volatile("cp.async.commit_group;" ::: "memory");

    int buf = 0;
    for (int chunk = 0; chunk < 8; chunk++) {
        if (chunk + 1 < 8) {
            const int k1 = (chunk + 1) * 32;
            char* nb = bufp[buf ^ 1];
            cpa_tile(Ahi, bm0, k1, nb + 0 * TILE_B, tid);
            cpa_tile(Alo, bm0, k1, nb + 1 * TILE_B, tid);
            cpa_tile(Bhi, bn0, k1, nb + 2 * TILE_B, tid);
            cpa_tile(Blo, bn0, k1, nb + 3 * TILE_B, tid);
            asm volatile("cp.async.commit_group;" ::: "memory");
            asm volatile("cp.async.wait_group 1;" ::: "memory");
        } else {
            asm volatile("cp.async.wait_group 0;" ::: "memory");
        }
        __syncthreads();

        const uint32_t sAh_b = smem_u32(bufp[buf] + 0 * TILE_B);
        const uint32_t sAl_b = smem_u32(bufp[buf] + 1 * TILE_B);
        const uint32_t sBh_b = smem_u32(bufp[buf] + 2 * TILE_B);
        const uint32_t sBl_b = smem_u32(bufp[buf] + 3 * TILE_B);

#pragma unroll
        for (int kk = 0; kk < 2; kk++) {
            const int segq = kk * 2 + lhalf;

            uint32_t aH[2][4], aL[2][4], bH[2][4], bL[2][4];
#pragma unroll
            for (int mt = 0; mt < 2; mt++) {
                int row = warp_m * 32 + mt * 16 + lrow;
                uint32_t off = (uint32_t)row * 64u + (uint32_t)((segq ^ ((row >> 1) & 3)) << 4);
                ldsm4(aH[mt], sAh_b + off);
                ldsm4(aL[mt], sAl_b + off);
            }
#pragma unroll
            for (int gg = 0; gg < 2; gg++) {
                int row = warp_n * 32 + gg * 16 + lrow;
                uint32_t off = (uint32_t)row * 64u + (uint32_t)((segq ^ ((row >> 1) & 3)) << 4);
                ldsm4(bH[gg], sBh_b + off);
                ldsm4(bL[gg], sBl_b + off);
            }

            // term-outer ordering: each acc reused at distance 8 MMAs
#define DO_TERM(Af, Bf)                                                        \
            _Pragma("unroll")                                                  \
            for (int mt = 0; mt < 2; mt++)                                     \
                _Pragma("unroll")                                              \
                for (int gg = 0; gg < 2; gg++) {                               \
                    mma16816(acc[mt][2 * gg + 0], Af[mt], Bf[gg][0], Bf[gg][2]); \
                    mma16816(acc[mt][2 * gg + 1], Af[mt], Bf[gg][1], Bf[gg][3]); \
                }
            DO_TERM(aH, bH)
            DO_TERM(aH, bL)
            DO_TERM(aL, bH)
#undef DO_TERM
        }
        __syncthreads();
        buf ^= 1;
    }

    // ---- epilogue ----
    auto epi = [&](float z, int gr, int gc) -> float {
        if (ep == 0) return z;
        if (ep == 1) return fmaxf(z + p1[gc], 0.f);
        if (ep == 2) return fmaxf(z + p1[gc], 0.f) * p2[gc] + p3[gc];
        if (ep == 3) return z + p1[gc];
        if (ep == 4) {
            float g = fast_sigmoid(z + p1[gc]);
            float a = p2[(size_t)gr * Ntot + gc];
            float hh = p3[(size_t)gr * Ntot + gc];
            return fmaxf(g * a + (1.f - g) * hh, 0.f);
        }
        if (ep == 5) return fast_tanh(z + p1[gc]);
        return p2[(size_t)gr * Ntot + gc] + fast_tanh(z + p1[gc]) * alpha;  // 6
    };

#pragma unroll
    for (int mt = 0; mt < 2; mt++) {
#pragma unroll
        for (int half = 0; half < 2; half++) {
            int gr = bm0 + warp_m * 32 + mt * 16 + (lane >> 2) + half * 8;
#pragma unroll
            for (int nt = 0; nt < 4; nt++) {
                int gc = bn0 + warp_n * 32 + nt * 8 + (lane & 3) * 2;
                float y0 = epi(acc[mt][nt][half * 2 + 0], gr, gc);
                float y1 = epi(acc[mt][nt][half * 2 + 1], gr, gc + 1);
                if (C) {
                    float2 o; o.x = y0; o.y = y1;
                    *(float2*)(C + (size_t)gr * Ntot + gc) = o;
                }
                if (Chi) {
                    split2(y0, y1, Chi + (size_t)gr * 256 + gc, Clo + (size_t)gr * 256 + gc);
                }
            }
        }
    }

    // ---- mirror write (symmetric sim): C[bn0+j, bm0+i] = acc[i][j], smem-staged ----
    if (mirror && bm0 != bn0) {
        float* ts = (float*)smem;     // 32 x 132 floats per pass = 16.9 KB
#pragma unroll 1
        for (int p = 0; p < 4; p++) {
            __syncthreads();
            if (warp_n == p) {
#pragma unroll
                for (int mt = 0; mt < 2; mt++)
#pragma unroll
                    for (int half = 0; half < 2; half++) {
                        int grl = warp_m * 32 + mt * 16 + (lane >> 2) + half * 8;
#pragma unroll
                        for (int nt = 0; nt < 4; nt++) {
                            int gcl = nt * 8 + (lane & 3) * 2;     // 0..31 within group
                            ts[(gcl + 0) * 132 + grl] = acc[mt][nt][half * 2 + 0];
                            ts[(gcl + 1) * 132 + grl] = acc[mt][nt][half * 2 + 1];
                        }
                    }
            }
            __syncthreads();
            // write 32 rows x 128 cols, coalesced float4
#pragma unroll
            for (int u = 0; u < 2; u++) {
                int i = tid + u * 512;           // 0..1023 float4 segments
                int j = i >> 5;                  // row 0..31
                int q = i & 31;                  // float4 col 0..31
                float4 v;
                v.x = ts[j * 132 + q * 4 + 0];
                v.y = ts[j * 132 + q * 4 + 1];
                v.z = ts[j * 132 + q * 4 + 2];
                v.w = ts[j * 132 + q * 4 + 3];
                *(float4*)(C + (size_t)(bn0 + p * 32 + j) * Ntot + bm0 + q * 4) = v;
            }
        }
    }
}

// ================= SIMT fp32 GEMM (odd shapes: enc1 K=83, dec2 N=34) =================
#define BM 128
#define BN 128
#define BK 8

__global__ __launch_bounds__(256) void gemm_kernel(
    const float* __restrict__ A, const float* __restrict__ B, float* __restrict__ C,
    int M, int N, int K, int ldb, int ep,
    const float* __restrict__ p1, hf* __restrict__ Chi, hf* __restrict__ Clo)
{
    __shared__ float As[2][BK][BM + 4];
    __shared__ float Bs[2][BK][BN + 4];

    const int tid = threadIdx.x;
    const int tx  = tid & 15;
    const int ty  = tid >> 4;
    const int bn0 = blockIdx.x * BN;
    const int bm0 = blockIdx.y * BM;

    float acc[8][8];
#pragma unroll
    for (int i = 0; i < 8; i++)
#pragma unroll
        for (int j = 0; j < 8; j++) acc[i][j] = 0.f;

    const int aRow = tid >> 1;
    const int aK   = (tid & 1) * 4;
    const int bRow = tid >> 5;
    const int bN   = (tid & 31) * 4;

    float ra[4], rb[4];
    const int ktiles = (K + BK - 1) / BK;

#define LOAD_AB(kt) do {                                                       \
        int k0_ = (kt) * BK;                                                   \
        int gr_ = bm0 + aRow, gk_ = k0_ + aK;                                  \
        _Pragma("unroll")                                                      \
        for (int j_ = 0; j_ < 4; j_++)                                         \
            ra[j_] = (gr_ < M && gk_ + j_ < K) ? A[(size_t)gr_ * K + gk_ + j_] : 0.f; \
        int gk2_ = k0_ + bRow, gn_ = bn0 + bN;                                 \
        _Pragma("unroll")                                                      \
        for (int j_ = 0; j_ < 4; j_++)                                         \
            rb[j_] = (gk2_ < K && gn_ + j_ < N) ? B[(size_t)gk2_ * ldb + gn_ + j_] : 0.f; \
    } while (0)

#define STS_AB2(buf) do {                                                      \
        _Pragma("unroll")                                                      \
        for (int j_ = 0; j_ < 4; j_++) As[buf][aK + j_][aRow] = ra[j_];        \
        _Pragma("unroll")                                                      \
        for (int j_ = 0; j_ < 4; j_++) Bs[buf][bRow][bN + j_] = rb[j_];        \
    } while (0)

    LOAD_AB(0);
    STS_AB2(0);
    __syncthreads();

    int cur = 0;
    for (int kt = 0; kt < ktiles; kt++) {
        const int hasNext = (kt + 1 < ktiles);
        if (hasNext) LOAD_AB(kt + 1);
#pragma unroll
        for (int kk = 0; kk < BK; kk++) {
            const float* as = As[cur][kk];
            const float* bs = Bs[cur][kk];
            float4 A0 = *(const float4*)(as + ty * 4);
            float4 A1 = *(const float4*)(as + 64 + ty * 4);
            float4 B0 = *(const float4*)(bs + tx * 4);
            float4 B1 = *(const float4*)(bs + 64 + tx * 4);
            float av[8] = {A0.x, A0.y, A0.z, A0.w, A1.x, A1.y, A1.z, A1.w};
            float bv[8] = {B0.x, B0.y, B0.z, B0.w, B1.x, B1.y, B1.z, B1.w};
#pragma unroll
            for (int i = 0; i < 8; i++)
#pragma unroll
                for (int j = 0; j < 8; j++)
                    acc[i][j] = fmaf(av[i], bv[j], acc[i][j]);
        }
        if (hasNext) { STS_AB2(cur ^ 1); __syncthreads(); cur ^= 1; }
    }

#pragma unroll
    for (int i = 0; i < 8; i++) {
        int gr = bm0 + ((i < 4) ? (ty * 4 + i) : (64 + ty * 4 + (i - 4)));
        if (gr >= M) continue;
#pragma unroll
        for (int j = 0; j < 8; j++) {
            int gc = bn0 + ((j < 4) ? (tx * 4 + j) : (64 + tx * 4 + (j - 4)));
            if (gc >= N) continue;
            float z = acc[i][j];
            float y;
            if (ep == 1) y = fmaxf(z + p1[gc], 0.f);
            else if (ep == 3) y = z + p1[gc];
            else y = z;
            if (C) C[(size_t)gr * N + gc] = y;
            if (Chi) {
                hf hb = __float2half_rn(y);
                Chi[(size_t)gr * 256 + gc] = hb;
                Clo[(size_t)gr * 256 + gc] = __float2half_rn(y - __half2float(hb));
            }
        }
    }
}

// ---------------- row-normalize h -> hn (+ fp16 split) ----------------
__global__ void rownorm_kernel()
{
    int row = blockIdx.x;
    int tid = threadIdx.x;                   // 256 == H_
    float v = g_h[row * H_ + tid];
    float s = v * v;
#pragma unroll
    for (int o = 16; o > 0; o >>= 1) s += __shfl_xor_sync(0xffffffff, s, o);
    __shared__ float ws[8];
    if ((tid & 31) == 0) ws[tid >> 5] = s;
    __syncthreads();
    if (tid < 8) {
        float t = ws[tid];
#pragma unroll
        for (int o = 4; o > 0; o >>= 1) t += __shfl_xor_sync(0xff, t, o);
        if (tid == 0) ws[0] = t;
    }
    __syncthreads();
    float denom = fmaxf(sqrtf(ws[0]), 1e-12f);
    float y = v / denom;
    g_hn[row * H_ + tid] = y;
    hf hb = __float2half_rn(y);
    g_hn_hi[row * H_ + tid] = hb;
    g_hn_lo[row * H_ + tid] = __float2half_rn(y - __half2float(hb));
}

// ---------------- per-row top-k over sim + adjacency normalize ----------------
__global__ void topk_kernel()
{
    const int row = blockIdx.x;
    const int tid = threadIdx.x;
    const float* srow = g_sim + (size_t)row * NN_;

    float lv[KNN_];
    int   li[KNN_];
#pragma unroll
    for (int r = 0; r < KNN_; r++) { lv[r] = -INFINITY; li[r] = 0x7fffffff; }

    for (int j = tid; j < NN_; j += 256) {
        float v = srow[j];
        if (v > lv[KNN_ - 1]) {
            int p = KNN_ - 1;
            while (p > 0 && v > lv[p - 1]) { lv[p] = lv[p - 1]; li[p] = li[p - 1]; p--; }
            lv[p] = v; li[p] = j;
        }
    }

    __shared__ float sv[256 * KNN_];
    __shared__ int   si[256 * KNN_];
#pragma unroll
    for (int r = 0; r < KNN_; r++) { sv[tid * KNN_ + r] = lv[r]; si[tid * KNN_ + r] = li[r]; }
    __syncthreads();

    __shared__ float rv[256];
    __shared__ int   ri[256];
    __shared__ int   rp[256];
    __shared__ float outv[KNN_];
    __shared__ int   outi[KNN_];

    const int TOT = 256 * KNN_;
    for (int r = 0; r < KNN_; r++) {
        float bv = -INFINITY; int bi = 0x7fffffff; int bp = -1;
        for (int t = tid; t < TOT; t += 256) {
            float v = sv[t]; int ii = si[t];
            if (v > bv || (v == bv && ii < bi)) { bv = v; bi = ii; bp = t; }
        }
        rv[tid] = bv; ri[tid] = bi; rp[tid] = bp;
        __syncthreads();
        for (int s = 128; s > 0; s >>= 1) {
            if (tid < s) {
                float v2 = rv[tid + s]; int i2 = ri[tid + s];
                if (v2 > rv[tid] || (v2 == rv[tid] && i2 < ri[tid])) {
                    rv[tid] = v2; ri[tid] = i2; rp[tid] = rp[tid + s];
                }
            }
            __syncthreads();
        }
        if (tid == 0) {
            outv[r] = rv[0]; outi[r] = ri[0];
            sv[rp[0]] = -INFINITY;
        }
        __syncthreads();
    }

    if (tid == 0) {
        float s = 0.f;
#pragma unroll
        for (int r = 0; r < KNN_; r++) s += outv[r];
        float inv = 1.f / fmaxf(s, 1.f);
#pragma unroll
        for (int r = 0; r < KNN_; r++) {
            g_nidx[row * KNN_ + r] = outi[r];
            g_nval[row * KNN_ + r] = outv[r] * inv;
        }
    }
}

// ---------------- sparse aggregation (+ fp16 split) ----------------
__global__ void agg_kernel()
{
    int row = blockIdx.x;
    int tid = threadIdx.x;                  // 256 == H_
    float acc = 0.f;
#pragma unroll
    for (int r = 0; r < KNN_; r++) {
        float w = g_nval[row * KNN_ + r];
        int   n = g_nidx[row * KNN_ + r];
        acc += w * g_h2[(size_t)n * H_ + tid];
    }
    g_agg[row * H_ + tid] = acc;
    hf hb = __float2half_rn(acc);
    g_ag_hi[row * H_ + tid] = hb;
    g_ag_lo[row * H_ + tid] = __float2half_rn(acc - __half2float(hb));
}

// ---------------- weight transpose + split (tiled, coalesced both ways) ----------------
// W: [256, N] row-major -> hi/lo: [N, 256]
__global__ void wsplit_kernel(const float* __restrict__ W, int N, hf* __restrict__ hi,
                              hf* __restrict__ lo)
{
    __shared__ float t[32][33];
    const int n0 = blockIdx.x * 32;
    const int k0 = blockIdx.y * 32;
    const int tx = threadIdx.x;              // 32
    const int ty = threadIdx.y;              // 8
#pragma unroll
    for (int i = ty; i < 32; i += 8)
        t[i][tx] = W[(size_t)(k0 + i) * N + n0 + tx];
    __syncthreads();
#pragma unroll
    for (int i = ty; i < 32; i += 8) {
        float v = t[tx][i];                  // = W[k0+tx][n0+i]
        hf hb = __float2half_rn(v);
        hi[(size_t)(n0 + i) * 256 + k0 + tx] = hb;
        lo[(size_t)(n0 + i) * 256 + k0 + tx] = __float2half_rn(v - __half2float(hb));
    }
}

// ---------------- tiny precompute ----------------
__global__ void precompute_kernel(const float* __restrict__ bn_g, const float* __restrict__ bn_b,
                                  const float* __restrict__ bn_m, const float* __restrict__ bn_v,
                                  const float* __restrict__ t_w1, const float* __restrict__ t_b1,
                                  const float* __restrict__ t_w2, const float* __restrict__ t_b2,
                                  const float* __restrict__ gate_w, const float* __restrict__ gate_b,
                                  const float* __restrict__ sde_w1, const float* __restrict__ sde_b1)
{
    int b = blockIdx.x;
    int j = threadIdx.x;
    if (b == 0) {
        float s = bn_g[j] * rsqrtf(bn_v[j] + 1e-5f);
        g_bnscale[j] = s;
        g_bnshift[j] = bn_b[j] - bn_m[j] * s;
    } else if (b <= NL_) {
        int l = b - 1;
        float t = 0.5f * (float)l;
        __shared__ float te[TD_];
        __shared__ float te2[H_];
        if (j < TD_) te[j] = fmaxf(t * t_w1[l * TD_ + j] + t_b1[l * TD_ + j], 0.f);
        __syncthreads();
        float acc = t_b2[l * H_ + j];
#pragma unroll
        for (int k = 0; k < TD_; k++) acc += te[k] * t_w2[l * TD_ * H_ + k * H_ + j];
        te2[j] = acc;
        __syncthreads();
        float c = gate_b[l * H_ + j];
        const float* W = gate_w + (size_t)l * 2 * H_ * H_ + (size_t)H_ * H_;
        for (int k = 0; k < H_; k++) c += te2[k] * W[k * H_ + j];
        g_gatec[l * H_ + j] = c;
    } else {
        int s = b - 1 - NL_;
        float ts = (float)s * 0.1f;
        g_sdebias[s * H_ + j] = sde_b1[j] + ts * sde_w1[H_ * H_ + j];
    }
}

// ---------------- host ----------------
static inline void launch_mma(const hf* Ahi, const hf* Alo, const hf* Bhi, const hf* Blo,
                              float* C, int Ntot, int ep, int mirror,
                              const float* p1 = nullptr, const float* p2 = nullptr,
                              const float* p3 = nullptr, float alpha = 0.f,
                              hf* Chi = nullptr, hf* Clo = nullptr)
{
    dim3 grid(Ntot / 128, NN_ / 128);
    mma_gemm<<<grid, 512, MG_SMEM>>>(Ahi, Alo, Bhi, Blo, C, Ntot, ep, mirror,
                                     p1, p2, p3, alpha, Chi, Clo);
}
static inline void launch_wsplit(const float* W, int N, hf* hi, hf* lo)
{
    dim3 grid(N / 32, 8);
    wsplit_kernel<<<grid, dim3(32, 8)>>>(W, N, hi, lo);
}

extern "C" void kernel_launch(void* const* d_in, const int* in_sizes, int n_in,
                              void* d_out, int out_size)
{
    const float* x       = (const float*)d_in[0];
    const float* enc_w1  = (const float*)d_in[1];
    const float* enc_b1  = (const float*)d_in[2];
    const float* enc_w2  = (const float*)d_in[3];
    const float* enc_b2  = (const float*)d_in[4];
    const float* bn_g    = (const float*)d_in[5];
    const float* bn_b    = (const float*)d_in[6];
    const float* bn_m    = (const float*)d_in[7];
    const float* bn_v    = (const float*)d_in[8];
    const float* node_w  = (const float*)d_in[9];
    const float* node_b  = (const float*)d_in[10];
    const float* t_w1    = (const float*)d_in[11];
    const float* t_b1    = (const float*)d_in[12];
    const float* t_w2    = (const float*)d_in[13];
    const float* t_b2    = (const float*)d_in[14];
    const float* gate_w  = (const float*)d_in[15];
    const float* gate_b  = (const float*)d_in[16];
    const float* sde_w1  = (const float*)d_in[17];
    const float* sde_b1  = (const float*)d_in[18];
    const float* sde_w2  = (const float*)d_in[19];
    const float* sde_b2  = (const float*)d_in[20];
    const float* sde_w3  = (const float*)d_in[21];
    const float* sde_b3  = (const float*)d_in[22];
    const float* dec_w1  = (const float*)d_in[23];
    const float* dec_b1  = (const float*)d_in[24];
    const float* dec_w2  = (const float*)d_in[25];
    const float* dec_b2  = (const float*)d_in[26];
    float* out = (float*)d_out;

    cudaFuncSetAttribute(mma_gemm, cudaFuncAttributeMaxDynamicSharedMemorySize, MG_SMEM);

    float *sim, *h, *h2, *hn, *agg, *d1, *d2, *bns, *bnsh, *gatec, *sdeb;
    hf *hhi, *hlo, *h2hi, *h2lo, *hnhi, *hnlo, *aghi, *aglo, *d1hi, *d1lo, *d2hi, *d2lo, *whi, *wlo;
    cudaGetSymbolAddress((void**)&sim,   g_sim);
    cudaGetSymbolAddress((void**)&h,     g_h);
    cudaGetSymbolAddress((void**)&h2,    g_h2);
    cudaGetSymbolAddress((void**)&hn,    g_hn);
    cudaGetSymbolAddress((void**)&agg,   g_agg);
    cudaGetSymbolAddress((void**)&d1,    g_d1);
    cudaGetSymbolAddress((void**)&d2,    g_d2);
    cudaGetSymbolAddress((void**)&bns,   g_bnscale);
    cudaGetSymbolAddress((void**)&bnsh,  g_bnshift);
    cudaGetSymbolAddress((void**)&gatec, g_gatec);
    cudaGetSymbolAddress((void**)&sdeb,  g_sdebias);
    cudaGetSymbolAddress((void**)&hhi,  g_h_hi);  cudaGetSymbolAddress((void**)&hlo,  g_h_lo);
    cudaGetSymbolAddress((void**)&h2hi, g_h2_hi); cudaGetSymbolAddress((void**)&h2lo, g_h2_lo);
    cudaGetSymbolAddress((void**)&hnhi, g_hn_hi); cudaGetSymbolAddress((void**)&hnlo, g_hn_lo);
    cudaGetSymbolAddress((void**)&aghi, g_ag_hi); cudaGetSymbolAddress((void**)&aglo, g_ag_lo);
    cudaGetSymbolAddress((void**)&d1hi, g_d1_hi); cudaGetSymbolAddress((void**)&d1lo, g_d1_lo);
    cudaGetSymbolAddress((void**)&d2hi, g_d2_hi); cudaGetSymbolAddress((void**)&d2lo, g_d2_lo);
    cudaGetSymbolAddress((void**)&whi, g_w_hi);   cudaGetSymbolAddress((void**)&wlo, g_w_lo);

    // Launch order: harness poison-memset is launch #1; put enc2 mma at our #5 so
    // ncu (-s 5 -c 1, capturing overall launch #6) profiles mma_gemm.
    // (our 1) precompute
    precompute_kernel<<<1 + NL_ + NSTEPS_, 256>>>(bn_g, bn_b, bn_m, bn_v,
                                                  t_w1, t_b1, t_w2, t_b2,
                                                  gate_w, gate_b, sde_w1, sde_b1);
    // (our 2) wsplit enc2
    launch_wsplit(enc_w2, 256, whi + 0 * WSLOT, wlo + 0 * WSLOT);
    // (our 3) enc1 SIMT (K=83), splits only
    {
        dim3 grid((H_ + BN - 1) / BN, (NN_ + BM - 1) / BM);
        gemm_kernel<<<grid, 256>>>(x, enc_w1, nullptr, NN_, H_, DIN_, H_, 1, enc_b1, h2hi, h2lo);
    }
    // (our 4) wsplit node0
    launch_wsplit(node_w, 256, whi + 1 * WSLOT, wlo + 1 * WSLOT);
    // (our 5) enc2 mma  <-- ncu target (overall #6)
    launch_mma(h2hi, h2lo, whi + 0 * WSLOT, wlo + 0 * WSLOT, h, 256, /*ep=*/2, 0,
               enc_b2, bns, bnsh, 0.f, hhi, hlo);
    // remaining wsplits
    launch_wsplit(node_w + H_ * H_,     256, whi + 2 * WSLOT, wlo + 2 * WSLOT);
    launch_wsplit(gate_w,               256, whi + 3 * WSLOT, wlo + 3 * WSLOT);
    launch_wsplit(gate_w + 2 * H_ * H_, 256, whi + 4 * WSLOT, wlo + 4 * WSLOT);
    launch_wsplit(sde_w1, 256, whi + 5 * WSLOT, wlo + 5 * WSLOT);
    launch_wsplit(sde_w2, 256, whi + 6 * WSLOT, wlo + 6 * WSLOT);
    launch_wsplit(sde_w3, 256, whi + 7 * WSLOT, wlo + 7 * WSLOT);
    launch_wsplit(dec_w1, 128, whi + 8 * WSLOT, wlo + 8 * WSLOT);

    // kNN graph (sim is symmetric: lower-triangle blocks + mirrored writes)
    rownorm_kernel<<<NN_, 256>>>();
    launch_mma(hnhi, hnlo, hnhi, hnlo, sim, NN_, /*ep=*/0, 1);
    topk_kernel<<<NN_, 256>>>();

    // temporal gated graph conv layers
    for (int l = 0; l < NL_; l++) {
        launch_mma(hhi, hlo, whi + (1 + l) * WSLOT, wlo + (1 + l) * WSLOT, h2, 256, /*ep=*/3, 0,
                   node_b + (size_t)l * H_);
        agg_kernel<<<NN_, 256>>>();
        launch_mma(aghi, aglo, whi + (3 + l) * WSLOT, wlo + (3 + l) * WSLOT, h, 256, /*ep=*/4, 0,
                   gatec + (size_t)l * H_, agg, h2, 0.f, hhi, hlo);
    }

    // SDE (drift-only Euler, 10 steps); d1/d2 fp32 stores are dead -> skipped
    const float dt = 0.1f;
    for (int s = 0; s < NSTEPS_; s++) {
        launch_mma(hhi, hlo, whi + 5 * WSLOT, wlo + 5 * WSLOT, nullptr, 256, /*ep=*/5, 0,
                   sdeb + (size_t)s * H_, nullptr, nullptr, 0.f, d1hi, d1lo);
        launch_mma(d1hi, d1lo, whi + 6 * WSLOT, wlo + 6 * WSLOT, nullptr, 256, /*ep=*/5, 0,
                   sde_b2, nullptr, nullptr, 0.f, d2hi, d2lo);
        launch_mma(d2hi, d2lo, whi + 7 * WSLOT, wlo + 7 * WSLOT, h, 256, /*ep=*/6, 0,
                   sde_b3, h, nullptr, dt, hhi, hlo);
    }

    // decoder: dec1 tensor (N=128), dec2 SIMT (K=128, N=34)
    launch_mma(hhi, hlo, whi + 8 * WSLOT, wlo + 8 * WSLOT, d1, 128, /*ep=*/1, 0, dec_b1);
    {
        dim3 grid((C_ + BN - 1) / BN, (NN_ + BM - 1) / BM);
        gemm_kernel<<<grid, 256>>>(d1, dec_w2, out, NN_, C_, H_ / 2, C_, 3, dec_b2, nullptr, nullptr);
    }
}

// round 9
// speedup vs baseline: 2.3320x; 1.0603x over previous
#include <cuda_runtime.h>
#include <cuda_bf16.h>
#include <cuda_fp16.h>
#include <math.h>
#include <stdint.h>

// ---------------- problem constants ----------------
#define NN_   8192
#define DIN_  83
#define H_    256
#define C_    34
#define TD_   16
#define NL_   2
#define KNN_  11
#define NSTEPS_ 10

typedef __half hf;

// ---------------- scratch (device globals; no allocation allowed) ----------------
__device__ float g_sim[(size_t)NN_ * NN_];          // 256 MB
__device__ float g_h  [NN_ * H_];
__device__ float g_h2 [NN_ * H_];
__device__ float g_hn [NN_ * H_];
__device__ float g_agg[NN_ * H_];
__device__ float g_d1 [NN_ * H_];
__device__ int   g_nidx[NN_ * KNN_];
__device__ float g_nval[NN_ * KNN_];
__device__ float g_bnscale[H_];
__device__ float g_bnshift[H_];
__device__ float g_gatec[NL_ * H_];
__device__ float g_sdebias[NSTEPS_ * H_];

// fp16 split copies of activations ([M,256] row-major hi/lo)
__device__ hf g_h_hi [NN_ * H_],  g_h_lo [NN_ * H_];
__device__ hf g_h2_hi[NN_ * H_],  g_h2_lo[NN_ * H_];
__device__ hf g_hn_hi[NN_ * H_],  g_hn_lo[NN_ * H_];
__device__ hf g_ag_hi[NN_ * H_],  g_ag_lo[NN_ * H_];

// transposed+split weights, [N,256] K-major; 9 slots of 64K elems
#define WSLOT 65536
__device__ hf g_w_hi[9 * WSLOT];
__device__ hf g_w_lo[9 * WSLOT];

// ================= helpers =================
__device__ __forceinline__ uint32_t smem_u32(const void* p) {
    uint32_t a;
    asm("{ .reg .u64 t; cvta.to.shared.u64 t, %1; cvt.u32.u64 %0, t; }" : "=r"(a) : "l"(p));
    return a;
}
__device__ __forceinline__ void ldsm4(uint32_t* r, uint32_t addr) {
    asm volatile("ldmatrix.sync.aligned.m8n8.x4.shared.b16 {%0,%1,%2,%3}, [%4];"
                 : "=r"(r[0]), "=r"(r[1]), "=r"(r[2]), "=r"(r[3]) : "r"(addr));
}
__device__ __forceinline__ void mma16816(float* d, const uint32_t* a, uint32_t b0, uint32_t b1) {
    asm volatile("mma.sync.aligned.m16n8k16.row.col.f32.f16.f16.f32 "
                 "{%0,%1,%2,%3}, {%4,%5,%6,%7}, {%8,%9}, {%0,%1,%2,%3};"
                 : "+f"(d[0]), "+f"(d[1]), "+f"(d[2]), "+f"(d[3])
                 : "r"(a[0]), "r"(a[1]), "r"(a[2]), "r"(a[3]), "r"(b0), "r"(b1));
}
__device__ __forceinline__ float fast_tanh(float x) {
    float ax = fabsf(x);
    float t = __expf(-2.f * ax);
    float r = __fdividef(1.f - t, 1.f + t);
    return copysignf(r, x);
}
__device__ __forceinline__ float fast_sigmoid(float x) {
    return __fdividef(1.f, 1.f + __expf(-x));
}
__device__ __forceinline__ void split2(float y0, float y1, hf* hi, hf* lo) {
    hf h0 = __float2half_rn(y0);
    hf h1 = __float2half_rn(y1);
    __half2 hp; hp.x = h0; hp.y = h1;
    __half2 lp;
    lp.x = __float2half_rn(y0 - __half2float(h0));
    lp.y = __float2half_rn(y1 - __half2float(h1));
    *(__half2*)hi = hp;
    *(__half2*)lo = lp;
}
#define CP_ASYNC16(sa, gp) \
    asm volatile("cp.async.cg.shared.global [%0], [%1], 16;" :: "r"(sa), "l"(gp))
#define CP_COMMIT() asm volatile("cp.async.commit_group;" ::: "memory")
#define CP_WAIT(n)  asm volatile("cp.async.wait_group %0;" :: "n"(n) : "memory")

// ================= tensor-core split-fp16 GEMM (mma.sync, cp.async pipelined) =================
// C[M=8192, Ntot] = (Ahi+Alo) @ (Bhi+Blo)^T, 3 split terms (AhBh+AhBl+AlBh), fp32 accum.
// CTA tile 128x128, 512 threads / 16 warps, warp tile 32x32.
// K chunked 8 x 32, cp.async double buffered.
// mirror=1 (A==B symmetric): lower-triangle blocks only; off-diagonal writes
// the transposed tile too (smem staged). C may be nullptr.
// Epilogues: 0 y=z; 1 relu(z+p1); 2 relu(z+p1)*p2+p3; 3 z+p1;
//            4 gate; 5 tanh(z+p1); 6 p2[i,n]+tanh(z+p1)*alpha.

#define TILE_B   8192                    // 128 rows * 32 hf * 2B
#define BUF_B    (4 * TILE_B)            // Ah,Al,Bh,Bl
#define MG_SMEM  (2 * BUF_B)             // 64 KB double buffered

__device__ __forceinline__ void cpa_tile(const hf* __restrict__ src, int r0, int k0,
                                         char* __restrict__ dst, int tid)
{
    int row = tid >> 2;                      // 0..127
    int seg = tid & 3;                       // 0..3 (16B each)
    const void* gp = src + (size_t)(r0 + row) * 256 + k0 + seg * 8;
    uint32_t off = (uint32_t)row * 64u + (uint32_t)((seg ^ ((row >> 1) & 3)) << 4);
    uint32_t sa = smem_u32(dst + off);
    CP_ASYNC16(sa, gp);
}

__global__ __launch_bounds__(512) void mma_gemm(
    const hf* __restrict__ Ahi, const hf* __restrict__ Alo,
    const hf* __restrict__ Bhi, const hf* __restrict__ Blo,
    float* __restrict__ C, int Ntot, int ep, int mirror,
    const float* __restrict__ p1, const float* __restrict__ p2,
    const float* __restrict__ p3, float alpha,
    hf* __restrict__ Chi, hf* __restrict__ Clo)
{
    const int bn0 = blockIdx.x * 128;
    const int bm0 = blockIdx.y * 128;
    if (mirror && bn0 > bm0) return;            // symmetric: lower triangle only

    extern __shared__ char smem[];
    char* bufp[2] = {smem, smem + BUF_B};

    const int tid  = threadIdx.x;
    const int wid  = tid >> 5;
    const int lane = tid & 31;
    const int warp_m = wid & 3;                 // rows  [warp_m*32, +32)
    const int warp_n = wid >> 2;                // cols  [warp_n*32, +32)

    float acc[2][4][4];
#pragma unroll
    for (int i = 0; i < 2; i++)
#pragma unroll
        for (int j = 0; j < 4; j++)
#pragma unroll
            for (int q = 0; q < 4; q++) acc[i][j][q] = 0.f;

    const int lrow  = lane & 15;
    const int lhalf = lane >> 4;

    cpa_tile(Ahi, bm0, 0, bufp[0] + 0 * TILE_B, tid);
    cpa_tile(Alo, bm0, 0, bufp[0] + 1 * TILE_B, tid);
    cpa_tile(Bhi, bn0, 0, bufp[0] + 2 * TILE_B, tid);
    cpa_tile(Blo, bn0, 0, bufp[0] + 3 * TILE_B, tid);
    CP_COMMIT();

    int buf = 0;
    for (int chunk = 0; chunk < 8; chunk++) {
        if (chunk + 1 < 8) {
            const int k1 = (chunk + 1) * 32;
            char* nb = bufp[buf ^ 1];
            cpa_tile(Ahi, bm0, k1, nb + 0 * TILE_B, tid);
            cpa_tile(Alo, bm0, k1, nb + 1 * TILE_B, tid);
            cpa_tile(Bhi, bn0, k1, nb + 2 * TILE_B, tid);
            cpa_tile(Blo, bn0, k1, nb + 3 * TILE_B, tid);
            CP_COMMIT();
            CP_WAIT(1);
        } else {
            CP_WAIT(0);
        }
        __syncthreads();

        const uint32_t sAh_b = smem_u32(bufp[buf] + 0 * TILE_B);
        const uint32_t sAl_b = smem_u32(bufp[buf] + 1 * TILE_B);
        const uint32_t sBh_b = smem_u32(bufp[buf] + 2 * TILE_B);
        const uint32_t sBl_b = smem_u32(bufp[buf] + 3 * TILE_B);

#pragma unroll
        for (int kk = 0; kk < 2; kk++) {
            const int segq = kk * 2 + lhalf;

            uint32_t aH[2][4], aL[2][4], bH[2][4], bL[2][4];
#pragma unroll
            for (int mt = 0; mt < 2; mt++) {
                int row = warp_m * 32 + mt * 16 + lrow;
                uint32_t off = (uint32_t)row * 64u + (uint32_t)((segq ^ ((row >> 1) & 3)) << 4);
                ldsm4(aH[mt], sAh_b + off);
                ldsm4(aL[mt], sAl_b + off);
            }
#pragma unroll
            for (int gg = 0; gg < 2; gg++) {
                int row = warp_n * 32 + gg * 16 + lrow;
                uint32_t off = (uint32_t)row * 64u + (uint32_t)((segq ^ ((row >> 1) & 3)) << 4);
                ldsm4(bH[gg], sBh_b + off);
                ldsm4(bL[gg], sBl_b + off);
            }

#define DO_TERM(Af, Bf)                                                        \
            _Pragma("unroll")                                                  \
            for (int mt = 0; mt < 2; mt++)                                     \
                _Pragma("unroll")                                              \
                for (int gg = 0; gg < 2; gg++) {                               \
                    mma16816(acc[mt][2 * gg + 0], Af[mt], Bf[gg][0], Bf[gg][2]); \
                    mma16816(acc[mt][2 * gg + 1], Af[mt], Bf[gg][1], Bf[gg][3]); \
                }
            DO_TERM(aH, bH)
            DO_TERM(aH, bL)
            DO_TERM(aL, bH)
#undef DO_TERM
        }
        __syncthreads();
        buf ^= 1;
    }

    auto epi = [&](float z, int gr, int gc) -> float {
        if (ep == 0) return z;
        if (ep == 1) return fmaxf(z + p1[gc], 0.f);
        if (ep == 2) return fmaxf(z + p1[gc], 0.f) * p2[gc] + p3[gc];
        if (ep == 3) return z + p1[gc];
        if (ep == 4) {
            float g = fast_sigmoid(z + p1[gc]);
            float a = p2[(size_t)gr * Ntot + gc];
            float hh = p3[(size_t)gr * Ntot + gc];
            return fmaxf(g * a + (1.f - g) * hh, 0.f);
        }
        if (ep == 5) return fast_tanh(z + p1[gc]);
        return p2[(size_t)gr * Ntot + gc] + fast_tanh(z + p1[gc]) * alpha;  // 6
    };

#pragma unroll
    for (int mt = 0; mt < 2; mt++) {
#pragma unroll
        for (int half = 0; half < 2; half++) {
            int gr = bm0 + warp_m * 32 + mt * 16 + (lane >> 2) + half * 8;
#pragma unroll
            for (int nt = 0; nt < 4; nt++) {
                int gc = bn0 + warp_n * 32 + nt * 8 + (lane & 3) * 2;
                float y0 = epi(acc[mt][nt][half * 2 + 0], gr, gc);
                float y1 = epi(acc[mt][nt][half * 2 + 1], gr, gc + 1);
                if (C) {
                    float2 o; o.x = y0; o.y = y1;
                    *(float2*)(C + (size_t)gr * Ntot + gc) = o;
                }
                if (Chi) {
                    split2(y0, y1, Chi + (size_t)gr * 256 + gc, Clo + (size_t)gr * 256 + gc);
                }
            }
        }
    }

    // ---- mirror write (symmetric sim) ----
    if (mirror && bm0 != bn0) {
        float* ts = (float*)smem;
#pragma unroll 1
        for (int p = 0; p < 4; p++) {
            __syncthreads();
            if (warp_n == p) {
#pragma unroll
                for (int mt = 0; mt < 2; mt++)
#pragma unroll
                    for (int half = 0; half < 2; half++) {
                        int grl = warp_m * 32 + mt * 16 + (lane >> 2) + half * 8;
#pragma unroll
                        for (int nt = 0; nt < 4; nt++) {
                            int gcl = nt * 8 + (lane & 3) * 2;
                            ts[(gcl + 0) * 132 + grl] = acc[mt][nt][half * 2 + 0];
                            ts[(gcl + 1) * 132 + grl] = acc[mt][nt][half * 2 + 1];
                        }
                    }
            }
            __syncthreads();
#pragma unroll
            for (int u = 0; u < 2; u++) {
                int i = tid + u * 512;
                int j = i >> 5;
                int q = i & 31;
                float4 v;
                v.x = ts[j * 132 + q * 4 + 0];
                v.y = ts[j * 132 + q * 4 + 1];
                v.z = ts[j * 132 + q * 4 + 2];
                v.w = ts[j * 132 + q * 4 + 3];
                *(float4*)(C + (size_t)(bn0 + p * 32 + j) * Ntot + bm0 + q * 4) = v;
            }
        }
    }
}

// ================= fused persistent SDE kernel =================
// 10 Euler steps x 3 tanh layers, rows independent: 128 CTAs x 64 rows.
// h fp32 + u splits resident in smem; weights streamed from L2 (double buffered).
// Same arithmetic as the per-launch version (3-term fp16 split, fp32 accum, fast_tanh).

#define SDE_SH   0                       // float[64*256]   64 KB
#define SDE_UH   65536                   // hf, swizzled    32 KB
#define SDE_UL   (65536 + 32768)         // hf, swizzled    32 KB
#define SDE_W    131072                  // 2 x (hi16K+lo16K) = 64 KB
#define SDE_SMEM 196608

__device__ __forceinline__ void sde_wchunk(const hf* __restrict__ W, int k0,
                                           char* __restrict__ dst, int tid)
{
#pragma unroll
    for (int u = 0; u < 4; u++) {
        int i = tid + u * 256;               // 1024 segs: 256 rows x 4
        int row = i >> 2, seg = i & 3;
        const void* gp = W + (size_t)row * 256 + k0 + seg * 8;
        uint32_t off = (uint32_t)row * 64u + (uint32_t)((seg ^ ((row >> 1) & 3)) << 4);
        CP_ASYNC16(smem_u32(dst + off), gp);
    }
}

__global__ __launch_bounds__(256) void sde_fused(
    const hf* __restrict__ W1h, const hf* __restrict__ W1l,
    const hf* __restrict__ W2h, const hf* __restrict__ W2l,
    const hf* __restrict__ W3h, const hf* __restrict__ W3l,
    const float* __restrict__ sdeb, const float* __restrict__ b2,
    const float* __restrict__ b3,
    const float* __restrict__ hin,
    hf* __restrict__ hhi_g, hf* __restrict__ hlo_g)
{
    extern __shared__ char smem[];
    float* sh = (float*)(smem + SDE_SH);
    char* sUh = smem + SDE_UH;
    char* sUl = smem + SDE_UL;

    const int tid  = threadIdx.x;
    const int wid  = tid >> 5;
    const int lane = tid & 31;
    const int warp_m = wid & 1;              // 2 warps over m (32 rows)
    const int warp_n = wid >> 1;             // 4 warps over n (64 cols)
    const int r0 = blockIdx.x * 64;
    const int lrow  = lane & 15;
    const int lhalf = lane >> 4;

    // initial loads: sh (fp32 h) and sU (h splits, swizzled chunk layout)
#pragma unroll
    for (int u = 0; u < 16; u++) {
        int i = tid + u * 256;               // 4096 16B segs
        int row = i >> 6, c4 = i & 63;
        CP_ASYNC16(smem_u32(sh + row * 256 + c4 * 4),
                   (const void*)(hin + (size_t)(r0 + row) * 256 + c4 * 4));
    }
#pragma unroll
    for (int u = 0; u < 8; u++) {
        int i = tid + u * 256;               // 2048 segs: 64 rows x 32
        int row = i >> 5, s32 = i & 31;
        int chunk = s32 >> 2, seg = s32 & 3;
        uint32_t off = (uint32_t)chunk * 4096u + (uint32_t)row * 64u
                     + (uint32_t)((seg ^ ((row >> 1) & 3)) << 4);
        CP_ASYNC16(smem_u32(sUh + off), (const void*)(hhi_g + (size_t)(r0 + row) * 256 + s32 * 8));
        CP_ASYNC16(smem_u32(sUl + off), (const void*)(hlo_g + (size_t)(r0 + row) * 256 + s32 * 8));
    }
    CP_COMMIT();
    CP_WAIT(0);
    __syncthreads();

    for (int step = 0; step < NSTEPS_; step++) {
#pragma unroll 1
        for (int layer = 0; layer < 3; layer++) {
            const hf* Wh = (layer == 0) ? W1h : (layer == 1) ? W2h : W3h;
            const hf* Wl = (layer == 0) ? W1l : (layer == 1) ? W2l : W3l;
            const float* bias = (layer == 0) ? (sdeb + step * H_) : (layer == 1) ? b2 : b3;

            float acc[2][8][4];
#pragma unroll
            for (int i = 0; i < 2; i++)
#pragma unroll
                for (int j = 0; j < 8; j++)
#pragma unroll
                    for (int q = 0; q < 4; q++) acc[i][j][q] = 0.f;

            sde_wchunk(Wh, 0, smem + SDE_W, tid);
            sde_wchunk(Wl, 0, smem + SDE_W + 16384, tid);
            CP_COMMIT();
            int wb = 0;
#pragma unroll 1
            for (int kc = 0; kc < 8; kc++) {
                if (kc + 1 < 8) {
                    char* nb = smem + SDE_W + (wb ^ 1) * 32768;
                    sde_wchunk(Wh, (kc + 1) * 32, nb, tid);
                    sde_wchunk(Wl, (kc + 1) * 32, nb + 16384, tid);
                    CP_COMMIT();
                    CP_WAIT(1);
                } else {
                    CP_WAIT(0);
                }
                __syncthreads();

                const uint32_t sWh_b = smem_u32(smem + SDE_W + wb * 32768);
                const uint32_t sWl_b = sWh_b + 16384;
                const uint32_t sAh_b = smem_u32(sUh) + kc * 4096;
                const uint32_t sAl_b = smem_u32(sUl) + kc * 4096;

#pragma unroll
                for (int kk = 0; kk < 2; kk++) {
                    const int segq = kk * 2 + lhalf;
                    uint32_t aH[2][4], aL[2][4], bH[4][4], bL[4][4];
#pragma unroll
                    for (int mt = 0; mt < 2; mt++) {
                        int row = warp_m * 32 + mt * 16 + lrow;
                        uint32_t off = (uint32_t)row * 64u
                                     + (uint32_t)((segq ^ ((row >> 1) & 3)) << 4);
                        ldsm4(aH[mt], sAh_b + off);
                        ldsm4(aL[mt], sAl_b + off);
                    }
#pragma unroll
                    for (int gg = 0; gg < 4; gg++) {
                        int row = warp_n * 64 + gg * 16 + lrow;
                        uint32_t off = (uint32_t)row * 64u
                                     + (uint32_t)((segq ^ ((row >> 1) & 3)) << 4);
                        ldsm4(bH[gg], sWh_b + off);
                        ldsm4(bL[gg], sWl_b + off);
                    }
#define DO_TERM4(Af, Bf)                                                       \
                    _Pragma("unroll")                                          \
                    for (int mt = 0; mt < 2; mt++)                             \
                        _Pragma("unroll")                                      \
                        for (int gg = 0; gg < 4; gg++) {                       \
                            mma16816(acc[mt][2 * gg + 0], Af[mt], Bf[gg][0], Bf[gg][2]); \
                            mma16816(acc[mt][2 * gg + 1], Af[mt], Bf[gg][1], Bf[gg][3]); \
                        }
                    DO_TERM4(aH, bH)
                    DO_TERM4(aH, bL)
                    DO_TERM4(aL, bH)
#undef DO_TERM4
                }
                __syncthreads();
                wb ^= 1;
            }

            // epilogue: tanh (+ Euler on layer 2), write u splits (or final output)
            const bool lastL = (layer == 2);
            const bool fin = lastL && (step == NSTEPS_ - 1);
#pragma unroll
            for (int mt = 0; mt < 2; mt++) {
#pragma unroll
                for (int half = 0; half < 2; half++) {
                    int lr = warp_m * 32 + mt * 16 + (lane >> 2) + half * 8;
#pragma unroll
                    for (int nt = 0; nt < 8; nt++) {
                        int gc = warp_n * 64 + nt * 8 + (lane & 3) * 2;
                        float y0 = fast_tanh(acc[mt][nt][half * 2 + 0] + bias[gc]);
                        float y1 = fast_tanh(acc[mt][nt][half * 2 + 1] + bias[gc + 1]);
                        if (lastL) {
                            y0 = sh[lr * 256 + gc] + y0 * 0.1f;
                            y1 = sh[lr * 256 + gc + 1] + y1 * 0.1f;
                            if (!fin) {
                                sh[lr * 256 + gc] = y0;
                                sh[lr * 256 + gc + 1] = y1;
                            }
                        }
                        if (fin) {
                            split2(y0, y1, hhi_g + (size_t)(r0 + lr) * 256 + gc,
                                           hlo_g + (size_t)(r0 + lr) * 256 + gc);
                        } else {
                            int chunk = gc >> 5, k = gc & 31, seg = k >> 3;
                            uint32_t boff = (uint32_t)chunk * 4096u + (uint32_t)lr * 64u
                                          + (uint32_t)((seg ^ ((lr >> 1) & 3)) << 4)
                                          + (uint32_t)(k & 7) * 2u;
                            split2(y0, y1, (hf*)(sUh + boff), (hf*)(sUl + boff));
                        }
                    }
                }
            }
            __syncthreads();
        }
    }
}

// ================= SIMT fp32 GEMM (odd shapes: enc1 K=83, dec2 N=34) =================
#define BM 128
#define BN 128
#define BK 8

__global__ __launch_bounds__(256) void gemm_kernel(
    const float* __restrict__ A, const float* __restrict__ B, float* __restrict__ C,
    int M, int N, int K, int ldb, int ep,
    const float* __restrict__ p1, hf* __restrict__ Chi, hf* __restrict__ Clo)
{
    __shared__ float As[2][BK][BM + 4];
    __shared__ float Bs[2][BK][BN + 4];

    const int tid = threadIdx.x;
    const int tx  = tid & 15;
    const int ty  = tid >> 4;
    const int bn0 = blockIdx.x * BN;
    const int bm0 = blockIdx.y * BM;

    float acc[8][8];
#pragma unroll
    for (int i = 0; i < 8; i++)
#pragma unroll
        for (int j = 0; j < 8; j++) acc[i][j] = 0.f;

    const int aRow = tid >> 1;
    const int aK   = (tid & 1) * 4;
    const int bRow = tid >> 5;
    const int bN   = (tid & 31) * 4;

    float ra[4], rb[4];
    const int ktiles = (K + BK - 1) / BK;

#define LOAD_AB(kt) do {                                                       \
        int k0_ = (kt) * BK;                                                   \
        int gr_ = bm0 + aRow, gk_ = k0_ + aK;                                  \
        _Pragma("unroll")                                                      \
        for (int j_ = 0; j_ < 4; j_++)                                         \
            ra[j_] = (gr_ < M && gk_ + j_ < K) ? A[(size_t)gr_ * K + gk_ + j_] : 0.f; \
        int gk2_ = k0_ + bRow, gn_ = bn0 + bN;                                 \
        _Pragma("unroll")                                                      \
        for (int j_ = 0; j_ < 4; j_++)                                         \
            rb[j_] = (gk2_ < K && gn_ + j_ < N) ? B[(size_t)gk2_ * ldb + gn_ + j_] : 0.f; \
    } while (0)

#define STS_AB2(buf) do {                                                      \
        _Pragma("unroll")                                                      \
        for (int j_ = 0; j_ < 4; j_++) As[buf][aK + j_][aRow] = ra[j_];        \
        _Pragma("unroll")                                                      \
        for (int j_ = 0; j_ < 4; j_++) Bs[buf][bRow][bN + j_] = rb[j_];        \
    } while (0)

    LOAD_AB(0);
    STS_AB2(0);
    __syncthreads();

    int cur = 0;
    for (int kt = 0; kt < ktiles; kt++) {
        const int hasNext = (kt + 1 < ktiles);
        if (hasNext) LOAD_AB(kt + 1);
#pragma unroll
        for (int kk = 0; kk < BK; kk++) {
            const float* as = As[cur][kk];
            const float* bs = Bs[cur][kk];
            float4 A0 = *(const float4*)(as + ty * 4);
            float4 A1 = *(const float4*)(as + 64 + ty * 4);
            float4 B0 = *(const float4*)(bs + tx * 4);
            float4 B1 = *(const float4*)(bs + 64 + tx * 4);
            float av[8] = {A0.x, A0.y, A0.z, A0.w, A1.x, A1.y, A1.z, A1.w};
            float bv[8] = {B0.x, B0.y, B0.z, B0.w, B1.x, B1.y, B1.z, B1.w};
#pragma unroll
            for (int i = 0; i < 8; i++)
#pragma unroll
                for (int j = 0; j < 8; j++)
                    acc[i][j] = fmaf(av[i], bv[j], acc[i][j]);
        }
        if (hasNext) { STS_AB2(cur ^ 1); __syncthreads(); cur ^= 1; }
    }

#pragma unroll
    for (int i = 0; i < 8; i++) {
        int gr = bm0 + ((i < 4) ? (ty * 4 + i) : (64 + ty * 4 + (i - 4)));
        if (gr >= M) continue;
#pragma unroll
        for (int j = 0; j < 8; j++) {
            int gc = bn0 + ((j < 4) ? (tx * 4 + j) : (64 + tx * 4 + (j - 4)));
            if (gc >= N) continue;
            float z = acc[i][j];
            float y;
            if (ep == 1) y = fmaxf(z + p1[gc], 0.f);
            else if (ep == 3) y = z + p1[gc];
            else y = z;
            if (C) C[(size_t)gr * N + gc] = y;
            if (Chi) {
                hf hb = __float2half_rn(y);
                Chi[(size_t)gr * 256 + gc] = hb;
                Clo[(size_t)gr * 256 + gc] = __float2half_rn(y - __half2float(hb));
            }
        }
    }
}

// ---------------- row-normalize h -> hn (+ fp16 split) ----------------
__global__ void rownorm_kernel()
{
    int row = blockIdx.x;
    int tid = threadIdx.x;                   // 256 == H_
    float v = g_h[row * H_ + tid];
    float s = v * v;
#pragma unroll
    for (int o = 16; o > 0; o >>= 1) s += __shfl_xor_sync(0xffffffff, s, o);
    __shared__ float ws[8];
    if ((tid & 31) == 0) ws[tid >> 5] = s;
    __syncthreads();
    if (tid < 8) {
        float t = ws[tid];
#pragma unroll
        for (int o = 4; o > 0; o >>= 1) t += __shfl_xor_sync(0xff, t, o);
        if (tid == 0) ws[0] = t;
    }
    __syncthreads();
    float denom = fmaxf(sqrtf(ws[0]), 1e-12f);
    float y = v / denom;
    g_hn[row * H_ + tid] = y;
    hf hb = __float2half_rn(y);
    g_hn_hi[row * H_ + tid] = hb;
    g_hn_lo[row * H_ + tid] = __float2half_rn(y - __half2float(hb));
}

// ---------------- per-row top-k over sim + adjacency normalize ----------------
__global__ void topk_kernel()
{
    const int row = blockIdx.x;
    const int tid = threadIdx.x;
    const float* srow = g_sim + (size_t)row * NN_;

    float lv[KNN_];
    int   li[KNN_];
#pragma unroll
    for (int r = 0; r < KNN_; r++) { lv[r] = -INFINITY; li[r] = 0x7fffffff; }

    for (int j = tid; j < NN_; j += 256) {
        float v = srow[j];
        if (v > lv[KNN_ - 1]) {
            int p = KNN_ - 1;
            while (p > 0 && v > lv[p - 1]) { lv[p] = lv[p - 1]; li[p] = li[p - 1]; p--; }
            lv[p] = v; li[p] = j;
        }
    }

    __shared__ float sv[256 * KNN_];
    __shared__ int   si[256 * KNN_];
#pragma unroll
    for (int r = 0; r < KNN_; r++) { sv[tid * KNN_ + r] = lv[r]; si[tid * KNN_ + r] = li[r]; }
    __syncthreads();

    __shared__ float rv[256];
    __shared__ int   ri[256];
    __shared__ int   rp[256];
    __shared__ float outv[KNN_];
    __shared__ int   outi[KNN_];

    const int TOT = 256 * KNN_;
    for (int r = 0; r < KNN_; r++) {
        float bv = -INFINITY; int bi = 0x7fffffff; int bp = -1;
        for (int t = tid; t < TOT; t += 256) {
            float v = sv[t]; int ii = si[t];
            if (v > bv || (v == bv && ii < bi)) { bv = v; bi = ii; bp = t; }
        }
        rv[tid] = bv; ri[tid] = bi; rp[tid] = bp;
        __syncthreads();
        for (int s = 128; s > 0; s >>= 1) {
            if (tid < s) {
                float v2 = rv[tid + s]; int i2 = ri[tid + s];
                if (v2 > rv[tid] || (v2 == rv[tid] && i2 < ri[tid])) {
                    rv[tid] = v2; ri[tid] = i2; rp[tid] = rp[tid + s];
                }
            }
            __syncthreads();
        }
        if (tid == 0) {
            outv[r] = rv[0]; outi[r] = ri[0];
            sv[rp[0]] = -INFINITY;
        }
        __syncthreads();
    }

    if (tid == 0) {
        float s = 0.f;
#pragma unroll
        for (int r = 0; r < KNN_; r++) s += outv[r];
        float inv = 1.f / fmaxf(s, 1.f);
#pragma unroll
        for (int r = 0; r < KNN_; r++) {
            g_nidx[row * KNN_ + r] = outi[r];
            g_nval[row * KNN_ + r] = outv[r] * inv;
        }
    }
}

// ---------------- sparse aggregation (+ fp16 split) ----------------
__global__ void agg_kernel()
{
    int row = blockIdx.x;
    int tid = threadIdx.x;                  // 256 == H_
    float acc = 0.f;
#pragma unroll
    for (int r = 0; r < KNN_; r++) {
        float w = g_nval[row * KNN_ + r];
        int   n = g_nidx[row * KNN_ + r];
        acc += w * g_h2[(size_t)n * H_ + tid];
    }
    g_agg[row * H_ + tid] = acc;
    hf hb = __float2half_rn(acc);
    g_ag_hi[row * H_ + tid] = hb;
    g_ag_lo[row * H_ + tid] = __float2half_rn(acc - __half2float(hb));
}

// ---------------- weight transpose + split (tiled, coalesced both ways) ----------------
__global__ void wsplit_kernel(const float* __restrict__ W, int N, hf* __restrict__ hi,
                              hf* __restrict__ lo)
{
    __shared__ float t[32][33];
    const int n0 = blockIdx.x * 32;
    const int k0 = blockIdx.y * 32;
    const int tx = threadIdx.x;
    const int ty = threadIdx.y;
#pragma unroll
    for (int i = ty; i < 32; i += 8)
        t[i][tx] = W[(size_t)(k0 + i) * N + n0 + tx];
    __syncthreads();
#pragma unroll
    for (int i = ty; i < 32; i += 8) {
        float v = t[tx][i];
        hf hb = __float2half_rn(v);
        hi[(size_t)(n0 + i) * 256 + k0 + tx] = hb;
        lo[(size_t)(n0 + i) * 256 + k0 + tx] = __float2half_rn(v - __half2float(hb));
    }
}

// ---------------- tiny precompute ----------------
__global__ void precompute_kernel(const float* __restrict__ bn_g, const float* __restrict__ bn_b,
                                  const float* __restrict__ bn_m, const float* __restrict__ bn_v,
                                  const float* __restrict__ t_w1, const float* __restrict__ t_b1,
                                  const float* __restrict__ t_w2, const float* __restrict__ t_b2,
                                  const float* __restrict__ gate_w, const float* __restrict__ gate_b,
                                  const float* __restrict__ sde_w1, const float* __restrict__ sde_b1)
{
    int b = blockIdx.x;
    int j = threadIdx.x;
    if (b == 0) {
        float s = bn_g[j] * rsqrtf(bn_v[j] + 1e-5f);
        g_bnscale[j] = s;
        g_bnshift[j] = bn_b[j] - bn_m[j] * s;
    } else if (b <= NL_) {
        int l = b - 1;
        float t = 0.5f * (float)l;
        __shared__ float te[TD_];
        __shared__ float te2[H_];
        if (j < TD_) te[j] = fmaxf(t * t_w1[l * TD_ + j] + t_b1[l * TD_ + j], 0.f);
        __syncthreads();
        float acc = t_b2[l * H_ + j];
#pragma unroll
        for (int k = 0; k < TD_; k++) acc += te[k] * t_w2[l * TD_ * H_ + k * H_ + j];
        te2[j] = acc;
        __syncthreads();
        float c = gate_b[l * H_ + j];
        const float* W = gate_w + (size_t)l * 2 * H_ * H_ + (size_t)H_ * H_;
        for (int k = 0; k < H_; k++) c += te2[k] * W[k * H_ + j];
        g_gatec[l * H_ + j] = c;
    } else {
        int s = b - 1 - NL_;
        float ts = (float)s * 0.1f;
        g_sdebias[s * H_ + j] = sde_b1[j] + ts * sde_w1[H_ * H_ + j];
    }
}

// ---------------- host ----------------
static inline void launch_mma(const hf* Ahi, const hf* Alo, const hf* Bhi, const hf* Blo,
                              float* C, int Ntot, int ep, int mirror,
                              const float* p1 = nullptr, const float* p2 = nullptr,
                              const float* p3 = nullptr, float alpha = 0.f,
                              hf* Chi = nullptr, hf* Clo = nullptr)
{
    dim3 grid(Ntot / 128, NN_ / 128);
    mma_gemm<<<grid, 512, MG_SMEM>>>(Ahi, Alo, Bhi, Blo, C, Ntot, ep, mirror,
                                     p1, p2, p3, alpha, Chi, Clo);
}
static inline void launch_wsplit(const float* W, int N, hf* hi, hf* lo)
{
    dim3 grid(N / 32, 8);
    wsplit_kernel<<<grid, dim3(32, 8)>>>(W, N, hi, lo);
}

extern "C" void kernel_launch(void* const* d_in, const int* in_sizes, int n_in,
                              void* d_out, int out_size)
{
    const float* x       = (const float*)d_in[0];
    const float* enc_w1  = (const float*)d_in[1];
    const float* enc_b1  = (const float*)d_in[2];
    const float* enc_w2  = (const float*)d_in[3];
    const float* enc_b2  = (const float*)d_in[4];
    const float* bn_g    = (const float*)d_in[5];
    const float* bn_b    = (const float*)d_in[6];
    const float* bn_m    = (const float*)d_in[7];
    const float* bn_v    = (const float*)d_in[8];
    const float* node_w  = (const float*)d_in[9];
    const float* node_b  = (const float*)d_in[10];
    const float* t_w1    = (const float*)d_in[11];
    const float* t_b1    = (const float*)d_in[12];
    const float* t_w2    = (const float*)d_in[13];
    const float* t_b2    = (const float*)d_in[14];
    const float* gate_w  = (const float*)d_in[15];
    const float* gate_b  = (const float*)d_in[16];
    const float* sde_w1  = (const float*)d_in[17];
    const float* sde_b1  = (const float*)d_in[18];
    const float* sde_w2  = (const float*)d_in[19];
    const float* sde_b2  = (const float*)d_in[20];
    const float* sde_w3  = (const float*)d_in[21];
    const float* sde_b3  = (const float*)d_in[22];
    const float* dec_w1  = (const float*)d_in[23];
    const float* dec_b1  = (const float*)d_in[24];
    const float* dec_w2  = (const float*)d_in[25];
    const float* dec_b2  = (const float*)d_in[26];
    float* out = (float*)d_out;

    cudaFuncSetAttribute(mma_gemm, cudaFuncAttributeMaxDynamicSharedMemorySize, MG_SMEM);
    cudaFuncSetAttribute(sde_fused, cudaFuncAttributeMaxDynamicSharedMemorySize, SDE_SMEM);

    float *sim, *h, *h2, *hn, *agg, *d1, *bns, *bnsh, *gatec, *sdeb;
    hf *hhi, *hlo, *h2hi, *h2lo, *hnhi, *hnlo, *aghi, *aglo, *whi, *wlo;
    cudaGetSymbolAddress((void**)&sim,   g_sim);
    cudaGetSymbolAddress((void**)&h,     g_h);
    cudaGetSymbolAddress((void**)&h2,    g_h2);
    cudaGetSymbolAddress((void**)&hn,    g_hn);
    cudaGetSymbolAddress((void**)&agg,   g_agg);
    cudaGetSymbolAddress((void**)&d1,    g_d1);
    cudaGetSymbolAddress((void**)&bns,   g_bnscale);
    cudaGetSymbolAddress((void**)&bnsh,  g_bnshift);
    cudaGetSymbolAddress((void**)&gatec, g_gatec);
    cudaGetSymbolAddress((void**)&sdeb,  g_sdebias);
    cudaGetSymbolAddress((void**)&hhi,  g_h_hi);  cudaGetSymbolAddress((void**)&hlo,  g_h_lo);
    cudaGetSymbolAddress((void**)&h2hi, g_h2_hi); cudaGetSymbolAddress((void**)&h2lo, g_h2_lo);
    cudaGetSymbolAddress((void**)&hnhi, g_hn_hi); cudaGetSymbolAddress((void**)&hnlo, g_hn_lo);
    cudaGetSymbolAddress((void**)&aghi, g_ag_hi); cudaGetSymbolAddress((void**)&aglo, g_ag_lo);
    cudaGetSymbolAddress((void**)&whi, g_w_hi);   cudaGetSymbolAddress((void**)&wlo, g_w_lo);

    // ncu captures MY 6th launch (-s 5 -c 1) -> put enc2 mma there.
    // (1) precompute
    precompute_kernel<<<1 + NL_ + NSTEPS_, 256>>>(bn_g, bn_b, bn_m, bn_v,
                                                  t_w1, t_b1, t_w2, t_b2,
                                                  gate_w, gate_b, sde_w1, sde_b1);
    // (2) wsplit enc2
    launch_wsplit(enc_w2, 256, whi + 0 * WSLOT, wlo + 0 * WSLOT);
    // (3) enc1 SIMT (K=83), splits only
    {
        dim3 grid((H_ + BN - 1) / BN, (NN_ + BM - 1) / BM);
        gemm_kernel<<<grid, 256>>>(x, enc_w1, nullptr, NN_, H_, DIN_, H_, 1, enc_b1, h2hi, h2lo);
    }
    // (4,5) wsplits
    launch_wsplit(node_w,           256, whi + 1 * WSLOT, wlo + 1 * WSLOT);
    launch_wsplit(node_w + H_ * H_, 256, whi + 2 * WSLOT, wlo + 2 * WSLOT);
    // (6) enc2 mma  <-- ncu capture target
    launch_mma(h2hi, h2lo, whi + 0 * WSLOT, wlo + 0 * WSLOT, h, 256, /*ep=*/2, 0,
               enc_b2, bns, bnsh, 0.f, hhi, hlo);
    // remaining wsplits
    launch_wsplit(gate_w,               256, whi + 3 * WSLOT, wlo + 3 * WSLOT);
    launch_wsplit(gate_w + 2 * H_ * H_, 256, whi + 4 * WSLOT, wlo + 4 * WSLOT);
    launch_wsplit(sde_w1, 256, whi + 5 * WSLOT, wlo + 5 * WSLOT);
    launch_wsplit(sde_w2, 256, whi + 6 * WSLOT, wlo + 6 * WSLOT);
    launch_wsplit(sde_w3, 256, whi + 7 * WSLOT, wlo + 7 * WSLOT);
    launch_wsplit(dec_w1, 128, whi + 8 * WSLOT, wlo + 8 * WSLOT);

    // kNN graph (sim symmetric: lower-triangle + mirrored writes)
    rownorm_kernel<<<NN_, 256>>>();
    launch_mma(hnhi, hnlo, hnhi, hnlo, sim, NN_, /*ep=*/0, 1);
    topk_kernel<<<NN_, 256>>>();

    // temporal gated graph conv layers
    for (int l = 0; l < NL_; l++) {
        launch_mma(hhi, hlo, whi + (1 + l) * WSLOT, wlo + (1 + l) * WSLOT, h2, 256, /*ep=*/3, 0,
                   node_b + (size_t)l * H_);
        agg_kernel<<<NN_, 256>>>();
        launch_mma(aghi, aglo, whi + (3 + l) * WSLOT, wlo + (3 + l) * WSLOT, h, 256, /*ep=*/4, 0,
                   gatec + (size_t)l * H_, agg, h2, 0.f, hhi, hlo);
    }

    // SDE: single fused persistent kernel (128 CTAs x 64 rows, 10 steps x 3 layers)
    sde_fused<<<NN_ / 64, 256, SDE_SMEM>>>(
        whi + 5 * WSLOT, wlo + 5 * WSLOT,
        whi + 6 * WSLOT, wlo + 6 * WSLOT,
        whi + 7 * WSLOT, wlo + 7 * WSLOT,
        sdeb, sde_b2, sde_b3, h, hhi, hlo);

    // decoder: dec1 tensor (N=128), dec2 SIMT (K=128, N=34)
    launch_mma(hhi, hlo, whi + 8 * WSLOT, wlo + 8 * WSLOT, d1, 128, /*ep=*/1, 0, dec_b1);
    {
        dim3 grid((C_ + BN - 1) / BN, (NN_ + BM - 1) / BM);
        gemm_kernel<<<grid, 256>>>(d1, dec_w2, out, NN_, C_, H_ / 2, C_, 3, dec_b2, nullptr, nullptr);
    }
}

// round 10
// speedup vs baseline: 2.7980x; 1.1998x over previous
#include <cuda_runtime.h>
#include <cuda_bf16.h>
#include <cuda_fp16.h>
#include <math.h>
#include <stdint.h>

// ---------------- problem constants ----------------
#define NN_   8192
#define DIN_  83
#define H_    256
#define C_    34
#define TD_   16
#define NL_   2
#define KNN_  11
#define NSTEPS_ 10
#define NTILE 64
#define NCAND (NTILE * KNN_)            // 704 candidates per row

typedef __half hf;

// ---------------- scratch (device globals; no allocation allowed) ----------------
__device__ float g_h  [NN_ * H_];
__device__ float g_h2 [NN_ * H_];
__device__ float g_hn [NN_ * H_];
__device__ float g_agg[NN_ * H_];
__device__ float g_d1 [NN_ * H_];
__device__ int   g_nidx[NN_ * KNN_];
__device__ float g_nval[NN_ * KNN_];
__device__ float g_bnscale[H_];
__device__ float g_bnshift[H_];
__device__ float g_gatec[NL_ * H_];
__device__ float g_sdebias[NSTEPS_ * H_];
__device__ float g_cv[(size_t)NN_ * NCAND];       // topk candidate values (23 MB)
__device__ int   g_ci[(size_t)NN_ * NCAND];       // topk candidate indices (23 MB)

// fp16 split copies of activations ([M,256] row-major hi/lo)
__device__ hf g_h_hi [NN_ * H_],  g_h_lo [NN_ * H_];
__device__ hf g_h2_hi[NN_ * H_],  g_h2_lo[NN_ * H_];
__device__ hf g_hn_hi[NN_ * H_],  g_hn_lo[NN_ * H_];
__device__ hf g_ag_hi[NN_ * H_],  g_ag_lo[NN_ * H_];

// transposed+split weights, [N,256] K-major; 9 slots of 64K elems
#define WSLOT 65536
__device__ hf g_w_hi[9 * WSLOT];
__device__ hf g_w_lo[9 * WSLOT];

// ================= helpers =================
__device__ __forceinline__ uint32_t smem_u32(const void* p) {
    uint32_t a;
    asm("{ .reg .u64 t; cvta.to.shared.u64 t, %1; cvt.u32.u64 %0, t; }" : "=r"(a) : "l"(p));
    return a;
}
__device__ __forceinline__ void ldsm4(uint32_t* r, uint32_t addr) {
    asm volatile("ldmatrix.sync.aligned.m8n8.x4.shared.b16 {%0,%1,%2,%3}, [%4];"
                 : "=r"(r[0]), "=r"(r[1]), "=r"(r[2]), "=r"(r[3]) : "r"(addr));
}
__device__ __forceinline__ void mma16816(float* d, const uint32_t* a, uint32_t b0, uint32_t b1) {
    asm volatile("mma.sync.aligned.m16n8k16.row.col.f32.f16.f16.f32 "
                 "{%0,%1,%2,%3}, {%4,%5,%6,%7}, {%8,%9}, {%0,%1,%2,%3};"
                 : "+f"(d[0]), "+f"(d[1]), "+f"(d[2]), "+f"(d[3])
                 : "r"(a[0]), "r"(a[1]), "r"(a[2]), "r"(a[3]), "r"(b0), "r"(b1));
}
__device__ __forceinline__ float fast_tanh(float x) {
    float ax = fabsf(x);
    float t = __expf(-2.f * ax);
    float r = __fdividef(1.f - t, 1.f + t);
    return copysignf(r, x);
}
__device__ __forceinline__ float fast_sigmoid(float x) {
    return __fdividef(1.f, 1.f + __expf(-x));
}
__device__ __forceinline__ void split2(float y0, float y1, hf* hi, hf* lo) {
    hf h0 = __float2half_rn(y0);
    hf h1 = __float2half_rn(y1);
    __half2 hp; hp.x = h0; hp.y = h1;
    __half2 lp;
    lp.x = __float2half_rn(y0 - __half2float(h0));
    lp.y = __float2half_rn(y1 - __half2float(h1));
    *(__half2*)hi = hp;
    *(__half2*)lo = lp;
}
#define CP_ASYNC16(sa, gp) \
    asm volatile("cp.async.cg.shared.global [%0], [%1], 16;" :: "r"(sa), "l"(gp))
#define CP_COMMIT() asm volatile("cp.async.commit_group;" ::: "memory")
#define CP_WAIT(n)  asm volatile("cp.async.wait_group %0;" :: "n"(n) : "memory")

// ================= tensor-core split-fp16 GEMM (mma.sync, cp.async pipelined) =================
// C[M=8192, Ntot] = (Ahi+Alo) @ (Bhi+Blo)^T, 3 split terms, fp32 accum.
// CTA tile 128x128, 512 threads / 16 warps, warp tile 32x32. K = 8 x 32 chunks.
// cand=1 (sim mode, A==B symmetric): lower-triangle CTAs only; instead of storing
// C, stage the tile in smem and extract per-row top-11 candidates for the direct
// rows AND (via column scans) the mirrored rows. sim never touches DRAM.
// Epilogues: 0 y=z; 1 relu(z+p1); 2 relu(z+p1)*p2+p3; 3 z+p1;
//            4 gate; 5 tanh(z+p1); 6 p2[i,n]+tanh(z+p1)*alpha.

#define TILE_B   8192                    // 128 rows * 32 hf * 2B
#define BUF_B    (4 * TILE_B)            // Ah,Al,Bh,Bl
#define MG_SMEM  (128 * 133 * 4)         // 68096 B: max(load bufs 64K, cand staging)

__device__ __forceinline__ void cpa_tile(const hf* __restrict__ src, int r0, int k0,
                                         char* __restrict__ dst, int tid)
{
    int row = tid >> 2;                      // 0..127
    int seg = tid & 3;                       // 0..3 (16B each)
    const void* gp = src + (size_t)(r0 + row) * 256 + k0 + seg * 8;
    uint32_t off = (uint32_t)row * 64u + (uint32_t)((seg ^ ((row >> 1) & 3)) << 4);
    CP_ASYNC16(smem_u32(dst + off), gp);
}

__global__ __launch_bounds__(512) void mma_gemm(
    const hf* __restrict__ Ahi, const hf* __restrict__ Alo,
    const hf* __restrict__ Bhi, const hf* __restrict__ Blo,
    float* __restrict__ C, int Ntot, int ep, int cand,
    const float* __restrict__ p1, const float* __restrict__ p2,
    const float* __restrict__ p3, float alpha,
    hf* __restrict__ Chi, hf* __restrict__ Clo)
{
    const int bn0 = blockIdx.x * 128;
    const int bm0 = blockIdx.y * 128;
    if (cand && bn0 > bm0) return;              // symmetric: lower triangle only

    extern __shared__ char smem[];
    char* bufp[2] = {smem, smem + BUF_B};

    const int tid  = threadIdx.x;
    const int wid  = tid >> 5;
    const int lane = tid & 31;
    const int warp_m = wid & 3;                 // rows  [warp_m*32, +32)
    const int warp_n = wid >> 2;                // cols  [warp_n*32, +32)

    float acc[2][4][4];
#pragma unroll
    for (int i = 0; i < 2; i++)
#pragma unroll
        for (int j = 0; j < 4; j++)
#pragma unroll
            for (int q = 0; q < 4; q++) acc[i][j][q] = 0.f;

    const int lrow  = lane & 15;
    const int lhalf = lane >> 4;

    cpa_tile(Ahi, bm0, 0, bufp[0] + 0 * TILE_B, tid);
    cpa_tile(Alo, bm0, 0, bufp[0] + 1 * TILE_B, tid);
    cpa_tile(Bhi, bn0, 0, bufp[0] + 2 * TILE_B, tid);
    cpa_tile(Blo, bn0, 0, bufp[0] + 3 * TILE_B, tid);
    CP_COMMIT();

    int buf = 0;
    for (int chunk = 0; chunk < 8; chunk++) {
        if (chunk + 1 < 8) {
            const int k1 = (chunk + 1) * 32;
            char* nb = bufp[buf ^ 1];
            cpa_tile(Ahi, bm0, k1, nb + 0 * TILE_B, tid);
            cpa_tile(Alo, bm0, k1, nb + 1 * TILE_B, tid);
            cpa_tile(Bhi, bn0, k1, nb + 2 * TILE_B, tid);
            cpa_tile(Blo, bn0, k1, nb + 3 * TILE_B, tid);
            CP_COMMIT();
            CP_WAIT(1);
        } else {
            CP_WAIT(0);
        }
        __syncthreads();

        const uint32_t sAh_b = smem_u32(bufp[buf] + 0 * TILE_B);
        const uint32_t sAl_b = smem_u32(bufp[buf] + 1 * TILE_B);
        const uint32_t sBh_b = smem_u32(bufp[buf] + 2 * TILE_B);
        const uint32_t sBl_b = smem_u32(bufp[buf] + 3 * TILE_B);

#pragma unroll
        for (int kk = 0; kk < 2; kk++) {
            const int segq = kk * 2 + lhalf;

            uint32_t aH[2][4], aL[2][4], bH[2][4], bL[2][4];
#pragma unroll
            for (int mt = 0; mt < 2; mt++) {
                int row = warp_m * 32 + mt * 16 + lrow;
                uint32_t off = (uint32_t)row * 64u + (uint32_t)((segq ^ ((row >> 1) & 3)) << 4);
                ldsm4(aH[mt], sAh_b + off);
                ldsm4(aL[mt], sAl_b + off);
            }
#pragma unroll
            for (int gg = 0; gg < 2; gg++) {
                int row = warp_n * 32 + gg * 16 + lrow;
                uint32_t off = (uint32_t)row * 64u + (uint32_t)((segq ^ ((row >> 1) & 3)) << 4);
                ldsm4(bH[gg], sBh_b + off);
                ldsm4(bL[gg], sBl_b + off);
            }

#define DO_TERM(Af, Bf)                                                        \
            _Pragma("unroll")                                                  \
            for (int mt = 0; mt < 2; mt++)                                     \
                _Pragma("unroll")                                              \
                for (int gg = 0; gg < 2; gg++) {                               \
                    mma16816(acc[mt][2 * gg + 0], Af[mt], Bf[gg][0], Bf[gg][2]); \
                    mma16816(acc[mt][2 * gg + 1], Af[mt], Bf[gg][1], Bf[gg][3]); \
                }
            DO_TERM(aH, bH)
            DO_TERM(aH, bL)
            DO_TERM(aL, bH)
#undef DO_TERM
        }
        __syncthreads();
        buf ^= 1;
    }

    if (cand) {
        // ---- stage full 128x128 tile, pitch 133 (conflict-free row & col scans) ----
        float* ts = (float*)smem;
#pragma unroll
        for (int mt = 0; mt < 2; mt++)
#pragma unroll
            for (int half = 0; half < 2; half++) {
                int lr = warp_m * 32 + mt * 16 + (lane >> 2) + half * 8;
#pragma unroll
                for (int nt = 0; nt < 4; nt++) {
                    int lc = warp_n * 32 + nt * 8 + (lane & 3) * 2;
                    ts[lr * 133 + lc]     = acc[mt][nt][half * 2 + 0];
                    ts[lr * 133 + lc + 1] = acc[mt][nt][half * 2 + 1];
                }
            }
        __syncthreads();

        float lv[KNN_]; int li[KNN_];
        if (tid < 128) {
            // direct: row bm0+tid, cols bn0..+127
            int r = tid;
#pragma unroll
            for (int q = 0; q < KNN_; q++) { lv[q] = -INFINITY; li[q] = 0x7fffffff; }
            for (int c = 0; c < 128; c++) {
                float v = ts[r * 133 + c];
                if (v > lv[KNN_ - 1]) {
                    int p = KNN_ - 1;
                    while (p > 0 && v > lv[p - 1]) { lv[p] = lv[p - 1]; li[p] = li[p - 1]; p--; }
                    lv[p] = v; li[p] = bn0 + c;
                }
            }
            size_t base = (size_t)(bm0 + r) * NCAND + (size_t)(bn0 >> 7) * KNN_;
#pragma unroll
            for (int q = 0; q < KNN_; q++) { g_cv[base + q] = lv[q]; g_ci[base + q] = li[q]; }
        } else if (tid < 256 && bm0 != bn0) {
            // mirror: row bn0+c, cols bm0..+127 (column scan of staged tile)
            int c = tid - 128;
#pragma unroll
            for (int q = 0; q < KNN_; q++) { lv[q] = -INFINITY; li[q] = 0x7fffffff; }
            for (int r = 0; r < 128; r++) {
                float v = ts[r * 133 + c];
                if (v > lv[KNN_ - 1]) {
                    int p = KNN_ - 1;
                    while (p > 0 && v > lv[p - 1]) { lv[p] = lv[p - 1]; li[p] = li[p - 1]; p--; }
                    lv[p] = v; li[p] = bm0 + r;
                }
            }
            size_t base = (size_t)(bn0 + c) * NCAND + (size_t)(bm0 >> 7) * KNN_;
#pragma unroll
            for (int q = 0; q < KNN_; q++) { g_cv[base + q] = lv[q]; g_ci[base + q] = li[q]; }
        }
        return;
    }

    auto epi = [&](float z, int gr, int gc) -> float {
        if (ep == 0) return z;
        if (ep == 1) return fmaxf(z + p1[gc], 0.f);
        if (ep == 2) return fmaxf(z + p1[gc], 0.f) * p2[gc] + p3[gc];
        if (ep == 3) return z + p1[gc];
        if (ep == 4) {
            float g = fast_sigmoid(z + p1[gc]);
            float a = p2[(size_t)gr * Ntot + gc];
            float hh = p3[(size_t)gr * Ntot + gc];
            return fmaxf(g * a + (1.f - g) * hh, 0.f);
        }
        if (ep == 5) return fast_tanh(z + p1[gc]);
        return p2[(size_t)gr * Ntot + gc] + fast_tanh(z + p1[gc]) * alpha;  // 6
    };

#pragma unroll
    for (int mt = 0; mt < 2; mt++) {
#pragma unroll
        for (int half = 0; half < 2; half++) {
            int gr = bm0 + warp_m * 32 + mt * 16 + (lane >> 2) + half * 8;
#pragma unroll
            for (int nt = 0; nt < 4; nt++) {
                int gc = bn0 + warp_n * 32 + nt * 8 + (lane & 3) * 2;
                float y0 = epi(acc[mt][nt][half * 2 + 0], gr, gc);
                float y1 = epi(acc[mt][nt][half * 2 + 1], gr, gc + 1);
                if (C) {
                    float2 o; o.x = y0; o.y = y1;
                    *(float2*)(C + (size_t)gr * Ntot + gc) = o;
                }
                if (Chi) {
                    split2(y0, y1, Chi + (size_t)gr * 256 + gc, Clo + (size_t)gr * 256 + gc);
                }
            }
        }
    }
}

// ================= fused persistent SDE kernel =================
#define SDE_SH   0                       // float[64*256]   64 KB
#define SDE_UH   65536                   // hf, swizzled    32 KB
#define SDE_UL   (65536 + 32768)         // hf, swizzled    32 KB
#define SDE_W    131072                  // 2 x (hi16K+lo16K) = 64 KB
#define SDE_SMEM 196608

__device__ __forceinline__ void sde_wchunk(const hf* __restrict__ W, int k0,
                                           char* __restrict__ dst, int tid)
{
#pragma unroll
    for (int u = 0; u < 4; u++) {
        int i = tid + u * 256;
        int row = i >> 2, seg = i & 3;
        const void* gp = W + (size_t)row * 256 + k0 + seg * 8;
        uint32_t off = (uint32_t)row * 64u + (uint32_t)((seg ^ ((row >> 1) & 3)) << 4);
        CP_ASYNC16(smem_u32(dst + off), gp);
    }
}

__global__ __launch_bounds__(256) void sde_fused(
    const hf* __restrict__ W1h, const hf* __restrict__ W1l,
    const hf* __restrict__ W2h, const hf* __restrict__ W2l,
    const hf* __restrict__ W3h, const hf* __restrict__ W3l,
    const float* __restrict__ sdeb, const float* __restrict__ b2,
    const float* __restrict__ b3,
    const float* __restrict__ hin,
    hf* __restrict__ hhi_g, hf* __restrict__ hlo_g)
{
    extern __shared__ char smem[];
    float* sh = (float*)(smem + SDE_SH);
    char* sUh = smem + SDE_UH;
    char* sUl = smem + SDE_UL;

    const int tid  = threadIdx.x;
    const int wid  = tid >> 5;
    const int lane = tid & 31;
    const int warp_m = wid & 1;
    const int warp_n = wid >> 1;
    const int r0 = blockIdx.x * 64;
    const int lrow  = lane & 15;
    const int lhalf = lane >> 4;

#pragma unroll
    for (int u = 0; u < 16; u++) {
        int i = tid + u * 256;
        int row = i >> 6, c4 = i & 63;
        CP_ASYNC16(smem_u32(sh + row * 256 + c4 * 4),
                   (const void*)(hin + (size_t)(r0 + row) * 256 + c4 * 4));
    }
#pragma unroll
    for (int u = 0; u < 8; u++) {
        int i = tid + u * 256;
        int row = i >> 5, s32 = i & 31;
        int chunk = s32 >> 2, seg = s32 & 3;
        uint32_t off = (uint32_t)chunk * 4096u + (uint32_t)row * 64u
                     + (uint32_t)((seg ^ ((row >> 1) & 3)) << 4);
        CP_ASYNC16(smem_u32(sUh + off), (const void*)(hhi_g + (size_t)(r0 + row) * 256 + s32 * 8));
        CP_ASYNC16(smem_u32(sUl + off), (const void*)(hlo_g + (size_t)(r0 + row) * 256 + s32 * 8));
    }
    CP_COMMIT();
    CP_WAIT(0);
    __syncthreads();

    for (int step = 0; step < NSTEPS_; step++) {
#pragma unroll 1
        for (int layer = 0; layer < 3; layer++) {
            const hf* Wh = (layer == 0) ? W1h : (layer == 1) ? W2h : W3h;
            const hf* Wl = (layer == 0) ? W1l : (layer == 1) ? W2l : W3l;
            const float* bias = (layer == 0) ? (sdeb + step * H_) : (layer == 1) ? b2 : b3;

            float acc[2][8][4];
#pragma unroll
            for (int i = 0; i < 2; i++)
#pragma unroll
                for (int j = 0; j < 8; j++)
#pragma unroll
                    for (int q = 0; q < 4; q++) acc[i][j][q] = 0.f;

            sde_wchunk(Wh, 0, smem + SDE_W, tid);
            sde_wchunk(Wl, 0, smem + SDE_W + 16384, tid);
            CP_COMMIT();
            int wb = 0;
#pragma unroll 1
            for (int kc = 0; kc < 8; kc++) {
                if (kc + 1 < 8) {
                    char* nb = smem + SDE_W + (wb ^ 1) * 32768;
                    sde_wchunk(Wh, (kc + 1) * 32, nb, tid);
                    sde_wchunk(Wl, (kc + 1) * 32, nb + 16384, tid);
                    CP_COMMIT();
                    CP_WAIT(1);
                } else {
                    CP_WAIT(0);
                }
                __syncthreads();

                const uint32_t sWh_b = smem_u32(smem + SDE_W + wb * 32768);
                const uint32_t sWl_b = sWh_b + 16384;
                const uint32_t sAh_b = smem_u32(sUh) + kc * 4096;
                const uint32_t sAl_b = smem_u32(sUl) + kc * 4096;

#pragma unroll
                for (int kk = 0; kk < 2; kk++) {
                    const int segq = kk * 2 + lhalf;
                    uint32_t aH[2][4], aL[2][4], bH[4][4], bL[4][4];
#pragma unroll
                    for (int mt = 0; mt < 2; mt++) {
                        int row = warp_m * 32 + mt * 16 + lrow;
                        uint32_t off = (uint32_t)row * 64u
                                     + (uint32_t)((segq ^ ((row >> 1) & 3)) << 4);
                        ldsm4(aH[mt], sAh_b + off);
                        ldsm4(aL[mt], sAl_b + off);
                    }
#pragma unroll
                    for (int gg = 0; gg < 4; gg++) {
                        int row = warp_n * 64 + gg * 16 + lrow;
                        uint32_t off = (uint32_t)row * 64u
                                     + (uint32_t)((segq ^ ((row >> 1) & 3)) << 4);
                        ldsm4(bH[gg], sWh_b + off);
                        ldsm4(bL[gg], sWl_b + off);
                    }
#define DO_TERM4(Af, Bf)                                                       \
                    _Pragma("unroll")                                          \
                    for (int mt = 0; mt < 2; mt++)                             \
                        _Pragma("unroll")                                      \
                        for (int gg = 0; gg < 4; gg++) {                       \
                            mma16816(acc[mt][2 * gg + 0], Af[mt], Bf[gg][0], Bf[gg][2]); \
                            mma16816(acc[mt][2 * gg + 1], Af[mt], Bf[gg][1], Bf[gg][3]); \
                        }
                    DO_TERM4(aH, bH)
                    DO_TERM4(aH, bL)
                    DO_TERM4(aL, bH)
#undef DO_TERM4
                }
                __syncthreads();
                wb ^= 1;
            }

            const bool lastL = (layer == 2);
            const bool fin = lastL && (step == NSTEPS_ - 1);
#pragma unroll
            for (int mt = 0; mt < 2; mt++) {
#pragma unroll
                for (int half = 0; half < 2; half++) {
                    int lr = warp_m * 32 + mt * 16 + (lane >> 2) + half * 8;
#pragma unroll
                    for (int nt = 0; nt < 8; nt++) {
                        int gc = warp_n * 64 + nt * 8 + (lane & 3) * 2;
                        float y0 = fast_tanh(acc[mt][nt][half * 2 + 0] + bias[gc]);
                        float y1 = fast_tanh(acc[mt][nt][half * 2 + 1] + bias[gc + 1]);
                        if (lastL) {
                            y0 = sh[lr * 256 + gc] + y0 * 0.1f;
                            y1 = sh[lr * 256 + gc + 1] + y1 * 0.1f;
                            if (!fin) {
                                sh[lr * 256 + gc] = y0;
                                sh[lr * 256 + gc + 1] = y1;
                            }
                        }
                        if (fin) {
                            split2(y0, y1, hhi_g + (size_t)(r0 + lr) * 256 + gc,
                                           hlo_g + (size_t)(r0 + lr) * 256 + gc);
                        } else {
                            int chunk = gc >> 5, k = gc & 31, seg = k >> 3;
                            uint32_t boff = (uint32_t)chunk * 4096u + (uint32_t)lr * 64u
                                          + (uint32_t)((seg ^ ((lr >> 1) & 3)) << 4)
                                          + (uint32_t)(k & 7) * 2u;
                            split2(y0, y1, (hf*)(sUh + boff), (hf*)(sUl + boff));
                        }
                    }
                }
            }
            __syncthreads();
        }
    }
}

// ================= SIMT fp32 GEMM (odd shapes: enc1 K=83, dec2 N=34) =================
#define BM 128
#define BN 128
#define BK 8

__global__ __launch_bounds__(256) void gemm_kernel(
    const float* __restrict__ A, const float* __restrict__ B, float* __restrict__ C,
    int M, int N, int K, int ldb, int ep,
    const float* __restrict__ p1, hf* __restrict__ Chi, hf* __restrict__ Clo)
{
    __shared__ float As[2][BK][BM + 4];
    __shared__ float Bs[2][BK][BN + 4];

    const int tid = threadIdx.x;
    const int tx  = tid & 15;
    const int ty  = tid >> 4;
    const int bn0 = blockIdx.x * BN;
    const int bm0 = blockIdx.y * BM;

    float acc[8][8];
#pragma unroll
    for (int i = 0; i < 8; i++)
#pragma unroll
        for (int j = 0; j < 8; j++) acc[i][j] = 0.f;

    const int aRow = tid >> 1;
    const int aK   = (tid & 1) * 4;
    const int bRow = tid >> 5;
    const int bN   = (tid & 31) * 4;

    float ra[4], rb[4];
    const int ktiles = (K + BK - 1) / BK;

#define LOAD_AB(kt) do {                                                       \
        int k0_ = (kt) * BK;                                                   \
        int gr_ = bm0 + aRow, gk_ = k0_ + aK;                                  \
        _Pragma("unroll")                                                      \
        for (int j_ = 0; j_ < 4; j_++)                                         \
            ra[j_] = (gr_ < M && gk_ + j_ < K) ? A[(size_t)gr_ * K + gk_ + j_] : 0.f; \
        int gk2_ = k0_ + bRow, gn_ = bn0 + bN;                                 \
        _Pragma("unroll")                                                      \
        for (int j_ = 0; j_ < 4; j_++)                                         \
            rb[j_] = (gk2_ < K && gn_ + j_ < N) ? B[(size_t)gk2_ * ldb + gn_ + j_] : 0.f; \
    } while (0)

#define STS_AB2(buf) do {                                                      \
        _Pragma("unroll")                                                      \
        for (int j_ = 0; j_ < 4; j_++) As[buf][aK + j_][aRow] = ra[j_];        \
        _Pragma("unroll")                                                      \
        for (int j_ = 0; j_ < 4; j_++) Bs[buf][bRow][bN + j_] = rb[j_];        \
    } while (0)

    LOAD_AB(0);
    STS_AB2(0);
    __syncthreads();

    int cur = 0;
    for (int kt = 0; kt < ktiles; kt++) {
        const int hasNext = (kt + 1 < ktiles);
        if (hasNext) LOAD_AB(kt + 1);
#pragma unroll
        for (int kk = 0; kk < BK; kk++) {
            const float* as = As[cur][kk];
            const float* bs = Bs[cur][kk];
            float4 A0 = *(const float4*)(as + ty * 4);
            float4 A1 = *(const float4*)(as + 64 + ty * 4);
            float4 B0 = *(const float4*)(bs + tx * 4);
            float4 B1 = *(const float4*)(bs + 64 + tx * 4);
            float av[8] = {A0.x, A0.y, A0.z, A0.w, A1.x, A1.y, A1.z, A1.w};
            float bv[8] = {B0.x, B0.y, B0.z, B0.w, B1.x, B1.y, B1.z, B1.w};
#pragma unroll
            for (int i = 0; i < 8; i++)
#pragma unroll
                for (int j = 0; j < 8; j++)
                    acc[i][j] = fmaf(av[i], bv[j], acc[i][j]);
        }
        if (hasNext) { STS_AB2(cur ^ 1); __syncthreads(); cur ^= 1; }
    }

#pragma unroll
    for (int i = 0; i < 8; i++) {
        int gr = bm0 + ((i < 4) ? (ty * 4 + i) : (64 + ty * 4 + (i - 4)));
        if (gr >= M) continue;
#pragma unroll
        for (int j = 0; j < 8; j++) {
            int gc = bn0 + ((j < 4) ? (tx * 4 + j) : (64 + tx * 4 + (j - 4)));
            if (gc >= N) continue;
            float z = acc[i][j];
            float y;
            if (ep == 1) y = fmaxf(z + p1[gc], 0.f);
            else if (ep == 3) y = z + p1[gc];
            else y = z;
            if (C) C[(size_t)gr * N + gc] = y;
            if (Chi) {
                hf hb = __float2half_rn(y);
                Chi[(size_t)gr * 256 + gc] = hb;
                Clo[(size_t)gr * 256 + gc] = __float2half_rn(y - __half2float(hb));
            }
        }
    }
}

// ---------------- row-normalize h -> hn (+ fp16 split) ----------------
__global__ void rownorm_kernel()
{
    int row = blockIdx.x;
    int tid = threadIdx.x;                   // 256 == H_
    float v = g_h[row * H_ + tid];
    float s = v * v;
#pragma unroll
    for (int o = 16; o > 0; o >>= 1) s += __shfl_xor_sync(0xffffffff, s, o);
    __shared__ float ws[8];
    if ((tid & 31) == 0) ws[tid >> 5] = s;
    __syncthreads();
    if (tid < 8) {
        float t = ws[tid];
#pragma unroll
        for (int o = 4; o > 0; o >>= 1) t += __shfl_xor_sync(0xff, t, o);
        if (tid == 0) ws[0] = t;
    }
    __syncthreads();
    float denom = fmaxf(sqrtf(ws[0]), 1e-12f);
    float y = v / denom;
    g_hn[row * H_ + tid] = y;
    hf hb = __float2half_rn(y);
    g_hn_hi[row * H_ + tid] = hb;
    g_hn_lo[row * H_ + tid] = __float2half_rn(y - __half2float(hb));
}

// ---------------- top-k over per-tile candidates + adjacency normalize ----------------
__global__ void topk_kernel()
{
    const int row = blockIdx.x;
    const int tid = threadIdx.x;             // 256
    const float* cv = g_cv + (size_t)row * NCAND;
    const int*   ci = g_ci + (size_t)row * NCAND;

    float lv[KNN_];
    int   li[KNN_];
#pragma unroll
    for (int r = 0; r < KNN_; r++) { lv[r] = -INFINITY; li[r] = 0x7fffffff; }

    for (int j = tid; j < NCAND; j += 256) {
        float v = cv[j];
        int ii = ci[j];
        if (v > lv[KNN_ - 1] || (v == lv[KNN_ - 1] && ii < li[KNN_ - 1])) {
            int p = KNN_ - 1;
            while (p > 0 && (v > lv[p - 1] || (v == lv[p - 1] && ii < li[p - 1]))) {
                lv[p] = lv[p - 1]; li[p] = li[p - 1]; p--;
            }
            lv[p] = v; li[p] = ii;
        }
    }

    __shared__ float sv[256 * KNN_];
    __shared__ int   si[256 * KNN_];
#pragma unroll
    for (int r = 0; r < KNN_; r++) { sv[tid * KNN_ + r] = lv[r]; si[tid * KNN_ + r] = li[r]; }
    __syncthreads();

    __shared__ float rv[256];
    __shared__ int   ri[256];
    __shared__ int   rp[256];
    __shared__ float outv[KNN_];
    __shared__ int   outi[KNN_];

    const int TOT = 256 * KNN_;
    for (int r = 0; r < KNN_; r++) {
        float bv = -INFINITY; int bi = 0x7fffffff; int bp = -1;
        for (int t = tid; t < TOT; t += 256) {
            float v = sv[t]; int ii = si[t];
            if (v > bv || (v == bv && ii < bi)) { bv = v; bi = ii; bp = t; }
        }
        rv[tid] = bv; ri[tid] = bi; rp[tid] = bp;
        __syncthreads();
        for (int s = 128; s > 0; s >>= 1) {
            if (tid < s) {
                float v2 = rv[tid + s]; int i2 = ri[tid + s];
                if (v2 > rv[tid] || (v2 == rv[tid] && i2 < ri[tid])) {
                    rv[tid] = v2; ri[tid] = i2; rp[tid] = rp[tid + s];
                }
            }
            __syncthreads();
        }
        if (tid == 0) {
            outv[r] = rv[0]; outi[r] = ri[0];
            sv[rp[0]] = -INFINITY;
            si[rp[0]] = 0x7fffffff;
        }
        __syncthreads();
    }

    if (tid == 0) {
        float s = 0.f;
#pragma unroll
        for (int r = 0; r < KNN_; r++) s += outv[r];
        float inv = 1.f / fmaxf(s, 1.f);
#pragma unroll
        for (int r = 0; r < KNN_; r++) {
            g_nidx[row * KNN_ + r] = outi[r];
            g_nval[row * KNN_ + r] = outv[r] * inv;
        }
    }
}

// ---------------- sparse aggregation (+ fp16 split) ----------------
__global__ void agg_kernel()
{
    int row = blockIdx.x;
    int tid = threadIdx.x;                  // 256 == H_
    float acc = 0.f;
#pragma unroll
    for (int r = 0; r < KNN_; r++) {
        float w = g_nval[row * KNN_ + r];
        int   n = g_nidx[row * KNN_ + r];
        acc += w * g_h2[(size_t)n * H_ + tid];
    }
    g_agg[row * H_ + tid] = acc;
    hf hb = __float2half_rn(acc);
    g_ag_hi[row * H_ + tid] = hb;
    g_ag_lo[row * H_ + tid] = __float2half_rn(acc - __half2float(hb));
}

// ---------------- all weight transposes+splits in ONE launch ----------------
// grid (8, 8, 9); slot = blockIdx.z. W[256,N] row-major -> [N,256] hi/lo.
__global__ void wsplit_all(
    const float* w0, const float* w1, const float* w2, const float* w3,
    const float* w4, const float* w5, const float* w6, const float* w7,
    const float* w8, hf* __restrict__ hi_base, hf* __restrict__ lo_base)
{
    const int slot = blockIdx.z;
    const float* W = (slot == 0) ? w0 : (slot == 1) ? w1 : (slot == 2) ? w2 :
                     (slot == 3) ? w3 : (slot == 4) ? w4 : (slot == 5) ? w5 :
                     (slot == 6) ? w6 : (slot == 7) ? w7 : w8;
    const int N = (slot == 8) ? 128 : 256;
    hf* hi = hi_base + (size_t)slot * WSLOT;
    hf* lo = lo_base + (size_t)slot * WSLOT;

    __shared__ float t[32][33];
    const int n0 = blockIdx.x * 32;
    if (n0 >= N) return;
    const int k0 = blockIdx.y * 32;
    const int tx = threadIdx.x;
    const int ty = threadIdx.y;
#pragma unroll
    for (int i = ty; i < 32; i += 8)
        t[i][tx] = W[(size_t)(k0 + i) * N + n0 + tx];
    __syncthreads();
#pragma unroll
    for (int i = ty; i < 32; i += 8) {
        float v = t[tx][i];
        hf hb = __float2half_rn(v);
        hi[(size_t)(n0 + i) * 256 + k0 + tx] = hb;
        lo[(size_t)(n0 + i) * 256 + k0 + tx] = __float2half_rn(v - __half2float(hb));
    }
}

// ---------------- tiny precompute ----------------
__global__ void precompute_kernel(const float* __restrict__ bn_g, const float* __restrict__ bn_b,
                                  const float* __restrict__ bn_m, const float* __restrict__ bn_v,
                                  const float* __restrict__ t_w1, const float* __restrict__ t_b1,
                                  const float* __restrict__ t_w2, const float* __restrict__ t_b2,
                                  const float* __restrict__ gate_w, const float* __restrict__ gate_b,
                                  const float* __restrict__ sde_w1, const float* __restrict__ sde_b1)
{
    int b = blockIdx.x;
    int j = threadIdx.x;
    if (b == 0) {
        float s = bn_g[j] * rsqrtf(bn_v[j] + 1e-5f);
        g_bnscale[j] = s;
        g_bnshift[j] = bn_b[j] - bn_m[j] * s;
    } else if (b <= NL_) {
        int l = b - 1;
        float t = 0.5f * (float)l;
        __shared__ float te[TD_];
        __shared__ float te2[H_];
        if (j < TD_) te[j] = fmaxf(t * t_w1[l * TD_ + j] + t_b1[l * TD_ + j], 0.f);
        __syncthreads();
        float acc = t_b2[l * H_ + j];
#pragma unroll
        for (int k = 0; k < TD_; k++) acc += te[k] * t_w2[l * TD_ * H_ + k * H_ + j];
        te2[j] = acc;
        __syncthreads();
        float c = gate_b[l * H_ + j];
        const float* W = gate_w + (size_t)l * 2 * H_ * H_ + (size_t)H_ * H_;
        for (int k = 0; k < H_; k++) c += te2[k] * W[k * H_ + j];
        g_gatec[l * H_ + j] = c;
    } else {
        int s = b - 1 - NL_;
        float ts = (float)s * 0.1f;
        g_sdebias[s * H_ + j] = sde_b1[j] + ts * sde_w1[H_ * H_ + j];
    }
}

// ---------------- host ----------------
static inline void launch_mma(const hf* Ahi, const hf* Alo, const hf* Bhi, const hf* Blo,
                              float* C, int Ntot, int ep, int cand,
                              const float* p1 = nullptr, const float* p2 = nullptr,
                              const float* p3 = nullptr, float alpha = 0.f,
                              hf* Chi = nullptr, hf* Clo = nullptr)
{
    dim3 grid(Ntot / 128, NN_ / 128);
    mma_gemm<<<grid, 512, MG_SMEM>>>(Ahi, Alo, Bhi, Blo, C, Ntot, ep, cand,
                                     p1, p2, p3, alpha, Chi, Clo);
}

extern "C" void kernel_launch(void* const* d_in, const int* in_sizes, int n_in,
                              void* d_out, int out_size)
{
    const float* x       = (const float*)d_in[0];
    const float* enc_w1  = (const float*)d_in[1];
    const float* enc_b1  = (const float*)d_in[2];
    const float* enc_w2  = (const float*)d_in[3];
    const float* enc_b2  = (const float*)d_in[4];
    const float* bn_g    = (const float*)d_in[5];
    const float* bn_b    = (const float*)d_in[6];
    const float* bn_m    = (const float*)d_in[7];
    const float* bn_v    = (const float*)d_in[8];
    const float* node_w  = (const float*)d_in[9];
    const float* node_b  = (const float*)d_in[10];
    const float* t_w1    = (const float*)d_in[11];
    const float* t_b1    = (const float*)d_in[12];
    const float* t_w2    = (const float*)d_in[13];
    const float* t_b2    = (const float*)d_in[14];
    const float* gate_w  = (const float*)d_in[15];
    const float* gate_b  = (const float*)d_in[16];
    const float* sde_w1  = (const float*)d_in[17];
    const float* sde_b1  = (const float*)d_in[18];
    const float* sde_w2  = (const float*)d_in[19];
    const float* sde_b2  = (const float*)d_in[20];
    const float* sde_w3  = (const float*)d_in[21];
    const float* sde_b3  = (const float*)d_in[22];
    const float* dec_w1  = (const float*)d_in[23];
    const float* dec_b1  = (const float*)d_in[24];
    const float* dec_w2  = (const float*)d_in[25];
    const float* dec_b2  = (const float*)d_in[26];
    float* out = (float*)d_out;

    cudaFuncSetAttribute(mma_gemm, cudaFuncAttributeMaxDynamicSharedMemorySize, MG_SMEM);
    cudaFuncSetAttribute(sde_fused, cudaFuncAttributeMaxDynamicSharedMemorySize, SDE_SMEM);

    float *h, *h2, *hn, *agg, *d1, *bns, *bnsh, *gatec, *sdeb;
    hf *hhi, *hlo, *h2hi, *h2lo, *hnhi, *hnlo, *aghi, *aglo, *whi, *wlo;
    cudaGetSymbolAddress((void**)&h,     g_h);
    cudaGetSymbolAddress((void**)&h2,    g_h2);
    cudaGetSymbolAddress((void**)&hn,    g_hn);
    cudaGetSymbolAddress((void**)&agg,   g_agg);
    cudaGetSymbolAddress((void**)&d1,    g_d1);
    cudaGetSymbolAddress((void**)&bns,   g_bnscale);
    cudaGetSymbolAddress((void**)&bnsh,  g_bnshift);
    cudaGetSymbolAddress((void**)&gatec, g_gatec);
    cudaGetSymbolAddress((void**)&sdeb,  g_sdebias);
    cudaGetSymbolAddress((void**)&hhi,  g_h_hi);  cudaGetSymbolAddress((void**)&hlo,  g_h_lo);
    cudaGetSymbolAddress((void**)&h2hi, g_h2_hi); cudaGetSymbolAddress((void**)&h2lo, g_h2_lo);
    cudaGetSymbolAddress((void**)&hnhi, g_hn_hi); cudaGetSymbolAddress((void**)&hnlo, g_hn_lo);
    cudaGetSymbolAddress((void**)&aghi, g_ag_hi); cudaGetSymbolAddress((void**)&aglo, g_ag_lo);
    cudaGetSymbolAddress((void**)&whi, g_w_hi);   cudaGetSymbolAddress((void**)&wlo, g_w_lo);

    // (1) precompute
    precompute_kernel<<<1 + NL_ + NSTEPS_, 256>>>(bn_g, bn_b, bn_m, bn_v,
                                                  t_w1, t_b1, t_w2, t_b2,
                                                  gate_w, gate_b, sde_w1, sde_b1);
    // (2) ALL weight splits in one launch
    {
        dim3 grid(8, 8, 9);
        wsplit_all<<<grid, dim3(32, 8)>>>(
            enc_w2, node_w, node_w + H_ * H_, gate_w, gate_w + 2 * H_ * H_,
            sde_w1, sde_w2, sde_w3, dec_w1, whi, wlo);
    }
    // (3) enc1 SIMT (K=83), splits only
    {
        dim3 grid((H_ + BN - 1) / BN, (NN_ + BM - 1) / BM);
        gemm_kernel<<<grid, 256>>>(x, enc_w1, nullptr, NN_, H_, DIN_, H_, 1, enc_b1, h2hi, h2lo);
    }
    // (4) enc2 mma
    launch_mma(h2hi, h2lo, whi + 0 * WSLOT, wlo + 0 * WSLOT, h, 256, /*ep=*/2, 0,
               enc_b2, bns, bnsh, 0.f, hhi, hlo);
    // (5) rownorm
    rownorm_kernel<<<NN_, 256>>>();
    // (6) sim mma with fused candidate extraction (sim never hits DRAM)
    launch_mma(hnhi, hnlo, hnhi, hnlo, nullptr, NN_, /*ep=*/0, /*cand=*/1);
    // (7) top-k over candidates
    topk_kernel<<<NN_, 256>>>();

    // temporal gated graph conv layers
    for (int l = 0; l < NL_; l++) {
        launch_mma(hhi, hlo, whi + (1 + l) * WSLOT, wlo + (1 + l) * WSLOT, h2, 256, /*ep=*/3, 0,
                   node_b + (size_t)l * H_);
        agg_kernel<<<NN_, 256>>>();
        launch_mma(aghi, aglo, whi + (3 + l) * WSLOT, wlo + (3 + l) * WSLOT, h, 256, /*ep=*/4, 0,
                   gatec + (size_t)l * H_, agg, h2, 0.f, hhi, hlo);
    }

    // SDE: fused persistent kernel (128 CTAs x 64 rows, 10 steps x 3 layers)
    sde_fused<<<NN_ / 64, 256, SDE_SMEM>>>(
        whi + 5 * WSLOT, wlo + 5 * WSLOT,
        whi + 6 * WSLOT, wlo + 6 * WSLOT,
        whi + 7 * WSLOT, wlo + 7 * WSLOT,
        sdeb, sde_b2, sde_b3, h, hhi, hlo);

    // decoder: dec1 tensor (N=128), dec2 SIMT (K=128, N=34)
    launch_mma(hhi, hlo, whi + 8 * WSLOT, wlo + 8 * WSLOT, d1, 128, /*ep=*/1, 0, dec_b1);
    {
        dim3 grid((C_ + BN - 1) / BN, (NN_ + BM - 1) / BM);
        gemm_kernel<<<grid, 256>>>(d1, dec_w2, out, NN_, C_, H_ / 2, C_, 3, dec_b2, nullptr, nullptr);
    }
}

// round 11
// speedup vs baseline: 2.8906x; 1.0331x over previous
#include <cuda_runtime.h>
#include <cuda_bf16.h>
#include <cuda_fp16.h>
#include <math.h>
#include <stdint.h>

// ---------------- problem constants ----------------
#define NN_   8192
#define DIN_  83
#define H_    256
#define C_    34
#define TD_   16
#define NL_   2
#define KNN_  11
#define NSTEPS_ 10
#define NTILE 64
#define NCAND (NTILE * KNN_)            // 704 candidates per row

typedef __half hf;

// ---------------- scratch (device globals; no allocation allowed) ----------------
__device__ float g_h  [NN_ * H_];
__device__ float g_h2 [NN_ * H_];
__device__ float g_hn [NN_ * H_];
__device__ float g_agg[NN_ * H_];
__device__ float g_d1 [NN_ * H_];
__device__ int   g_nidx[NN_ * KNN_];
__device__ float g_nval[NN_ * KNN_];
__device__ float g_bnscale[H_];
__device__ float g_bnshift[H_];
__device__ float g_gatec[NL_ * H_];
__device__ float g_sdebias[NSTEPS_ * H_];
__device__ float g_cv[(size_t)NN_ * NCAND];       // topk candidate values (23 MB)
__device__ int   g_ci[(size_t)NN_ * NCAND];       // topk candidate indices (23 MB)

// fp16 split copies of activations ([M,256] row-major hi/lo)
__device__ hf g_h_hi [NN_ * H_],  g_h_lo [NN_ * H_];
__device__ hf g_h2_hi[NN_ * H_],  g_h2_lo[NN_ * H_];
__device__ hf g_hn_hi[NN_ * H_],  g_hn_lo[NN_ * H_];
__device__ hf g_ag_hi[NN_ * H_],  g_ag_lo[NN_ * H_];

// transposed+split weights, [N,256] K-major; 9 slots of 64K elems
#define WSLOT 65536
__device__ hf g_w_hi[9 * WSLOT];
__device__ hf g_w_lo[9 * WSLOT];

// ================= helpers =================
__device__ __forceinline__ uint32_t smem_u32(const void* p) {
    uint32_t a;
    asm("{ .reg .u64 t; cvta.to.shared.u64 t, %1; cvt.u32.u64 %0, t; }" : "=r"(a) : "l"(p));
    return a;
}
__device__ __forceinline__ void ldsm4(uint32_t* r, uint32_t addr) {
    asm volatile("ldmatrix.sync.aligned.m8n8.x4.shared.b16 {%0,%1,%2,%3}, [%4];"
                 : "=r"(r[0]), "=r"(r[1]), "=r"(r[2]), "=r"(r[3]) : "r"(addr));
}
__device__ __forceinline__ void mma16816(float* d, const uint32_t* a, uint32_t b0, uint32_t b1) {
    asm volatile("mma.sync.aligned.m16n8k16.row.col.f32.f16.f16.f32 "
                 "{%0,%1,%2,%3}, {%4,%5,%6,%7}, {%8,%9}, {%0,%1,%2,%3};"
                 : "+f"(d[0]), "+f"(d[1]), "+f"(d[2]), "+f"(d[3])
                 : "r"(a[0]), "r"(a[1]), "r"(a[2]), "r"(a[3]), "r"(b0), "r"(b1));
}
__device__ __forceinline__ float fast_tanh(float x) {
    float ax = fabsf(x);
    float t = __expf(-2.f * ax);
    float r = __fdividef(1.f - t, 1.f + t);
    return copysignf(r, x);
}
__device__ __forceinline__ float fast_sigmoid(float x) {
    return __fdividef(1.f, 1.f + __expf(-x));
}
__device__ __forceinline__ void split2(float y0, float y1, hf* hi, hf* lo) {
    hf h0 = __float2half_rn(y0);
    hf h1 = __float2half_rn(y1);
    __half2 hp; hp.x = h0; hp.y = h1;
    __half2 lp;
    lp.x = __float2half_rn(y0 - __half2float(h0));
    lp.y = __float2half_rn(y1 - __half2float(h1));
    *(__half2*)hi = hp;
    *(__half2*)lo = lp;
}
#define CP_ASYNC16(sa, gp) \
    asm volatile("cp.async.cg.shared.global [%0], [%1], 16;" :: "r"(sa), "l"(gp))
#define CP_COMMIT() asm volatile("cp.async.commit_group;" ::: "memory")
#define CP_WAIT(n)  asm volatile("cp.async.wait_group %0;" :: "n"(n) : "memory")

// ================= tensor-core split-fp16 GEMM =================
// 256 threads / 8 warps, warp tile 32x64, CTA tile 128x128, 2 CTAs/SM.
// 3 split terms (AhBh+AhBl+AlBh), fp32 accum, cp.async double buffered (K = 8x32).
// cand=1: symmetric sim mode; lower-triangle CTAs extract per-row top-11 for
// direct rows AND mirrored rows (column scans); sim never hits DRAM.

#define TILE_B   8192                    // 128 rows * 32 hf * 2B
#define BUF_B    (4 * TILE_B)            // Ah,Al,Bh,Bl
#define MG_SMEM  (128 * 133 * 4)         // 68096 B: max(load bufs 64K, cand staging)

__device__ __forceinline__ void cpa_tile(const hf* __restrict__ src, int r0, int k0,
                                         char* __restrict__ dst, int tid)
{
#pragma unroll
    for (int u = 0; u < 2; u++) {
        int i = tid + u * 256;               // 512 16B segs
        int row = i >> 2;                    // 0..127
        int seg = i & 3;
        const void* gp = src + (size_t)(r0 + row) * 256 + k0 + seg * 8;
        uint32_t off = (uint32_t)row * 64u + (uint32_t)((seg ^ ((row >> 1) & 3)) << 4);
        CP_ASYNC16(smem_u32(dst + off), gp);
    }
}

__global__ __launch_bounds__(256, 2) void mma_gemm(
    const hf* __restrict__ Ahi, const hf* __restrict__ Alo,
    const hf* __restrict__ Bhi, const hf* __restrict__ Blo,
    float* __restrict__ C, int Ntot, int ep, int cand,
    const float* __restrict__ p1, const float* __restrict__ p2,
    const float* __restrict__ p3, float alpha,
    hf* __restrict__ Chi, hf* __restrict__ Clo)
{
    const int bn0 = blockIdx.x * 128;
    const int bm0 = blockIdx.y * 128;
    if (cand && bn0 > bm0) return;              // symmetric: lower triangle only

    extern __shared__ char smem[];
    char* bufp[2] = {smem, smem + BUF_B};

    const int tid  = threadIdx.x;
    const int wid  = tid >> 5;
    const int lane = tid & 31;
    const int warp_m = wid & 3;                 // rows  [warp_m*32, +32)
    const int warp_n = wid >> 2;                // cols  [warp_n*64, +64)

    float acc[2][8][4];
#pragma unroll
    for (int i = 0; i < 2; i++)
#pragma unroll
        for (int j = 0; j < 8; j++)
#pragma unroll
            for (int q = 0; q < 4; q++) acc[i][j][q] = 0.f;

    const int lrow  = lane & 15;
    const int lhalf = lane >> 4;

    cpa_tile(Ahi, bm0, 0, bufp[0] + 0 * TILE_B, tid);
    cpa_tile(Alo, bm0, 0, bufp[0] + 1 * TILE_B, tid);
    cpa_tile(Bhi, bn0, 0, bufp[0] + 2 * TILE_B, tid);
    cpa_tile(Blo, bn0, 0, bufp[0] + 3 * TILE_B, tid);
    CP_COMMIT();

    int buf = 0;
    for (int chunk = 0; chunk < 8; chunk++) {
        if (chunk + 1 < 8) {
            const int k1 = (chunk + 1) * 32;
            char* nb = bufp[buf ^ 1];
            cpa_tile(Ahi, bm0, k1, nb + 0 * TILE_B, tid);
            cpa_tile(Alo, bm0, k1, nb + 1 * TILE_B, tid);
            cpa_tile(Bhi, bn0, k1, nb + 2 * TILE_B, tid);
            cpa_tile(Blo, bn0, k1, nb + 3 * TILE_B, tid);
            CP_COMMIT();
            CP_WAIT(1);
        } else {
            CP_WAIT(0);
        }
        __syncthreads();

        const uint32_t sAh_b = smem_u32(bufp[buf] + 0 * TILE_B);
        const uint32_t sAl_b = smem_u32(bufp[buf] + 1 * TILE_B);
        const uint32_t sBh_b = smem_u32(bufp[buf] + 2 * TILE_B);
        const uint32_t sBl_b = smem_u32(bufp[buf] + 3 * TILE_B);

#pragma unroll
        for (int kk = 0; kk < 2; kk++) {
            const int segq = kk * 2 + lhalf;

            uint32_t aH[2][4], aL[2][4], bH[4][4], bL[4][4];
#pragma unroll
            for (int mt = 0; mt < 2; mt++) {
                int row = warp_m * 32 + mt * 16 + lrow;
                uint32_t off = (uint32_t)row * 64u + (uint32_t)((segq ^ ((row >> 1) & 3)) << 4);
                ldsm4(aH[mt], sAh_b + off);
                ldsm4(aL[mt], sAl_b + off);
            }
#pragma unroll
            for (int gg = 0; gg < 4; gg++) {
                int row = warp_n * 64 + gg * 16 + lrow;
                uint32_t off = (uint32_t)row * 64u + (uint32_t)((segq ^ ((row >> 1) & 3)) << 4);
                ldsm4(bH[gg], sBh_b + off);
                ldsm4(bL[gg], sBl_b + off);
            }

#define DO_TERM(Af, Bf)                                                        \
            _Pragma("unroll")                                                  \
            for (int mt = 0; mt < 2; mt++)                                     \
                _Pragma("unroll")                                              \
                for (int gg = 0; gg < 4; gg++) {                               \
                    mma16816(acc[mt][2 * gg + 0], Af[mt], Bf[gg][0], Bf[gg][2]); \
                    mma16816(acc[mt][2 * gg + 1], Af[mt], Bf[gg][1], Bf[gg][3]); \
                }
            DO_TERM(aH, bH)
            DO_TERM(aH, bL)
            DO_TERM(aL, bH)
#undef DO_TERM
        }
        __syncthreads();
        buf ^= 1;
    }

    if (cand) {
        // ---- stage full 128x128 tile, pitch 133 (conflict-free row & col scans) ----
        float* ts = (float*)smem;
#pragma unroll
        for (int mt = 0; mt < 2; mt++)
#pragma unroll
            for (int half = 0; half < 2; half++) {
                int lr = warp_m * 32 + mt * 16 + (lane >> 2) + half * 8;
#pragma unroll
                for (int nt = 0; nt < 8; nt++) {
                    int lc = warp_n * 64 + nt * 8 + (lane & 3) * 2;
                    ts[lr * 133 + lc]     = acc[mt][nt][half * 2 + 0];
                    ts[lr * 133 + lc + 1] = acc[mt][nt][half * 2 + 1];
                }
            }
        __syncthreads();

        float lv[KNN_]; int li[KNN_];
        if (tid < 128) {
            // direct: row bm0+tid, cols bn0..+127
            int r = tid;
#pragma unroll
            for (int q = 0; q < KNN_; q++) { lv[q] = -INFINITY; li[q] = 0x7fffffff; }
            for (int c = 0; c < 128; c++) {
                float v = ts[r * 133 + c];
                if (v > lv[KNN_ - 1]) {
                    int p = KNN_ - 1;
                    while (p > 0 && v > lv[p - 1]) { lv[p] = lv[p - 1]; li[p] = li[p - 1]; p--; }
                    lv[p] = v; li[p] = bn0 + c;
                }
            }
            size_t base = (size_t)(bm0 + r) * NCAND + (size_t)(bn0 >> 7) * KNN_;
#pragma unroll
            for (int q = 0; q < KNN_; q++) { g_cv[base + q] = lv[q]; g_ci[base + q] = li[q]; }
        } else if (bm0 != bn0) {
            // mirror: row bn0+c, cols bm0..+127 (column scan of staged tile)
            int c = tid - 128;
#pragma unroll
            for (int q = 0; q < KNN_; q++) { lv[q] = -INFINITY; li[q] = 0x7fffffff; }
            for (int r = 0; r < 128; r++) {
                float v = ts[r * 133 + c];
                if (v > lv[KNN_ - 1]) {
                    int p = KNN_ - 1;
                    while (p > 0 && v > lv[p - 1]) { lv[p] = lv[p - 1]; li[p] = li[p - 1]; p--; }
                    lv[p] = v; li[p] = bm0 + r;
                }
            }
            size_t base = (size_t)(bn0 + c) * NCAND + (size_t)(bm0 >> 7) * KNN_;
#pragma unroll
            for (int q = 0; q < KNN_; q++) { g_cv[base + q] = lv[q]; g_ci[base + q] = li[q]; }
        }
        return;
    }

    auto epi = [&](float z, int gr, int gc) -> float {
        if (ep == 0) return z;
        if (ep == 1) return fmaxf(z + p1[gc], 0.f);
        if (ep == 2) return fmaxf(z + p1[gc], 0.f) * p2[gc] + p3[gc];
        if (ep == 3) return z + p1[gc];
        if (ep == 4) {
            float g = fast_sigmoid(z + p1[gc]);
            float a = p2[(size_t)gr * Ntot + gc];
            float hh = p3[(size_t)gr * Ntot + gc];
            return fmaxf(g * a + (1.f - g) * hh, 0.f);
        }
        if (ep == 5) return fast_tanh(z + p1[gc]);
        return p2[(size_t)gr * Ntot + gc] + fast_tanh(z + p1[gc]) * alpha;  // 6
    };

#pragma unroll
    for (int mt = 0; mt < 2; mt++) {
#pragma unroll
        for (int half = 0; half < 2; half++) {
            int gr = bm0 + warp_m * 32 + mt * 16 + (lane >> 2) + half * 8;
#pragma unroll
            for (int nt = 0; nt < 8; nt++) {
                int gc = bn0 + warp_n * 64 + nt * 8 + (lane & 3) * 2;
                float y0 = epi(acc[mt][nt][half * 2 + 0], gr, gc);
                float y1 = epi(acc[mt][nt][half * 2 + 1], gr, gc + 1);
                if (C) {
                    float2 o; o.x = y0; o.y = y1;
                    *(float2*)(C + (size_t)gr * Ntot + gc) = o;
                }
                if (Chi) {
                    split2(y0, y1, Chi + (size_t)gr * 256 + gc, Clo + (size_t)gr * 256 + gc);
                }
            }
        }
    }
}

// ================= fused persistent SDE kernel (512 threads / 16 warps) =================
// 10 Euler steps x 3 tanh layers, 128 CTAs x 64 rows. Warp tile 16x64 (4x4 warp grid).
// h fp32 + u splits resident in smem; weights streamed from L2 (double buffered).
#define SDE_SH   0                       // float[64*256]   64 KB
#define SDE_UH   65536                   // hf, swizzled    32 KB
#define SDE_UL   (65536 + 32768)         // hf, swizzled    32 KB
#define SDE_W    131072                  // 2 x (hi16K+lo16K) = 64 KB
#define SDE_SMEM 196608

__device__ __forceinline__ void sde_wchunk(const hf* __restrict__ W, int k0,
                                           char* __restrict__ dst, int tid)
{
#pragma unroll
    for (int u = 0; u < 2; u++) {
        int i = tid + u * 512;               // 1024 segs: 256 rows x 4
        int row = i >> 2, seg = i & 3;
        const void* gp = W + (size_t)row * 256 + k0 + seg * 8;
        uint32_t off = (uint32_t)row * 64u + (uint32_t)((seg ^ ((row >> 1) & 3)) << 4);
        CP_ASYNC16(smem_u32(dst + off), gp);
    }
}

__global__ __launch_bounds__(512) void sde_fused(
    const hf* __restrict__ W1h, const hf* __restrict__ W1l,
    const hf* __restrict__ W2h, const hf* __restrict__ W2l,
    const hf* __restrict__ W3h, const hf* __restrict__ W3l,
    const float* __restrict__ sdeb, const float* __restrict__ b2,
    const float* __restrict__ b3,
    const float* __restrict__ hin,
    hf* __restrict__ hhi_g, hf* __restrict__ hlo_g)
{
    extern __shared__ char smem[];
    float* sh = (float*)(smem + SDE_SH);
    char* sUh = smem + SDE_UH;
    char* sUl = smem + SDE_UL;

    const int tid  = threadIdx.x;
    const int wid  = tid >> 5;
    const int lane = tid & 31;
    const int warp_m = wid & 3;              // 4 warps over m (16 rows each)
    const int warp_n = wid >> 2;             // 4 warps over n (64 cols each)
    const int r0 = blockIdx.x * 64;
    const int lrow  = lane & 15;
    const int lhalf = lane >> 4;

    // initial loads: sh (fp32 h) and sU (h splits, swizzled chunk layout)
#pragma unroll
    for (int u = 0; u < 8; u++) {
        int i = tid + u * 512;               // 4096 16B segs
        int row = i >> 6, c4 = i & 63;
        CP_ASYNC16(smem_u32(sh + row * 256 + c4 * 4),
                   (const void*)(hin + (size_t)(r0 + row) * 256 + c4 * 4));
    }
#pragma unroll
    for (int u = 0; u < 4; u++) {
        int i = tid + u * 512;               // 2048 segs: 64 rows x 32
        int row = i >> 5, s32 = i & 31;
        int chunk = s32 >> 2, seg = s32 & 3;
        uint32_t off = (uint32_t)chunk * 4096u + (uint32_t)row * 64u
                     + (uint32_t)((seg ^ ((row >> 1) & 3)) << 4);
        CP_ASYNC16(smem_u32(sUh + off), (const void*)(hhi_g + (size_t)(r0 + row) * 256 + s32 * 8));
        CP_ASYNC16(smem_u32(sUl + off), (const void*)(hlo_g + (size_t)(r0 + row) * 256 + s32 * 8));
    }
    CP_COMMIT();
    CP_WAIT(0);
    __syncthreads();

    for (int step = 0; step < NSTEPS_; step++) {
#pragma unroll 1
        for (int layer = 0; layer < 3; layer++) {
            const hf* Wh = (layer == 0) ? W1h : (layer == 1) ? W2h : W3h;
            const hf* Wl = (layer == 0) ? W1l : (layer == 1) ? W2l : W3l;
            const float* bias = (layer == 0) ? (sdeb + step * H_) : (layer == 1) ? b2 : b3;

            float acc[8][4];
#pragma unroll
            for (int j = 0; j < 8; j++)
#pragma unroll
                for (int q = 0; q < 4; q++) acc[j][q] = 0.f;

            sde_wchunk(Wh, 0, smem + SDE_W, tid);
            sde_wchunk(Wl, 0, smem + SDE_W + 16384, tid);
            CP_COMMIT();
            int wb = 0;
#pragma unroll 1
            for (int kc = 0; kc < 8; kc++) {
                if (kc + 1 < 8) {
                    char* nb = smem + SDE_W + (wb ^ 1) * 32768;
                    sde_wchunk(Wh, (kc + 1) * 32, nb, tid);
                    sde_wchunk(Wl, (kc + 1) * 32, nb + 16384, tid);
                    CP_COMMIT();
                    CP_WAIT(1);
                } else {
                    CP_WAIT(0);
                }
                __syncthreads();

                const uint32_t sWh_b = smem_u32(smem + SDE_W + wb * 32768);
                const uint32_t sWl_b = sWh_b + 16384;
                const uint32_t sAh_b = smem_u32(sUh) + kc * 4096;
                const uint32_t sAl_b = smem_u32(sUl) + kc * 4096;

#pragma unroll
                for (int kk = 0; kk < 2; kk++) {
                    const int segq = kk * 2 + lhalf;
                    uint32_t aH[4], aL[4], bH[4][4], bL[4][4];
                    {
                        int row = warp_m * 16 + lrow;
                        uint32_t off = (uint32_t)row * 64u
                                     + (uint32_t)((segq ^ ((row >> 1) & 3)) << 4);
                        ldsm4(aH, sAh_b + off);
                        ldsm4(aL, sAl_b + off);
                    }
#pragma unroll
                    for (int gg = 0; gg < 4; gg++) {
                        int row = warp_n * 64 + gg * 16 + lrow;
                        uint32_t off = (uint32_t)row * 64u
                                     + (uint32_t)((segq ^ ((row >> 1) & 3)) << 4);
                        ldsm4(bH[gg], sWh_b + off);
                        ldsm4(bL[gg], sWl_b + off);
                    }
#define DO_TERM4(Af, Bf)                                                       \
                    _Pragma("unroll")                                          \
                    for (int gg = 0; gg < 4; gg++) {                           \
                        mma16816(acc[2 * gg + 0], Af, Bf[gg][0], Bf[gg][2]);   \
                        mma16816(acc[2 * gg + 1], Af, Bf[gg][1], Bf[gg][3]);   \
                    }
                    DO_TERM4(aH, bH)
                    DO_TERM4(aH, bL)
                    DO_TERM4(aL, bH)
#undef DO_TERM4
                }
                __syncthreads();
                wb ^= 1;
            }

            const bool lastL = (layer == 2);
            const bool fin = lastL && (step == NSTEPS_ - 1);
#pragma unroll
            for (int half = 0; half < 2; half++) {
                int lr = warp_m * 16 + (lane >> 2) + half * 8;
#pragma unroll
                for (int nt = 0; nt < 8; nt++) {
                    int gc = warp_n * 64 + nt * 8 + (lane & 3) * 2;
                    float y0 = fast_tanh(acc[nt][half * 2 + 0] + bias[gc]);
                    float y1 = fast_tanh(acc[nt][half * 2 + 1] + bias[gc + 1]);
                    if (lastL) {
                        y0 = sh[lr * 256 + gc] + y0 * 0.1f;
                        y1 = sh[lr * 256 + gc + 1] + y1 * 0.1f;
                        if (!fin) {
                            sh[lr * 256 + gc] = y0;
                            sh[lr * 256 + gc + 1] = y1;
                        }
                    }
                    if (fin) {
                        split2(y0, y1, hhi_g + (size_t)(r0 + lr) * 256 + gc,
                                       hlo_g + (size_t)(r0 + lr) * 256 + gc);
                    } else {
                        int chunk = gc >> 5, k = gc & 31, seg = k >> 3;
                        uint32_t boff = (uint32_t)chunk * 4096u + (uint32_t)lr * 64u
                                      + (uint32_t)((seg ^ ((lr >> 1) & 3)) << 4)
                                      + (uint32_t)(k & 7) * 2u;
                        split2(y0, y1, (hf*)(sUh + boff), (hf*)(sUl + boff));
                    }
                }
            }
            __syncthreads();
        }
    }
}

// ================= SIMT fp32 GEMM (odd shapes: enc1 K=83, dec2 N=34) =================
#define BM 128
#define BN 128
#define BK 8

__global__ __launch_bounds__(256) void gemm_kernel(
    const float* __restrict__ A, const float* __restrict__ B, float* __restrict__ C,
    int M, int N, int K, int ldb, int ep,
    const float* __restrict__ p1, hf* __restrict__ Chi, hf* __restrict__ Clo)
{
    __shared__ float As[2][BK][BM + 4];
    __shared__ float Bs[2][BK][BN + 4];

    const int tid = threadIdx.x;
    const int tx  = tid & 15;
    const int ty  = tid >> 4;
    const int bn0 = blockIdx.x * BN;
    const int bm0 = blockIdx.y * BM;

    float acc[8][8];
#pragma unroll
    for (int i = 0; i < 8; i++)
#pragma unroll
        for (int j = 0; j < 8; j++) acc[i][j] = 0.f;

    const int aRow = tid >> 1;
    const int aK   = (tid & 1) * 4;
    const int bRow = tid >> 5;
    const int bN   = (tid & 31) * 4;

    float ra[4], rb[4];
    const int ktiles = (K + BK - 1) / BK;

#define LOAD_AB(kt) do {                                                       \
        int k0_ = (kt) * BK;                                                   \
        int gr_ = bm0 + aRow, gk_ = k0_ + aK;                                  \
        _Pragma("unroll")                                                      \
        for (int j_ = 0; j_ < 4; j_++)                                         \
            ra[j_] = (gr_ < M && gk_ + j_ < K) ? A[(size_t)gr_ * K + gk_ + j_] : 0.f; \
        int gk2_ = k0_ + bRow, gn_ = bn0 + bN;                                 \
        _Pragma("unroll")                                                      \
        for (int j_ = 0; j_ < 4; j_++)                                         \
            rb[j_] = (gk2_ < K && gn_ + j_ < N) ? B[(size_t)gk2_ * ldb + gn_ + j_] : 0.f; \
    } while (0)

#define STS_AB2(buf) do {                                                      \
        _Pragma("unroll")                                                      \
        for (int j_ = 0; j_ < 4; j_++) As[buf][aK + j_][aRow] = ra[j_];        \
        _Pragma("unroll")                                                      \
        for (int j_ = 0; j_ < 4; j_++) Bs[buf][bRow][bN + j_] = rb[j_];        \
    } while (0)

    LOAD_AB(0);
    STS_AB2(0);
    __syncthreads();

    int cur = 0;
    for (int kt = 0; kt < ktiles; kt++) {
        const int hasNext = (kt + 1 < ktiles);
        if (hasNext) LOAD_AB(kt + 1);
#pragma unroll
        for (int kk = 0; kk < BK; kk++) {
            const float* as = As[cur][kk];
            const float* bs = Bs[cur][kk];
            float4 A0 = *(const float4*)(as + ty * 4);
            float4 A1 = *(const float4*)(as + 64 + ty * 4);
            float4 B0 = *(const float4*)(bs + tx * 4);
            float4 B1 = *(const float4*)(bs + 64 + tx * 4);
            float av[8] = {A0.x, A0.y, A0.z, A0.w, A1.x, A1.y, A1.z, A1.w};
            float bv[8] = {B0.x, B0.y, B0.z, B0.w, B1.x, B1.y, B1.z, B1.w};
#pragma unroll
            for (int i = 0; i < 8; i++)
#pragma unroll
                for (int j = 0; j < 8; j++)
                    acc[i][j] = fmaf(av[i], bv[j], acc[i][j]);
        }
        if (hasNext) { STS_AB2(cur ^ 1); __syncthreads(); cur ^= 1; }
    }

#pragma unroll
    for (int i = 0; i < 8; i++) {
        int gr = bm0 + ((i < 4) ? (ty * 4 + i) : (64 + ty * 4 + (i - 4)));
        if (gr >= M) continue;
#pragma unroll
        for (int j = 0; j < 8; j++) {
            int gc = bn0 + ((j < 4) ? (tx * 4 + j) : (64 + tx * 4 + (j - 4)));
            if (gc >= N) continue;
            float z = acc[i][j];
            float y;
            if (ep == 1) y = fmaxf(z + p1[gc], 0.f);
            else if (ep == 3) y = z + p1[gc];
            else y = z;
            if (C) C[(size_t)gr * N + gc] = y;
            if (Chi) {
                hf hb = __float2half_rn(y);
                Chi[(size_t)gr * 256 + gc] = hb;
                Clo[(size_t)gr * 256 + gc] = __float2half_rn(y - __half2float(hb));
            }
        }
    }
}

// ---------------- row-normalize h -> hn (+ fp16 split) ----------------
__global__ void rownorm_kernel()
{
    int row = blockIdx.x;
    int tid = threadIdx.x;                   // 256 == H_
    float v = g_h[row * H_ + tid];
    float s = v * v;
#pragma unroll
    for (int o = 16; o > 0; o >>= 1) s += __shfl_xor_sync(0xffffffff, s, o);
    __shared__ float ws[8];
    if ((tid & 31) == 0) ws[tid >> 5] = s;
    __syncthreads();
    if (tid < 8) {
        float t = ws[tid];
#pragma unroll
        for (int o = 4; o > 0; o >>= 1) t += __shfl_xor_sync(0xff, t, o);
        if (tid == 0) ws[0] = t;
    }
    __syncthreads();
    float denom = fmaxf(sqrtf(ws[0]), 1e-12f);
    float y = v / denom;
    g_hn[row * H_ + tid] = y;
    hf hb = __float2half_rn(y);
    g_hn_hi[row * H_ + tid] = hb;
    g_hn_lo[row * H_ + tid] = __float2half_rn(y - __half2float(hb));
}

// ---------------- top-k over per-tile candidates + adjacency normalize ----------------
__global__ void topk_kernel()
{
    const int row = blockIdx.x;
    const int tid = threadIdx.x;             // 256
    const float* cv = g_cv + (size_t)row * NCAND;
    const int*   ci = g_ci + (size_t)row * NCAND;

    float lv[KNN_];
    int   li[KNN_];
#pragma unroll
    for (int r = 0; r < KNN_; r++) { lv[r] = -INFINITY; li[r] = 0x7fffffff; }

    for (int j = tid; j < NCAND; j += 256) {
        float v = cv[j];
        int ii = ci[j];
        if (v > lv[KNN_ - 1] || (v == lv[KNN_ - 1] && ii < li[KNN_ - 1])) {
            int p = KNN_ - 1;
            while (p > 0 && (v > lv[p - 1] || (v == lv[p - 1] && ii < li[p - 1]))) {
                lv[p] = lv[p - 1]; li[p] = li[p - 1]; p--;
            }
            lv[p] = v; li[p] = ii;
        }
    }

    __shared__ float sv[256 * KNN_];
    __shared__ int   si[256 * KNN_];
#pragma unroll
    for (int r = 0; r < KNN_; r++) { sv[tid * KNN_ + r] = lv[r]; si[tid * KNN_ + r] = li[r]; }
    __syncthreads();

    __shared__ float rv[256];
    __shared__ int   ri[256];
    __shared__ int   rp[256];
    __shared__ float outv[KNN_];
    __shared__ int   outi[KNN_];

    const int TOT = 256 * KNN_;
    for (int r = 0; r < KNN_; r++) {
        float bv = -INFINITY; int bi = 0x7fffffff; int bp = -1;
        for (int t = tid; t < TOT; t += 256) {
            float v = sv[t]; int ii = si[t];
            if (v > bv || (v == bv && ii < bi)) { bv = v; bi = ii; bp = t; }
        }
        rv[tid] = bv; ri[tid] = bi; rp[tid] = bp;
        __syncthreads();
        for (int s = 128; s > 0; s >>= 1) {
            if (tid < s) {
                float v2 = rv[tid + s]; int i2 = ri[tid + s];
                if (v2 > rv[tid] || (v2 == rv[tid] && i2 < ri[tid])) {
                    rv[tid] = v2; ri[tid] = i2; rp[tid] = rp[tid + s];
                }
            }
            __syncthreads();
        }
        if (tid == 0) {
            outv[r] = rv[0]; outi[r] = ri[0];
            sv[rp[0]] = -INFINITY;
            si[rp[0]] = 0x7fffffff;
        }
        __syncthreads();
    }

    if (tid == 0) {
        float s = 0.f;
#pragma unroll
        for (int r = 0; r < KNN_; r++) s += outv[r];
        float inv = 1.f / fmaxf(s, 1.f);
#pragma unroll
        for (int r = 0; r < KNN_; r++) {
            g_nidx[row * KNN_ + r] = outi[r];
            g_nval[row * KNN_ + r] = outv[r] * inv;
        }
    }
}

// ---------------- sparse aggregation (+ fp16 split) ----------------
__global__ void agg_kernel()
{
    int row = blockIdx.x;
    int tid = threadIdx.x;                  // 256 == H_
    float acc = 0.f;
#pragma unroll
    for (int r = 0; r < KNN_; r++) {
        float w = g_nval[row * KNN_ + r];
        int   n = g_nidx[row * KNN_ + r];
        acc += w * g_h2[(size_t)n * H_ + tid];
    }
    g_agg[row * H_ + tid] = acc;
    hf hb = __float2half_rn(acc);
    g_ag_hi[row * H_ + tid] = hb;
    g_ag_lo[row * H_ + tid] = __float2half_rn(acc - __half2float(hb));
}

// ---------------- all weight transposes+splits in ONE launch ----------------
__global__ void wsplit_all(
    const float* w0, const float* w1, const float* w2, const float* w3,
    const float* w4, const float* w5, const float* w6, const float* w7,
    const float* w8, hf* __restrict__ hi_base, hf* __restrict__ lo_base)
{
    const int slot = blockIdx.z;
    const float* W = (slot == 0) ? w0 : (slot == 1) ? w1 : (slot == 2) ? w2 :
                     (slot == 3) ? w3 : (slot == 4) ? w4 : (slot == 5) ? w5 :
                     (slot == 6) ? w6 : (slot == 7) ? w7 : w8;
    const int N = (slot == 8) ? 128 : 256;
    hf* hi = hi_base + (size_t)slot * WSLOT;
    hf* lo = lo_base + (size_t)slot * WSLOT;

    __shared__ float t[32][33];
    const int n0 = blockIdx.x * 32;
    if (n0 >= N) return;
    const int k0 = blockIdx.y * 32;
    const int tx = threadIdx.x;
    const int ty = threadIdx.y;
#pragma unroll
    for (int i = ty; i < 32; i += 8)
        t[i][tx] = W[(size_t)(k0 + i) * N + n0 + tx];
    __syncthreads();
#pragma unroll
    for (int i = ty; i < 32; i += 8) {
        float v = t[tx][i];
        hf hb = __float2half_rn(v);
        hi[(size_t)(n0 + i) * 256 + k0 + tx] = hb;
        lo[(size_t)(n0 + i) * 256 + k0 + tx] = __float2half_rn(v - __half2float(hb));
    }
}

// ---------------- tiny precompute ----------------
__global__ void precompute_kernel(const float* __restrict__ bn_g, const float* __restrict__ bn_b,
                                  const float* __restrict__ bn_m, const float* __restrict__ bn_v,
                                  const float* __restrict__ t_w1, const float* __restrict__ t_b1,
                                  const float* __restrict__ t_w2, const float* __restrict__ t_b2,
                                  const float* __restrict__ gate_w, const float* __restrict__ gate_b,
                                  const float* __restrict__ sde_w1, const float* __restrict__ sde_b1)
{
    int b = blockIdx.x;
    int j = threadIdx.x;
    if (b == 0) {
        float s = bn_g[j] * rsqrtf(bn_v[j] + 1e-5f);
        g_bnscale[j] = s;
        g_bnshift[j] = bn_b[j] - bn_m[j] * s;
    } else if (b <= NL_) {
        int l = b - 1;
        float t = 0.5f * (float)l;
        __shared__ float te[TD_];
        __shared__ float te2[H_];
        if (j < TD_) te[j] = fmaxf(t * t_w1[l * TD_ + j] + t_b1[l * TD_ + j], 0.f);
        __syncthreads();
        float acc = t_b2[l * H_ + j];
#pragma unroll
        for (int k = 0; k < TD_; k++) acc += te[k] * t_w2[l * TD_ * H_ + k * H_ + j];
        te2[j] = acc;
        __syncthreads();
        float c = gate_b[l * H_ + j];
        const float* W = gate_w + (size_t)l * 2 * H_ * H_ + (size_t)H_ * H_;
        for (int k = 0; k < H_; k++) c += te2[k] * W[k * H_ + j];
        g_gatec[l * H_ + j] = c;
    } else {
        int s = b - 1 - NL_;
        float ts = (float)s * 0.1f;
        g_sdebias[s * H_ + j] = sde_b1[j] + ts * sde_w1[H_ * H_ + j];
    }
}

// ---------------- host ----------------
static inline void launch_mma(const hf* Ahi, const hf* Alo, const hf* Bhi, const hf* Blo,
                              float* C, int Ntot, int ep, int cand,
                              const float* p1 = nullptr, const float* p2 = nullptr,
                              const float* p3 = nullptr, float alpha = 0.f,
                              hf* Chi = nullptr, hf* Clo = nullptr)
{
    dim3 grid(Ntot / 128, NN_ / 128);
    mma_gemm<<<grid, 256, MG_SMEM>>>(Ahi, Alo, Bhi, Blo, C, Ntot, ep, cand,
                                     p1, p2, p3, alpha, Chi, Clo);
}

extern "C" void kernel_launch(void* const* d_in, const int* in_sizes, int n_in,
                              void* d_out, int out_size)
{
    const float* x       = (const float*)d_in[0];
    const float* enc_w1  = (const float*)d_in[1];
    const float* enc_b1  = (const float*)d_in[2];
    const float* enc_w2  = (const float*)d_in[3];
    const float* enc_b2  = (const float*)d_in[4];
    const float* bn_g    = (const float*)d_in[5];
    const float* bn_b    = (const float*)d_in[6];
    const float* bn_m    = (const float*)d_in[7];
    const float* bn_v    = (const float*)d_in[8];
    const float* node_w  = (const float*)d_in[9];
    const float* node_b  = (const float*)d_in[10];
    const float* t_w1    = (const float*)d_in[11];
    const float* t_b1    = (const float*)d_in[12];
    const float* t_w2    = (const float*)d_in[13];
    const float* t_b2    = (const float*)d_in[14];
    const float* gate_w  = (const float*)d_in[15];
    const float* gate_b  = (const float*)d_in[16];
    const float* sde_w1  = (const float*)d_in[17];
    const float* sde_b1  = (const float*)d_in[18];
    const float* sde_w2  = (const float*)d_in[19];
    const float* sde_b2  = (const float*)d_in[20];
    const float* sde_w3  = (const float*)d_in[21];
    const float* sde_b3  = (const float*)d_in[22];
    const float* dec_w1  = (const float*)d_in[23];
    const float* dec_b1  = (const float*)d_in[24];
    const float* dec_w2  = (const float*)d_in[25];
    const float* dec_b2  = (const float*)d_in[26];
    float* out = (float*)d_out;

    cudaFuncSetAttribute(mma_gemm, cudaFuncAttributeMaxDynamicSharedMemorySize, MG_SMEM);
    cudaFuncSetAttribute(sde_fused, cudaFuncAttributeMaxDynamicSharedMemorySize, SDE_SMEM);

    float *h, *h2, *hn, *agg, *d1, *bns, *bnsh, *gatec, *sdeb;
    hf *hhi, *hlo, *h2hi, *h2lo, *hnhi, *hnlo, *aghi, *aglo, *whi, *wlo;
    cudaGetSymbolAddress((void**)&h,     g_h);
    cudaGetSymbolAddress((void**)&h2,    g_h2);
    cudaGetSymbolAddress((void**)&hn,    g_hn);
    cudaGetSymbolAddress((void**)&agg,   g_agg);
    cudaGetSymbolAddress((void**)&d1,    g_d1);
    cudaGetSymbolAddress((void**)&bns,   g_bnscale);
    cudaGetSymbolAddress((void**)&bnsh,  g_bnshift);
    cudaGetSymbolAddress((void**)&gatec, g_gatec);
    cudaGetSymbolAddress((void**)&sdeb,  g_sdebias);
    cudaGetSymbolAddress((void**)&hhi,  g_h_hi);  cudaGetSymbolAddress((void**)&hlo,  g_h_lo);
    cudaGetSymbolAddress((void**)&h2hi, g_h2_hi); cudaGetSymbolAddress((void**)&h2lo, g_h2_lo);
    cudaGetSymbolAddress((void**)&hnhi, g_hn_hi); cudaGetSymbolAddress((void**)&hnlo, g_hn_lo);
    cudaGetSymbolAddress((void**)&aghi, g_ag_hi); cudaGetSymbolAddress((void**)&aglo, g_ag_lo);
    cudaGetSymbolAddress((void**)&whi, g_w_hi);   cudaGetSymbolAddress((void**)&wlo, g_w_lo);

    // (1) precompute
    precompute_kernel<<<1 + NL_ + NSTEPS_, 256>>>(bn_g, bn_b, bn_m, bn_v,
                                                  t_w1, t_b1, t_w2, t_b2,
                                                  gate_w, gate_b, sde_w1, sde_b1);
    // (2) ALL weight splits in one launch
    {
        dim3 grid(8, 8, 9);
        wsplit_all<<<grid, dim3(32, 8)>>>(
            enc_w2, node_w, node_w + H_ * H_, gate_w, gate_w + 2 * H_ * H_,
            sde_w1, sde_w2, sde_w3, dec_w1, whi, wlo);
    }
    // (3) enc1 SIMT (K=83), splits only
    {
        dim3 grid((H_ + BN - 1) / BN, (NN_ + BM - 1) / BM);
        gemm_kernel<<<grid, 256>>>(x, enc_w1, nullptr, NN_, H_, DIN_, H_, 1, enc_b1, h2hi, h2lo);
    }
    // (4) enc2 mma
    launch_mma(h2hi, h2lo, whi + 0 * WSLOT, wlo + 0 * WSLOT, h, 256, /*ep=*/2, 0,
               enc_b2, bns, bnsh, 0.f, hhi, hlo);
    // (5) rownorm
    rownorm_kernel<<<NN_, 256>>>();
    // (6) sim mma with fused candidate extraction (sim never hits DRAM)
    launch_mma(hnhi, hnlo, hnhi, hnlo, nullptr, NN_, /*ep=*/0, /*cand=*/1);
    // (7) top-k over candidates
    topk_kernel<<<NN_, 256>>>();

    // temporal gated graph conv layers
    for (int l = 0; l < NL_; l++) {
        launch_mma(hhi, hlo, whi + (1 + l) * WSLOT, wlo + (1 + l) * WSLOT, h2, 256, /*ep=*/3, 0,
                   node_b + (size_t)l * H_);
        agg_kernel<<<NN_, 256>>>();
        launch_mma(aghi, aglo, whi + (3 + l) * WSLOT, wlo + (3 + l) * WSLOT, h, 256, /*ep=*/4, 0,
                   gatec + (size_t)l * H_, agg, h2, 0.f, hhi, hlo);
    }

    // SDE: fused persistent kernel (128 CTAs x 64 rows, 10 steps x 3 layers, 512 thr)
    sde_fused<<<NN_ / 64, 512, SDE_SMEM>>>(
        whi + 5 * WSLOT, wlo + 5 * WSLOT,
        whi + 6 * WSLOT, wlo + 6 * WSLOT,
        whi + 7 * WSLOT, wlo + 7 * WSLOT,
        sdeb, sde_b2, sde_b3, h, hhi, hlo);

    // decoder: dec1 tensor (N=128), dec2 SIMT (K=128, N=34)
    launch_mma(hhi, hlo, whi + 8 * WSLOT, wlo + 8 * WSLOT, d1, 128, /*ep=*/1, 0, dec_b1);
    {
        dim3 grid((C_ + BN - 1) / BN, (NN_ + BM - 1) / BM);
        gemm_kernel<<<grid, 256>>>(d1, dec_w2, out, NN_, C_, H_ / 2, C_, 3, dec_b2, nullptr, nullptr);
    }
}